// round 9
// baseline (speedup 1.0000x reference)
#include <cuda_runtime.h>
#include <cuda_fp16.h>
#include <math.h>

#define NN 100000
#define NNBR 12
#define NE (NN*NNBR)
#define CD 192
#define KD 64
#define NBINS 1024
#define NB4 256
#define BN_EPS 1e-5f

#define K1G 296
#define K2G 296
#define K4G 296
#define NST 12500   // NE/96 supertiles (8 nodes each)

// ---------------- scratch (static __device__, no allocs) ----------------
// PD/PS stored in PERMUTED column order: P<128: even=core j (j=P/2),
// odd=filter j; P>=128: bond j=P-128.
__device__ __half g_PDh[(size_t)NN*CD];
__device__ __half g_PSh[(size_t)NN*CD];
__device__ float  g_binS[(size_t)CD*NBINS];  // [P][bin]
__device__ float  g_binQ[(size_t)CD*NBINS];
__device__ float  g_scale[CD];               // permuted order
__device__ float  g_shift[CD];
__device__ float  g_nbr[NN*KD];
__device__ float  g_b4S[KD*NB4];
__device__ float  g_b4Q[KD*NB4];
__device__ float  g_scale4[KD];
__device__ float  g_shift4[KD];
__device__ int    g_is64;

__device__ __forceinline__ void ffma2(float2 &d, float2 a, float2 b) {
    asm("fma.rn.f32x2 %0, %1, %2, %0;"
        : "+l"(reinterpret_cast<unsigned long long&>(d))
        : "l"(reinterpret_cast<unsigned long long&>(a)),
          "l"(reinterpret_cast<unsigned long long&>(b)));
}

__device__ __forceinline__ void mma16816(float* c, const unsigned* a, const unsigned* b) {
    asm volatile(
        "mma.sync.aligned.m16n8k16.row.col.f32.f16.f16.f32 "
        "{%0,%1,%2,%3}, {%4,%5,%6,%7}, {%8,%9}, {%0,%1,%2,%3};"
        : "+f"(c[0]), "+f"(c[1]), "+f"(c[2]), "+f"(c[3])
        : "r"(a[0]), "r"(a[1]), "r"(a[2]), "r"(a[3]), "r"(b[0]), "r"(b[1]));
}

__device__ __forceinline__ unsigned smem_u32(const void* p) {
    return (unsigned)__cvta_generic_to_shared(p);
}
__device__ __forceinline__ void cpa16(unsigned s, const void* g) {
    asm volatile("cp.async.cg.shared.global [%0], [%1], 16;" :: "r"(s), "l"(g));
}
__device__ __forceinline__ void cpa_commit() {
    asm volatile("cp.async.commit_group;");
}
__device__ __forceinline__ void cpa_wait1() {
    asm volatile("cp.async.wait_group 1;");
}

__device__ __forceinline__ float softplus_f(float x) {
    return fmaxf(x, 0.f) + __logf(1.f + __expf(-fabsf(x)));
}
__device__ __forceinline__ float sigmoid_f(float x) {
    return __fdividef(1.f, 1.f + __expf(-x));
}

// original col j (0..191) -> permuted position P
__device__ __forceinline__ int permP(int j) {
    if (j < 64)  return 2*j;
    if (j < 128) return 2*(j-64) + 1;
    return j;
}

// ---------------- K1: zero stats + detect dtype + node pre-GEMM -----------
#define K1_SMEM (64*384*4 + 2*64*8*4)
__global__ void k1_nodegemm(const float* __restrict__ x,
                            const int*   __restrict__ eidx32,
                            const float* __restrict__ Wc, const float* __restrict__ bc,
                            const float* __restrict__ Wf, const float* __restrict__ bf,
                            const float* __restrict__ Wb, const float* __restrict__ bb)
{
    extern __shared__ float sm[];
    float* sW = sm;             // [64][384]
    float* sX = sm + 64*384;    // [2][64][8]
    int tx = threadIdx.x, ty = threadIdx.y;
    int tid = ty*96 + tx;
    int gtid = blockIdx.x*192 + tid;

    for (int i = gtid; i < CD*NBINS; i += K1G*192) { g_binS[i] = 0.f; g_binQ[i] = 0.f; }
    for (int i = gtid; i < KD*NB4;   i += K1G*192) { g_b4S[i]  = 0.f; g_b4Q[i]  = 0.f; }
    if (gtid == 0) g_is64 = (eidx32[25] == 0) ? 1 : 0;

    for (int idx = tid; idx < 64*384; idx += 192) {
        int k  = idx / 384;
        int j3 = idx - k*384;
        int j  = (j3 >= 192) ? j3 - 192 : j3;
        int kk = (j3 >= 192) ? 64 + k : k;
        const float* W; int r;
        if (j < 64)       { W = Wc; r = j; }
        else if (j < 128) { W = Wf; r = j - 64; }
        else              { W = Wb; r = j - 128; }
        sW[idx] = W[r*CD + kk];
    }
    int j0 = tx, j1 = tx + 96;
    int P0 = permP(j0), P1 = permP(j1);
    float bias0 = (j0 < 64) ? bc[j0] : ((j0 < 128) ? bf[j0-64] : bb[j0-128]);
    float bias1 = (j1 < 128) ? bf[j1-64] : bb[j1-128];
    float* sXt = sX + ty*512;

    for (int g = blockIdx.x; g < NN/16; g += gridDim.x) {
        int n0 = (g*2 + ty) * 8;
        __syncthreads();
        const float4* x4 = (const float4*)(x + (size_t)n0*64);
        for (int i = tx; i < 128; i += 96) {
            float4 v = x4[i];
            int nl = i >> 4, k4 = (i & 15) * 4;
            sXt[(k4+0)*8 + nl] = v.x;
            sXt[(k4+1)*8 + nl] = v.y;
            sXt[(k4+2)*8 + nl] = v.z;
            sXt[(k4+3)*8 + nl] = v.w;
        }
        __syncthreads();

        float2 ad0[4], ad1[4], as0[4], as1[4];
        #pragma unroll
        for (int p = 0; p < 4; p++) {
            ad0[p] = make_float2(0.f,0.f); ad1[p] = make_float2(0.f,0.f);
            as0[p] = make_float2(0.f,0.f); as1[p] = make_float2(0.f,0.f);
        }
        #pragma unroll 8
        for (int k = 0; k < 64; k++) {
            float wd0 = sW[k*384 + j0];
            float wd1 = sW[k*384 + j1];
            float ws0 = sW[k*384 + 192 + j0];
            float ws1 = sW[k*384 + 192 + j1];
            float2 Wd0 = make_float2(wd0, wd0), Wd1 = make_float2(wd1, wd1);
            float2 Ws0 = make_float2(ws0, ws0), Ws1 = make_float2(ws1, ws1);
            const float2* xp = (const float2*)(sXt + k*8);
            #pragma unroll
            for (int p = 0; p < 4; p++) {
                float2 xv = xp[p];
                ffma2(ad0[p], xv, Wd0);
                ffma2(ad1[p], xv, Wd1);
                ffma2(as0[p], xv, Ws0);
                ffma2(as1[p], xv, Ws1);
            }
        }
        #pragma unroll
        for (int p = 0; p < 4; p++) {
            size_t na = (size_t)(n0 + 2*p)*CD, nb = na + CD;
            g_PDh[na + P0] = __float2half_rn(ad0[p].x + bias0);
            g_PDh[nb + P0] = __float2half_rn(ad0[p].y + bias0);
            g_PDh[na + P1] = __float2half_rn(ad1[p].x + bias1);
            g_PDh[nb + P1] = __float2half_rn(ad1[p].y + bias1);
            g_PSh[na + P0] = __float2half_rn(as0[p].x);
            g_PSh[nb + P0] = __float2half_rn(as0[p].y);
            g_PSh[na + P1] = __float2half_rn(as1[p].x);
            g_PSh[nb + P1] = __float2half_rn(as1[p].y);
        }
    }
}

// ---------------- shared smem layout for k2/k4 ----------------------------
#define SW_BYTES  (192*32*4)       // 24576: permuted W_edge fp16 [P][64k]
#define PD_STRIDE 400              // bytes per PD row (192 halves + pad)
#define PDB       (32*PD_STRIDE)   // 12800
#define PSB       (8*PD_STRIDE)    // 3200
#define PD_OFF(b) (SW_BYTES + (b)*PDB)
#define PS_OFF(b) (SW_BYTES + 2*PDB + (b)*PSB)
#define COMMON_SMEM (SW_BYTES + 2*PDB + 2*PSB)   // 56576
#define GT_OFF    COMMON_SMEM
#define GT_STRIDE 68
#define K2_SMEM   COMMON_SMEM
#define K4_SMEM   (GT_OFF + 96*GT_STRIDE*4)      // +26112 = 82688

// ---------------- K2s: stats-only edge GEMM (supertile-96) ----------------
__global__ void __launch_bounds__(256, 2)
k2_stats(const float* __restrict__ ea,
         const void* __restrict__ eidx_raw,
         const float* __restrict__ Wc,
         const float* __restrict__ Wf,
         const float* __restrict__ Wb)
{
    extern __shared__ char smc[];
    unsigned* sW32 = (unsigned*)smc;
    unsigned smb = smem_u32(smc);
    int tid = threadIdx.x;
    int w   = tid >> 5, lane = tid & 31;
    int gq  = lane >> 2, tl = lane & 3;
    int mb  = (w & 1) * 16;
    int nw  = (w >> 1);
    int is64 = g_is64;

    // permuted W_edge -> smem fp16 [P][k]
    for (int i = tid; i < 192*32; i += 256) {
        int P = i >> 5, k2 = i & 31;
        const float* W; int r;
        if (P < 128) { r = P >> 1; W = (P & 1) ? Wf : Wc; }
        else         { r = P - 128; W = Wb; }
        float2 v = *(const float2*)(W + (size_t)r*CD + 128 + 2*k2);
        __half2 h = __floats2half2_rn(v.x, v.y);
        sW32[P*32 + k2] = *(unsigned*)&h;
    }
    __syncthreads();

    unsigned Bf[6][4][2];
    #pragma unroll
    for (int nt = 0; nt < 6; nt++) {
        int n = nw*48 + nt*8 + gq;
        #pragma unroll
        for (int ks = 0; ks < 4; ks++) {
            Bf[nt][ks][0] = sW32[n*32 + ks*8 + tl];
            Bf[nt][ks][1] = sW32[n*32 + ks*8 + tl + 4];
        }
    }
    __syncthreads();

    float sS[12], sQ[12];
    #pragma unroll
    for (int i = 0; i < 12; i++) { sS[i] = 0.f; sQ[i] = 0.f; }

    auto stagePD = [&](int buf, int ebase) {
        #pragma unroll
        for (int i = 0; i < 3; i++) {
            int f = tid + i*256;
            int r = f / 24, c = f - r*24;
            int e = ebase + r;
            int dst;
            if (is64) dst = (int)((const long long*)eidx_raw)[(size_t)NE + e];
            else      dst = ((const int*)eidx_raw)[(size_t)NE + e];
            cpa16(smb + PD_OFF(buf) + r*PD_STRIDE + c*16,
                  g_PDh + (size_t)dst*CD + c*8);
        }
    };
    auto stagePS = [&](int buf, int nodebase) {
        if (tid < 192) {
            int r = tid / 24, c = tid - r*24;
            cpa16(smb + PS_OFF(buf) + r*PD_STRIDE + c*16,
                  g_PSh + (size_t)(nodebase + r)*CD + c*8);
        }
    };

    int buf = 0, psb = 0;
    stagePD(0, blockIdx.x*96);
    stagePS(0, blockIdx.x*8);
    cpa_commit();

    for (int st = blockIdx.x; st < NST; st += gridDim.x) {
        #pragma unroll 1
        for (int s = 0; s < 3; s++) {
            __syncthreads();   // all readers of buf^1 (and ps^1 two STs ago) done
            int nst = (s < 2) ? st : st + (int)gridDim.x;
            int nss = (s < 2) ? s + 1 : 0;
            if (nst < NST) {
                stagePD(buf ^ 1, nst*96 + nss*32);
                if (s == 2) stagePS(psb ^ 1, nst*8);
            }
            cpa_commit();
            cpa_wait1();
            __syncthreads();

            int ebase = st*96 + s*32;
            int r0 = mb + gq, r1 = r0 + 8;
            int e0g = ebase + r0, e1g = ebase + r1;
            const float* eaR0 = ea + (size_t)e0g*64;
            const float* eaR1 = ea + (size_t)e1g*64;

            float C[6][4];
            #pragma unroll
            for (int nt = 0; nt < 6; nt++)
                #pragma unroll
                for (int q = 0; q < 4; q++) C[nt][q] = 0.f;

            #pragma unroll
            for (int ks = 0; ks < 4; ks++) {
                unsigned A[4];
                int k0 = ks*8 + tl, k1 = k0 + 4;
                float2 v0 = *(const float2*)(eaR0 + 2*k0);
                float2 v1 = *(const float2*)(eaR1 + 2*k0);
                float2 v2 = *(const float2*)(eaR0 + 2*k1);
                float2 v3 = *(const float2*)(eaR1 + 2*k1);
                __half2 h0 = __floats2half2_rn(v0.x, v0.y);
                __half2 h1 = __floats2half2_rn(v1.x, v1.y);
                __half2 h2 = __floats2half2_rn(v2.x, v2.y);
                __half2 h3 = __floats2half2_rn(v3.x, v3.y);
                A[0] = *(unsigned*)&h0;
                A[1] = *(unsigned*)&h1;
                A[2] = *(unsigned*)&h2;
                A[3] = *(unsigned*)&h3;
                #pragma unroll
                for (int nt = 0; nt < 6; nt++)
                    mma16816(C[nt], A, Bf[nt][ks]);
            }

            const __half* pd = (const __half*)(smc + PD_OFF(buf));
            const __half* ps = (const __half*)(smc + PS_OFF(psb));
            int ln0 = (s*32 + r0) / 12, ln1 = (s*32 + r1) / 12;
            #pragma unroll
            for (int nt = 0; nt < 6; nt++) {
                int P0 = nw*48 + nt*8 + 2*tl;
                float2 pd0 = __half22float2(*(const __half2*)(pd + r0*200 + P0));
                float2 pd1 = __half22float2(*(const __half2*)(pd + r1*200 + P0));
                float2 ps0 = __half22float2(*(const __half2*)(ps + ln0*200 + P0));
                float2 ps1 = __half22float2(*(const __half2*)(ps + ln1*200 + P0));
                float u0x = C[nt][0] + pd0.x + ps0.x, u0y = C[nt][1] + pd0.y + ps0.y;
                float u1x = C[nt][2] + pd1.x + ps1.x, u1y = C[nt][3] + pd1.y + ps1.y;
                sS[nt*2]   += u0x + u1x;
                sQ[nt*2]   += u0x*u0x + u1x*u1x;
                sS[nt*2+1] += u0y + u1y;
                sQ[nt*2+1] += u0y*u0y + u1y*u1y;
            }
            buf ^= 1;
        }
        psb ^= 1;
    }

    #pragma unroll
    for (int i = 0; i < 12; i++) {
        sS[i] += __shfl_xor_sync(0xffffffff, sS[i], 4);
        sS[i] += __shfl_xor_sync(0xffffffff, sS[i], 8);
        sS[i] += __shfl_xor_sync(0xffffffff, sS[i], 16);
        sQ[i] += __shfl_xor_sync(0xffffffff, sQ[i], 4);
        sQ[i] += __shfl_xor_sync(0xffffffff, sQ[i], 8);
        sQ[i] += __shfl_xor_sync(0xffffffff, sQ[i], 16);
    }
    if (lane < 4) {
        int bin = blockIdx.x & (NBINS - 1);
        #pragma unroll
        for (int nt = 0; nt < 6; nt++) {
            int col = nw*48 + nt*8 + 2*lane;
            atomicAdd(&g_binS[(size_t)col*NBINS + bin],     sS[nt*2]);
            atomicAdd(&g_binQ[(size_t)col*NBINS + bin],     sQ[nt*2]);
            atomicAdd(&g_binS[(size_t)(col+1)*NBINS + bin], sS[nt*2+1]);
            atomicAdd(&g_binQ[(size_t)(col+1)*NBINS + bin], sQ[nt*2+1]);
        }
    }
}

// ---------------- K3: reduce bins (permuted) -> scale/shift ----------
__global__ void k3_reduce(const float* __restrict__ g1, const float* __restrict__ be1,
                          const float* __restrict__ g2, const float* __restrict__ be2,
                          const float* __restrict__ g3, const float* __restrict__ be3)
{
    __shared__ float sS[256], sQ[256];
    int P = blockIdx.x, t = threadIdx.x;
    float S = 0.f, Q = 0.f;
    for (int b = t; b < NBINS; b += 256) {
        S += g_binS[(size_t)P*NBINS + b];
        Q += g_binQ[(size_t)P*NBINS + b];
    }
    sS[t] = S; sQ[t] = Q;
    __syncthreads();
    for (int o = 128; o > 0; o >>= 1) {
        if (t < o) { sS[t] += sS[t+o]; sQ[t] += sQ[t+o]; }
        __syncthreads();
    }
    if (t == 0) {
        float mean = sS[0] / (float)NE;
        float var  = sQ[0] / (float)NE - mean*mean;
        float g, be;
        if (P < 128) {
            int jj = P >> 1;
            if ((P & 1) == 0) { g = g1[jj]; be = be1[jj]; }
            else              { g = g2[jj]; be = be2[jj]; }
        } else { g = g3[P-128]; be = be3[P-128]; }
        float sc = g * rsqrtf(var + BN_EPS);
        g_scale[P] = sc;
        g_shift[P] = be - mean * sc;
    }
}

// ---------------- K4f: fused recompute + BN + gate + bond + node-sum ------
__global__ void __launch_bounds__(256, 2)
k4_fused(const float* __restrict__ ea,
         const void* __restrict__ eidx_raw,
         const float* __restrict__ Wc,
         const float* __restrict__ Wf,
         const float* __restrict__ Wb,
         float* __restrict__ bond_out)
{
    extern __shared__ char smc[];
    unsigned* sW32 = (unsigned*)smc;
    float* gated = (float*)(smc + GT_OFF);
    unsigned smb = smem_u32(smc);
    int tid = threadIdx.x;
    int w   = tid >> 5, lane = tid & 31;
    int gq  = lane >> 2, tl = lane & 3;
    int mb  = (w & 1) * 16;
    int nw  = (w >> 1);
    int is64 = g_is64;

    for (int i = tid; i < 192*32; i += 256) {
        int P = i >> 5, k2 = i & 31;
        const float* W; int r;
        if (P < 128) { r = P >> 1; W = (P & 1) ? Wf : Wc; }
        else         { r = P - 128; W = Wb; }
        float2 v = *(const float2*)(W + (size_t)r*CD + 128 + 2*k2);
        __half2 h = __floats2half2_rn(v.x, v.y);
        sW32[P*32 + k2] = *(unsigned*)&h;
    }
    __syncthreads();

    unsigned Bf[6][4][2];
    #pragma unroll
    for (int nt = 0; nt < 6; nt++) {
        int n = nw*48 + nt*8 + gq;
        #pragma unroll
        for (int ks = 0; ks < 4; ks++) {
            Bf[nt][ks][0] = sW32[n*32 + ks*8 + tl];
            Bf[nt][ks][1] = sW32[n*32 + ks*8 + tl + 4];
        }
    }

    // per-lane BN scale/shift (permuted arrays; P0 even -> float2 aligned)
    float2 scp[6], shp[6];
    #pragma unroll
    for (int nt = 0; nt < 6; nt++) {
        int P0 = nw*48 + nt*8 + 2*tl;
        scp[nt] = *(const float2*)(g_scale + P0);
        shp[nt] = *(const float2*)(g_shift + P0);
    }

    float stS = 0.f, stQ = 0.f;

    auto stagePD = [&](int buf, int ebase) {
        #pragma unroll
        for (int i = 0; i < 3; i++) {
            int f = tid + i*256;
            int r = f / 24, c = f - r*24;
            int e = ebase + r;
            int dst;
            if (is64) dst = (int)((const long long*)eidx_raw)[(size_t)NE + e];
            else      dst = ((const int*)eidx_raw)[(size_t)NE + e];
            cpa16(smb + PD_OFF(buf) + r*PD_STRIDE + c*16,
                  g_PDh + (size_t)dst*CD + c*8);
        }
    };
    auto stagePS = [&](int buf, int nodebase) {
        if (tid < 192) {
            int r = tid / 24, c = tid - r*24;
            cpa16(smb + PS_OFF(buf) + r*PD_STRIDE + c*16,
                  g_PSh + (size_t)(nodebase + r)*CD + c*8);
        }
    };

    int buf = 0, psb = 0;
    stagePD(0, blockIdx.x*96);
    stagePS(0, blockIdx.x*8);
    cpa_commit();

    for (int st = blockIdx.x; st < NST; st += gridDim.x) {
        #pragma unroll 1
        for (int s = 0; s < 3; s++) {
            __syncthreads();   // protect buf^1 readers (and gated at s==0)
            int nst = (s < 2) ? st : st + (int)gridDim.x;
            int nss = (s < 2) ? s + 1 : 0;
            if (nst < NST) {
                stagePD(buf ^ 1, nst*96 + nss*32);
                if (s == 2) stagePS(psb ^ 1, nst*8);
            }
            cpa_commit();
            cpa_wait1();
            __syncthreads();

            int ebase = st*96 + s*32;
            int r0 = mb + gq, r1 = r0 + 8;
            int e0g = ebase + r0, e1g = ebase + r1;
            const float* eaR0 = ea + (size_t)e0g*64;
            const float* eaR1 = ea + (size_t)e1g*64;

            float C[6][4];
            #pragma unroll
            for (int nt = 0; nt < 6; nt++)
                #pragma unroll
                for (int q = 0; q < 4; q++) C[nt][q] = 0.f;

            #pragma unroll
            for (int ks = 0; ks < 4; ks++) {
                unsigned A[4];
                int k0 = ks*8 + tl, k1 = k0 + 4;
                float2 v0 = *(const float2*)(eaR0 + 2*k0);
                float2 v1 = *(const float2*)(eaR1 + 2*k0);
                float2 v2 = *(const float2*)(eaR0 + 2*k1);
                float2 v3 = *(const float2*)(eaR1 + 2*k1);
                __half2 h0 = __floats2half2_rn(v0.x, v0.y);
                __half2 h1 = __floats2half2_rn(v1.x, v1.y);
                __half2 h2 = __floats2half2_rn(v2.x, v2.y);
                __half2 h3 = __floats2half2_rn(v3.x, v3.y);
                A[0] = *(unsigned*)&h0;
                A[1] = *(unsigned*)&h1;
                A[2] = *(unsigned*)&h2;
                A[3] = *(unsigned*)&h3;
                #pragma unroll
                for (int nt = 0; nt < 6; nt++)
                    mma16816(C[nt], A, Bf[nt][ks]);
            }

            const __half* pd = (const __half*)(smc + PD_OFF(buf));
            const __half* ps = (const __half*)(smc + PS_OFF(psb));
            int ln0 = (s*32 + r0) / 12, ln1 = (s*32 + r1) / 12;
            int row0 = s*32 + r0, row1 = s*32 + r1;

            #pragma unroll
            for (int nt = 0; nt < 6; nt++) {
                int P0 = nw*48 + nt*8 + 2*tl;
                float2 pd0 = __half22float2(*(const __half2*)(pd + r0*200 + P0));
                float2 pd1 = __half22float2(*(const __half2*)(pd + r1*200 + P0));
                float2 ps0 = __half22float2(*(const __half2*)(ps + ln0*200 + P0));
                float2 ps1 = __half22float2(*(const __half2*)(ps + ln1*200 + P0));
                float v00 = fmaf(C[nt][0] + pd0.x + ps0.x, scp[nt].x, shp[nt].x);
                float v01 = fmaf(C[nt][1] + pd0.y + ps0.y, scp[nt].y, shp[nt].y);
                float v10 = fmaf(C[nt][2] + pd1.x + ps1.x, scp[nt].x, shp[nt].x);
                float v11 = fmaf(C[nt][3] + pd1.y + ps1.y, scp[nt].y, shp[nt].y);
                if (P0 < 128) {
                    int j = P0 >> 1;   // v0=core(sigmoid), v1=filter(softplus)
                    gated[row0*GT_STRIDE + j] = sigmoid_f(v00) * softplus_f(v01);
                    gated[row1*GT_STRIDE + j] = sigmoid_f(v10) * softplus_f(v11);
                } else {
                    int jb = P0 - 128;
                    float2 ev0 = *(const float2*)(eaR0 + jb);
                    float2 ev1 = *(const float2*)(eaR1 + jb);
                    float2 bo0, bo1;
                    bo0.x = softplus_f(ev0.x + v00);
                    bo0.y = softplus_f(ev0.y + v01);
                    bo1.x = softplus_f(ev1.x + v10);
                    bo1.y = softplus_f(ev1.y + v11);
                    *(float2*)(bond_out + (size_t)e0g*64 + jb) = bo0;
                    *(float2*)(bond_out + (size_t)e1g*64 + jb) = bo1;
                }
            }
            buf ^= 1;
        }
        __syncthreads();   // gated complete

        {
            int j = tid & 63;
            #pragma unroll
            for (int h = 0; h < 2; h++) {
                int d = (tid >> 6) + 4*h;
                float acc = 0.f;
                #pragma unroll
                for (int k = 0; k < 12; k++)
                    acc += gated[(d*12 + k)*GT_STRIDE + j];
                g_nbr[(size_t)(st*8 + d)*64 + j] = acc;
                stS += acc; stQ += acc*acc;
            }
        }
        psb ^= 1;
    }

    {
        int j = tid & 63;
        int bin = blockIdx.x & (NB4 - 1);
        atomicAdd(&g_b4S[j*NB4 + bin], stS);
        atomicAdd(&g_b4Q[j*NB4 + bin], stQ);
    }
}

// ---------------- K5: parallel reduce node-BN ----------------
__global__ void k5_reduce(const float* __restrict__ g4, const float* __restrict__ be4)
{
    __shared__ float sS[256], sQ[256];
    int j = blockIdx.x, t = threadIdx.x;
    float S = (t < NB4) ? g_b4S[j*NB4 + t] : 0.f;
    float Q = (t < NB4) ? g_b4Q[j*NB4 + t] : 0.f;
    sS[t] = S; sQ[t] = Q;
    __syncthreads();
    for (int o = 128; o > 0; o >>= 1) {
        if (t < o) { sS[t] += sS[t+o]; sQ[t] += sQ[t+o]; }
        __syncthreads();
    }
    if (t == 0) {
        float mean = sS[0] / (float)NN;
        float var  = sQ[0] / (float)NN - mean*mean;
        float sc = g4[j] * rsqrtf(var + BN_EPS);
        g_scale4[j] = sc;
        g_shift4[j] = be4[j] - mean * sc;
    }
}

// ---------------- K6: out = softplus(x + bn4(nbr_sum)) ----------------
__global__ void k6_out(const float* __restrict__ x, float* __restrict__ out)
{
    int i = blockIdx.x * 256 + threadIdx.x;
    if (i < NN*64) {
        int j = i & 63;
        float v = x[i] + fmaf(g_nbr[i], g_scale4[j], g_shift4[j]);
        out[i] = softplus_f(v);
    }
}

extern "C" void kernel_launch(void* const* d_in, const int* in_sizes, int n_in,
                              void* d_out, int out_size)
{
    const float* x   = (const float*)d_in[0];
    const void*  ei  = (const void*)d_in[1];
    const float* ea  = (const float*)d_in[2];
    const float* Wc  = (const float*)d_in[3];
    const float* bc  = (const float*)d_in[4];
    const float* Wf  = (const float*)d_in[5];
    const float* bf  = (const float*)d_in[6];
    const float* Wb  = (const float*)d_in[7];
    const float* bb  = (const float*)d_in[8];
    const float* g1  = (const float*)d_in[9];
    const float* be1 = (const float*)d_in[10];
    const float* g2  = (const float*)d_in[11];
    const float* be2 = (const float*)d_in[12];
    const float* g3  = (const float*)d_in[13];
    const float* be3 = (const float*)d_in[14];
    const float* g4  = (const float*)d_in[15];
    const float* be4 = (const float*)d_in[16];

    float* out  = (float*)d_out;
    float* bond = out + (size_t)NN * 64;

    cudaFuncSetAttribute(k1_nodegemm, cudaFuncAttributeMaxDynamicSharedMemorySize, K1_SMEM);
    cudaFuncSetAttribute(k2_stats,    cudaFuncAttributeMaxDynamicSharedMemorySize, K2_SMEM);
    cudaFuncSetAttribute(k4_fused,    cudaFuncAttributeMaxDynamicSharedMemorySize, K4_SMEM);

    k1_nodegemm<<<K1G, dim3(96,2,1), K1_SMEM>>>(x, (const int*)ei, Wc, bc, Wf, bf, Wb, bb);
    k2_stats<<<K2G, 256, K2_SMEM>>>(ea, ei, Wc, Wf, Wb);
    k3_reduce<<<CD, 256>>>(g1, be1, g2, be2, g3, be3);
    k4_fused<<<K4G, 256, K4_SMEM>>>(ea, ei, Wc, Wf, Wb, bond);
    k5_reduce<<<KD, 256>>>(g4, be4);
    k6_out<<<(NN*64 + 255)/256, 256>>>(x, out);
}

// round 10
// speedup vs baseline: 1.2969x; 1.2969x over previous
#include <cuda_runtime.h>
#include <cuda_fp16.h>
#include <math.h>

#define NN 100000
#define NNBR 12
#define NE (NN*NNBR)
#define CD 192
#define KD 64
#define NBINS 1024
#define NB4 256
#define BN_EPS 1e-5f

#define K1G 296
#define K2G 296
#define K4G 296
#define NST 12500   // NE/96 supertiles (8 nodes each)

// ---------------- scratch (static __device__, no allocs) ----------------
// PD/PS stored in PERMUTED column order: P<128: even=core j (j=P/2),
// odd=filter j; P>=128: bond j=P-128.
__device__ __half g_PDh[(size_t)NN*CD];
__device__ __half g_PSh[(size_t)NN*CD];
__device__ float  g_binS[(size_t)CD*NBINS];  // [P][bin]
__device__ float  g_binQ[(size_t)CD*NBINS];
__device__ float  g_scale[CD];               // permuted order
__device__ float  g_shift[CD];
__device__ float  g_nbr[NN*KD];
__device__ float  g_b4S[KD*NB4];
__device__ float  g_b4Q[KD*NB4];
__device__ float  g_scale4[KD];
__device__ float  g_shift4[KD];
__device__ int    g_is64;

__device__ __forceinline__ void ffma2(float2 &d, float2 a, float2 b) {
    asm("fma.rn.f32x2 %0, %1, %2, %0;"
        : "+l"(reinterpret_cast<unsigned long long&>(d))
        : "l"(reinterpret_cast<unsigned long long&>(a)),
          "l"(reinterpret_cast<unsigned long long&>(b)));
}

__device__ __forceinline__ void mma16816(float* c, const unsigned* a, const unsigned* b) {
    asm volatile(
        "mma.sync.aligned.m16n8k16.row.col.f32.f16.f16.f32 "
        "{%0,%1,%2,%3}, {%4,%5,%6,%7}, {%8,%9}, {%0,%1,%2,%3};"
        : "+f"(c[0]), "+f"(c[1]), "+f"(c[2]), "+f"(c[3])
        : "r"(a[0]), "r"(a[1]), "r"(a[2]), "r"(a[3]), "r"(b[0]), "r"(b[1]));
}

__device__ __forceinline__ void ldsm_x4(unsigned* a, unsigned saddr) {
    asm volatile("ldmatrix.sync.aligned.m8n8.x4.shared.b16 {%0,%1,%2,%3}, [%4];"
        : "=r"(a[0]), "=r"(a[1]), "=r"(a[2]), "=r"(a[3]) : "r"(saddr));
}

__device__ __forceinline__ unsigned smem_u32(const void* p) {
    return (unsigned)__cvta_generic_to_shared(p);
}
__device__ __forceinline__ void cpa16(unsigned s, const void* g) {
    asm volatile("cp.async.cg.shared.global [%0], [%1], 16;" :: "r"(s), "l"(g));
}
__device__ __forceinline__ void cpa_commit() {
    asm volatile("cp.async.commit_group;");
}
__device__ __forceinline__ void cpa_wait1() {
    asm volatile("cp.async.wait_group 1;");
}

__device__ __forceinline__ float softplus_f(float x) {
    return fmaxf(x, 0.f) + __logf(1.f + __expf(-fabsf(x)));
}
__device__ __forceinline__ float sigmoid_f(float x) {
    return __fdividef(1.f, 1.f + __expf(-x));
}

__device__ __forceinline__ int permP(int j) {
    if (j < 64)  return 2*j;
    if (j < 128) return 2*(j-64) + 1;
    return j;
}

// ---------------- K1: zero stats + detect dtype + node pre-GEMM -----------
#define K1_SMEM (64*384*4 + 2*64*8*4)
__global__ void k1_nodegemm(const float* __restrict__ x,
                            const int*   __restrict__ eidx32,
                            const float* __restrict__ Wc, const float* __restrict__ bc,
                            const float* __restrict__ Wf, const float* __restrict__ bf,
                            const float* __restrict__ Wb, const float* __restrict__ bb)
{
    extern __shared__ float sm[];
    float* sW = sm;             // [64][384]
    float* sX = sm + 64*384;    // [2][64][8]
    int tx = threadIdx.x, ty = threadIdx.y;
    int tid = ty*96 + tx;
    int gtid = blockIdx.x*192 + tid;

    for (int i = gtid; i < CD*NBINS; i += K1G*192) { g_binS[i] = 0.f; g_binQ[i] = 0.f; }
    for (int i = gtid; i < KD*NB4;   i += K1G*192) { g_b4S[i]  = 0.f; g_b4Q[i]  = 0.f; }
    if (gtid == 0) g_is64 = (eidx32[25] == 0) ? 1 : 0;

    for (int idx = tid; idx < 64*384; idx += 192) {
        int k  = idx / 384;
        int j3 = idx - k*384;
        int j  = (j3 >= 192) ? j3 - 192 : j3;
        int kk = (j3 >= 192) ? 64 + k : k;
        const float* W; int r;
        if (j < 64)       { W = Wc; r = j; }
        else if (j < 128) { W = Wf; r = j - 64; }
        else              { W = Wb; r = j - 128; }
        sW[idx] = W[r*CD + kk];
    }
    int j0 = tx, j1 = tx + 96;
    int P0 = permP(j0), P1 = permP(j1);
    float bias0 = (j0 < 64) ? bc[j0] : ((j0 < 128) ? bf[j0-64] : bb[j0-128]);
    float bias1 = (j1 < 128) ? bf[j1-64] : bb[j1-128];
    float* sXt = sX + ty*512;

    for (int g = blockIdx.x; g < NN/16; g += gridDim.x) {
        int n0 = (g*2 + ty) * 8;
        __syncthreads();
        const float4* x4 = (const float4*)(x + (size_t)n0*64);
        for (int i = tx; i < 128; i += 96) {
            float4 v = x4[i];
            int nl = i >> 4, k4 = (i & 15) * 4;
            sXt[(k4+0)*8 + nl] = v.x;
            sXt[(k4+1)*8 + nl] = v.y;
            sXt[(k4+2)*8 + nl] = v.z;
            sXt[(k4+3)*8 + nl] = v.w;
        }
        __syncthreads();

        float2 ad0[4], ad1[4], as0[4], as1[4];
        #pragma unroll
        for (int p = 0; p < 4; p++) {
            ad0[p] = make_float2(0.f,0.f); ad1[p] = make_float2(0.f,0.f);
            as0[p] = make_float2(0.f,0.f); as1[p] = make_float2(0.f,0.f);
        }
        #pragma unroll 8
        for (int k = 0; k < 64; k++) {
            float wd0 = sW[k*384 + j0];
            float wd1 = sW[k*384 + j1];
            float ws0 = sW[k*384 + 192 + j0];
            float ws1 = sW[k*384 + 192 + j1];
            float2 Wd0 = make_float2(wd0, wd0), Wd1 = make_float2(wd1, wd1);
            float2 Ws0 = make_float2(ws0, ws0), Ws1 = make_float2(ws1, ws1);
            const float2* xp = (const float2*)(sXt + k*8);
            #pragma unroll
            for (int p = 0; p < 4; p++) {
                float2 xv = xp[p];
                ffma2(ad0[p], xv, Wd0);
                ffma2(ad1[p], xv, Wd1);
                ffma2(as0[p], xv, Ws0);
                ffma2(as1[p], xv, Ws1);
            }
        }
        #pragma unroll
        for (int p = 0; p < 4; p++) {
            size_t na = (size_t)(n0 + 2*p)*CD, nb = na + CD;
            g_PDh[na + P0] = __float2half_rn(ad0[p].x + bias0);
            g_PDh[nb + P0] = __float2half_rn(ad0[p].y + bias0);
            g_PDh[na + P1] = __float2half_rn(ad1[p].x + bias1);
            g_PDh[nb + P1] = __float2half_rn(ad1[p].y + bias1);
            g_PSh[na + P0] = __float2half_rn(as0[p].x);
            g_PSh[nb + P0] = __float2half_rn(as0[p].y);
            g_PSh[na + P1] = __float2half_rn(as1[p].x);
            g_PSh[nb + P1] = __float2half_rn(as1[p].y);
        }
    }
}

// ---------------- shared smem layout for k2/k4 ----------------------------
#define SW_BYTES   (192*32*4)       // 24576: permuted W_edge fp16 [P][64k]
#define EA32_STRIDE 272             // 64 floats + 16B pad
#define EA32B      (32*EA32_STRIDE) // 8704
#define A16_STRIDE 144              // 64 halves + 16B pad (LDSM conflict-free)
#define A16B       (32*A16_STRIDE)  // 4608
#define PD_STRIDE  400
#define PDB        (32*PD_STRIDE)   // 12800
#define PSB        (8*PD_STRIDE)    // 3200
#define EA_OFF(b)  (SW_BYTES + (b)*EA32B)
#define A16_OFF    (SW_BYTES + 2*EA32B)
#define PD_OFF(b)  (A16_OFF + A16B + (b)*PDB)
#define PS_OFF(b)  (A16_OFF + A16B + 2*PDB + (b)*PSB)
#define COMMON_SMEM (A16_OFF + A16B + 2*PDB + 2*PSB)   // 78592
#define GT_OFF     COMMON_SMEM
#define GT_STRIDE  68
#define K2_SMEM    COMMON_SMEM
#define K4_SMEM    (GT_OFF + 96*GT_STRIDE*4)           // 104704

// ---------------- K2s: stats-only edge GEMM (supertile-96) ----------------
__global__ void __launch_bounds__(256, 2)
k2_stats(const float* __restrict__ ea,
         const void* __restrict__ eidx_raw,
         const float* __restrict__ Wc,
         const float* __restrict__ Wf,
         const float* __restrict__ Wb)
{
    extern __shared__ char smc[];
    unsigned* sW32 = (unsigned*)smc;
    unsigned smb = smem_u32(smc);
    int tid = threadIdx.x;
    int w   = tid >> 5, lane = tid & 31;
    int gq  = lane >> 2, tl = lane & 3;
    int mb  = (w & 1) * 16;
    int nw  = (w >> 1);
    int is64 = g_is64;

    for (int i = tid; i < 192*32; i += 256) {
        int P = i >> 5, k2 = i & 31;
        const float* W; int r;
        if (P < 128) { r = P >> 1; W = (P & 1) ? Wf : Wc; }
        else         { r = P - 128; W = Wb; }
        float2 v = *(const float2*)(W + (size_t)r*CD + 128 + 2*k2);
        __half2 h = __floats2half2_rn(v.x, v.y);
        sW32[P*32 + k2] = *(unsigned*)&h;
    }
    __syncthreads();

    unsigned Bf[6][4][2];
    #pragma unroll
    for (int nt = 0; nt < 6; nt++) {
        int n = nw*48 + nt*8 + gq;
        #pragma unroll
        for (int ks = 0; ks < 4; ks++) {
            Bf[nt][ks][0] = sW32[n*32 + ks*8 + tl];
            Bf[nt][ks][1] = sW32[n*32 + ks*8 + tl + 4];
        }
    }
    __syncthreads();

    // per-lane ldmatrix base address (rows mb..mb+15 of A16 tile)
    unsigned aBase = smb + A16_OFF + (mb + (lane & 15))*A16_STRIDE + (lane >> 4)*16;

    float sS[12], sQ[12];
    #pragma unroll
    for (int i = 0; i < 12; i++) { sS[i] = 0.f; sQ[i] = 0.f; }

    auto stageEA = [&](int buf, int ebase) {
        #pragma unroll
        for (int i = 0; i < 2; i++) {
            int f = tid + i*256;
            int r = f >> 4, c = f & 15;
            cpa16(smb + EA_OFF(buf) + r*EA32_STRIDE + c*16,
                  ea + (size_t)(ebase+r)*64 + c*4);
        }
    };
    auto stagePD = [&](int buf, int ebase) {
        #pragma unroll
        for (int i = 0; i < 3; i++) {
            int f = tid + i*256;
            int r = f / 24, c = f - r*24;
            int e = ebase + r;
            int dst;
            if (is64) dst = (int)((const long long*)eidx_raw)[(size_t)NE + e];
            else      dst = ((const int*)eidx_raw)[(size_t)NE + e];
            cpa16(smb + PD_OFF(buf) + r*PD_STRIDE + c*16,
                  g_PDh + (size_t)dst*CD + c*8);
        }
    };
    auto stagePS = [&](int buf, int nodebase) {
        if (tid < 192) {
            int r = tid / 24, c = tid - r*24;
            cpa16(smb + PS_OFF(buf) + r*PD_STRIDE + c*16,
                  g_PSh + (size_t)(nodebase + r)*CD + c*8);
        }
    };

    int buf = 0, psb = 0;
    stagePD(0, blockIdx.x*96);
    stageEA(0, blockIdx.x*96);
    stagePS(0, blockIdx.x*8);
    cpa_commit();

    for (int st = blockIdx.x; st < NST; st += gridDim.x) {
        #pragma unroll 1
        for (int s = 0; s < 3; s++) {
            __syncthreads();   // readers of buf^1 (and A16) done
            int nst = (s < 2) ? st : st + (int)gridDim.x;
            int nss = (s < 2) ? s + 1 : 0;
            if (nst < NST) {
                stagePD(buf ^ 1, nst*96 + nss*32);
                stageEA(buf ^ 1, nst*96 + nss*32);
                if (s == 2) stagePS(psb ^ 1, nst*8);
            }
            cpa_commit();
            cpa_wait1();
            __syncthreads();

            // convert fp32 ea (buf) -> fp16 A-tile
            {
                const float4* src = (const float4*)(smc + EA_OFF(buf)
                                    + (tid >> 3)*EA32_STRIDE) + (tid & 7)*2;
                float4 f0 = src[0], f1 = src[1];
                __half2 h0 = __floats2half2_rn(f0.x, f0.y);
                __half2 h1 = __floats2half2_rn(f0.z, f0.w);
                __half2 h2 = __floats2half2_rn(f1.x, f1.y);
                __half2 h3 = __floats2half2_rn(f1.z, f1.w);
                uint4 u;
                u.x = *(unsigned*)&h0; u.y = *(unsigned*)&h1;
                u.z = *(unsigned*)&h2; u.w = *(unsigned*)&h3;
                *(uint4*)(smc + A16_OFF + (tid >> 3)*A16_STRIDE + (tid & 7)*16) = u;
            }
            __syncthreads();

            float C[6][4];
            #pragma unroll
            for (int nt = 0; nt < 6; nt++)
                #pragma unroll
                for (int q = 0; q < 4; q++) C[nt][q] = 0.f;

            #pragma unroll
            for (int ks = 0; ks < 4; ks++) {
                unsigned A[4];
                ldsm_x4(A, aBase + ks*32);
                #pragma unroll
                for (int nt = 0; nt < 6; nt++)
                    mma16816(C[nt], A, Bf[nt][ks]);
            }

            const __half* pd = (const __half*)(smc + PD_OFF(buf));
            const __half* ps = (const __half*)(smc + PS_OFF(psb));
            int r0 = mb + gq, r1 = r0 + 8;
            int ln0 = (s*32 + r0) / 12, ln1 = (s*32 + r1) / 12;
            #pragma unroll
            for (int nt = 0; nt < 6; nt++) {
                int P0 = nw*48 + nt*8 + 2*tl;
                float2 pd0 = __half22float2(*(const __half2*)(pd + r0*200 + P0));
                float2 pd1 = __half22float2(*(const __half2*)(pd + r1*200 + P0));
                float2 ps0 = __half22float2(*(const __half2*)(ps + ln0*200 + P0));
                float2 ps1 = __half22float2(*(const __half2*)(ps + ln1*200 + P0));
                float u0x = C[nt][0] + pd0.x + ps0.x, u0y = C[nt][1] + pd0.y + ps0.y;
                float u1x = C[nt][2] + pd1.x + ps1.x, u1y = C[nt][3] + pd1.y + ps1.y;
                sS[nt*2]   += u0x + u1x;
                sQ[nt*2]   += u0x*u0x + u1x*u1x;
                sS[nt*2+1] += u0y + u1y;
                sQ[nt*2+1] += u0y*u0y + u1y*u1y;
            }
            buf ^= 1;
        }
        psb ^= 1;
    }

    #pragma unroll
    for (int i = 0; i < 12; i++) {
        sS[i] += __shfl_xor_sync(0xffffffff, sS[i], 4);
        sS[i] += __shfl_xor_sync(0xffffffff, sS[i], 8);
        sS[i] += __shfl_xor_sync(0xffffffff, sS[i], 16);
        sQ[i] += __shfl_xor_sync(0xffffffff, sQ[i], 4);
        sQ[i] += __shfl_xor_sync(0xffffffff, sQ[i], 8);
        sQ[i] += __shfl_xor_sync(0xffffffff, sQ[i], 16);
    }
    if (lane < 4) {
        int bin = blockIdx.x & (NBINS - 1);
        #pragma unroll
        for (int nt = 0; nt < 6; nt++) {
            int col = nw*48 + nt*8 + 2*lane;
            atomicAdd(&g_binS[(size_t)col*NBINS + bin],     sS[nt*2]);
            atomicAdd(&g_binQ[(size_t)col*NBINS + bin],     sQ[nt*2]);
            atomicAdd(&g_binS[(size_t)(col+1)*NBINS + bin], sS[nt*2+1]);
            atomicAdd(&g_binQ[(size_t)(col+1)*NBINS + bin], sQ[nt*2+1]);
        }
    }
}

// ---------------- K3: reduce bins (permuted) -> scale/shift ----------
__global__ void k3_reduce(const float* __restrict__ g1, const float* __restrict__ be1,
                          const float* __restrict__ g2, const float* __restrict__ be2,
                          const float* __restrict__ g3, const float* __restrict__ be3)
{
    __shared__ float sS[256], sQ[256];
    int P = blockIdx.x, t = threadIdx.x;
    float S = 0.f, Q = 0.f;
    for (int b = t; b < NBINS; b += 256) {
        S += g_binS[(size_t)P*NBINS + b];
        Q += g_binQ[(size_t)P*NBINS + b];
    }
    sS[t] = S; sQ[t] = Q;
    __syncthreads();
    for (int o = 128; o > 0; o >>= 1) {
        if (t < o) { sS[t] += sS[t+o]; sQ[t] += sQ[t+o]; }
        __syncthreads();
    }
    if (t == 0) {
        float mean = sS[0] / (float)NE;
        float var  = sQ[0] / (float)NE - mean*mean;
        float g, be;
        if (P < 128) {
            int jj = P >> 1;
            if ((P & 1) == 0) { g = g1[jj]; be = be1[jj]; }
            else              { g = g2[jj]; be = be2[jj]; }
        } else { g = g3[P-128]; be = be3[P-128]; }
        float sc = g * rsqrtf(var + BN_EPS);
        g_scale[P] = sc;
        g_shift[P] = be - mean * sc;
    }
}

// ---------------- K4f: fused recompute + BN + gate + bond + node-sum ------
__global__ void __launch_bounds__(256, 2)
k4_fused(const float* __restrict__ ea,
         const void* __restrict__ eidx_raw,
         const float* __restrict__ Wc,
         const float* __restrict__ Wf,
         const float* __restrict__ Wb,
         float* __restrict__ bond_out)
{
    extern __shared__ char smc[];
    unsigned* sW32 = (unsigned*)smc;
    float* gated = (float*)(smc + GT_OFF);
    unsigned smb = smem_u32(smc);
    int tid = threadIdx.x;
    int w   = tid >> 5, lane = tid & 31;
    int gq  = lane >> 2, tl = lane & 3;
    int mb  = (w & 1) * 16;
    int nw  = (w >> 1);
    int is64 = g_is64;

    for (int i = tid; i < 192*32; i += 256) {
        int P = i >> 5, k2 = i & 31;
        const float* W; int r;
        if (P < 128) { r = P >> 1; W = (P & 1) ? Wf : Wc; }
        else         { r = P - 128; W = Wb; }
        float2 v = *(const float2*)(W + (size_t)r*CD + 128 + 2*k2);
        __half2 h = __floats2half2_rn(v.x, v.y);
        sW32[P*32 + k2] = *(unsigned*)&h;
    }
    __syncthreads();

    unsigned Bf[6][4][2];
    #pragma unroll
    for (int nt = 0; nt < 6; nt++) {
        int n = nw*48 + nt*8 + gq;
        #pragma unroll
        for (int ks = 0; ks < 4; ks++) {
            Bf[nt][ks][0] = sW32[n*32 + ks*8 + tl];
            Bf[nt][ks][1] = sW32[n*32 + ks*8 + tl + 4];
        }
    }

    float2 scp[6], shp[6];
    #pragma unroll
    for (int nt = 0; nt < 6; nt++) {
        int P0 = nw*48 + nt*8 + 2*tl;
        scp[nt] = *(const float2*)(g_scale + P0);
        shp[nt] = *(const float2*)(g_shift + P0);
    }

    unsigned aBase = smb + A16_OFF + (mb + (lane & 15))*A16_STRIDE + (lane >> 4)*16;
    float stS = 0.f, stQ = 0.f;

    auto stageEA = [&](int buf, int ebase) {
        #pragma unroll
        for (int i = 0; i < 2; i++) {
            int f = tid + i*256;
            int r = f >> 4, c = f & 15;
            cpa16(smb + EA_OFF(buf) + r*EA32_STRIDE + c*16,
                  ea + (size_t)(ebase+r)*64 + c*4);
        }
    };
    auto stagePD = [&](int buf, int ebase) {
        #pragma unroll
        for (int i = 0; i < 3; i++) {
            int f = tid + i*256;
            int r = f / 24, c = f - r*24;
            int e = ebase + r;
            int dst;
            if (is64) dst = (int)((const long long*)eidx_raw)[(size_t)NE + e];
            else      dst = ((const int*)eidx_raw)[(size_t)NE + e];
            cpa16(smb + PD_OFF(buf) + r*PD_STRIDE + c*16,
                  g_PDh + (size_t)dst*CD + c*8);
        }
    };
    auto stagePS = [&](int buf, int nodebase) {
        if (tid < 192) {
            int r = tid / 24, c = tid - r*24;
            cpa16(smb + PS_OFF(buf) + r*PD_STRIDE + c*16,
                  g_PSh + (size_t)(nodebase + r)*CD + c*8);
        }
    };

    int buf = 0, psb = 0;
    stagePD(0, blockIdx.x*96);
    stageEA(0, blockIdx.x*96);
    stagePS(0, blockIdx.x*8);
    cpa_commit();

    for (int st = blockIdx.x; st < NST; st += gridDim.x) {
        #pragma unroll 1
        for (int s = 0; s < 3; s++) {
            __syncthreads();   // readers of buf^1 / A16 / (gated at s==0) done
            int nst = (s < 2) ? st : st + (int)gridDim.x;
            int nss = (s < 2) ? s + 1 : 0;
            if (nst < NST) {
                stagePD(buf ^ 1, nst*96 + nss*32);
                stageEA(buf ^ 1, nst*96 + nss*32);
                if (s == 2) stagePS(psb ^ 1, nst*8);
            }
            cpa_commit();
            cpa_wait1();
            __syncthreads();

            // convert fp32 ea (buf) -> fp16 A-tile
            {
                const float4* src = (const float4*)(smc + EA_OFF(buf)
                                    + (tid >> 3)*EA32_STRIDE) + (tid & 7)*2;
                float4 f0 = src[0], f1 = src[1];
                __half2 h0 = __floats2half2_rn(f0.x, f0.y);
                __half2 h1 = __floats2half2_rn(f0.z, f0.w);
                __half2 h2 = __floats2half2_rn(f1.x, f1.y);
                __half2 h3 = __floats2half2_rn(f1.z, f1.w);
                uint4 u;
                u.x = *(unsigned*)&h0; u.y = *(unsigned*)&h1;
                u.z = *(unsigned*)&h2; u.w = *(unsigned*)&h3;
                *(uint4*)(smc + A16_OFF + (tid >> 3)*A16_STRIDE + (tid & 7)*16) = u;
            }
            __syncthreads();

            int ebase = st*96 + s*32;
            int r0 = mb + gq, r1 = r0 + 8;
            int e0g = ebase + r0, e1g = ebase + r1;

            float C[6][4];
            #pragma unroll
            for (int nt = 0; nt < 6; nt++)
                #pragma unroll
                for (int q = 0; q < 4; q++) C[nt][q] = 0.f;

            #pragma unroll
            for (int ks = 0; ks < 4; ks++) {
                unsigned A[4];
                ldsm_x4(A, aBase + ks*32);
                #pragma unroll
                for (int nt = 0; nt < 6; nt++)
                    mma16816(C[nt], A, Bf[nt][ks]);
            }

            const __half* pd = (const __half*)(smc + PD_OFF(buf));
            const __half* ps = (const __half*)(smc + PS_OFF(psb));
            const float* eaS = (const float*)(smc + EA_OFF(buf));
            int ln0 = (s*32 + r0) / 12, ln1 = (s*32 + r1) / 12;
            int row0 = s*32 + r0, row1 = s*32 + r1;

            #pragma unroll
            for (int nt = 0; nt < 6; nt++) {
                int P0 = nw*48 + nt*8 + 2*tl;
                float2 pd0 = __half22float2(*(const __half2*)(pd + r0*200 + P0));
                float2 pd1 = __half22float2(*(const __half2*)(pd + r1*200 + P0));
                float2 ps0 = __half22float2(*(const __half2*)(ps + ln0*200 + P0));
                float2 ps1 = __half22float2(*(const __half2*)(ps + ln1*200 + P0));
                float v00 = fmaf(C[nt][0] + pd0.x + ps0.x, scp[nt].x, shp[nt].x);
                float v01 = fmaf(C[nt][1] + pd0.y + ps0.y, scp[nt].y, shp[nt].y);
                float v10 = fmaf(C[nt][2] + pd1.x + ps1.x, scp[nt].x, shp[nt].x);
                float v11 = fmaf(C[nt][3] + pd1.y + ps1.y, scp[nt].y, shp[nt].y);
                if (P0 < 128) {
                    int j = P0 >> 1;   // even=core(sigmoid), odd=filter(softplus)
                    gated[row0*GT_STRIDE + j] = sigmoid_f(v00) * softplus_f(v01);
                    gated[row1*GT_STRIDE + j] = sigmoid_f(v10) * softplus_f(v11);
                } else {
                    int jb = P0 - 128;
                    float2 ev0 = *(const float2*)(eaS + r0*68 + jb);
                    float2 ev1 = *(const float2*)(eaS + r1*68 + jb);
                    float2 bo0, bo1;
                    bo0.x = softplus_f(ev0.x + v00);
                    bo0.y = softplus_f(ev0.y + v01);
                    bo1.x = softplus_f(ev1.x + v10);
                    bo1.y = softplus_f(ev1.y + v11);
                    *(float2*)(bond_out + (size_t)e0g*64 + jb) = bo0;
                    *(float2*)(bond_out + (size_t)e1g*64 + jb) = bo1;
                }
            }
            buf ^= 1;
        }
        __syncthreads();   // gated complete

        {
            int j = tid & 63;
            #pragma unroll
            for (int h = 0; h < 2; h++) {
                int d = (tid >> 6) + 4*h;
                float acc = 0.f;
                #pragma unroll
                for (int k = 0; k < 12; k++)
                    acc += gated[(d*12 + k)*GT_STRIDE + j];
                g_nbr[(size_t)(st*8 + d)*64 + j] = acc;
                stS += acc; stQ += acc*acc;
            }
        }
        psb ^= 1;
    }

    {
        int j = tid & 63;
        int bin = blockIdx.x & (NB4 - 1);
        atomicAdd(&g_b4S[j*NB4 + bin], stS);
        atomicAdd(&g_b4Q[j*NB4 + bin], stQ);
    }
}

// ---------------- K5: parallel reduce node-BN ----------------
__global__ void k5_reduce(const float* __restrict__ g4, const float* __restrict__ be4)
{
    __shared__ float sS[256], sQ[256];
    int j = blockIdx.x, t = threadIdx.x;
    float S = (t < NB4) ? g_b4S[j*NB4 + t] : 0.f;
    float Q = (t < NB4) ? g_b4Q[j*NB4 + t] : 0.f;
    sS[t] = S; sQ[t] = Q;
    __syncthreads();
    for (int o = 128; o > 0; o >>= 1) {
        if (t < o) { sS[t] += sS[t+o]; sQ[t] += sQ[t+o]; }
        __syncthreads();
    }
    if (t == 0) {
        float mean = sS[0] / (float)NN;
        float var  = sQ[0] / (float)NN - mean*mean;
        float sc = g4[j] * rsqrtf(var + BN_EPS);
        g_scale4[j] = sc;
        g_shift4[j] = be4[j] - mean * sc;
    }
}

// ---------------- K6: out = softplus(x + bn4(nbr_sum)) ----------------
__global__ void k6_out(const float* __restrict__ x, float* __restrict__ out)
{
    int i = blockIdx.x * 256 + threadIdx.x;
    if (i < NN*64) {
        int j = i & 63;
        float v = x[i] + fmaf(g_nbr[i], g_scale4[j], g_shift4[j]);
        out[i] = softplus_f(v);
    }
}

extern "C" void kernel_launch(void* const* d_in, const int* in_sizes, int n_in,
                              void* d_out, int out_size)
{
    const float* x   = (const float*)d_in[0];
    const void*  ei  = (const void*)d_in[1];
    const float* ea  = (const float*)d_in[2];
    const float* Wc  = (const float*)d_in[3];
    const float* bc  = (const float*)d_in[4];
    const float* Wf  = (const float*)d_in[5];
    const float* bf  = (const float*)d_in[6];
    const float* Wb  = (const float*)d_in[7];
    const float* bb  = (const float*)d_in[8];
    const float* g1  = (const float*)d_in[9];
    const float* be1 = (const float*)d_in[10];
    const float* g2  = (const float*)d_in[11];
    const float* be2 = (const float*)d_in[12];
    const float* g3  = (const float*)d_in[13];
    const float* be3 = (const float*)d_in[14];
    const float* g4  = (const float*)d_in[15];
    const float* be4 = (const float*)d_in[16];

    float* out  = (float*)d_out;
    float* bond = out + (size_t)NN * 64;

    cudaFuncSetAttribute(k1_nodegemm, cudaFuncAttributeMaxDynamicSharedMemorySize, K1_SMEM);
    cudaFuncSetAttribute(k2_stats,    cudaFuncAttributeMaxDynamicSharedMemorySize, K2_SMEM);
    cudaFuncSetAttribute(k4_fused,    cudaFuncAttributeMaxDynamicSharedMemorySize, K4_SMEM);

    k1_nodegemm<<<K1G, dim3(96,2,1), K1_SMEM>>>(x, (const int*)ei, Wc, bc, Wf, bf, Wb, bb);
    k2_stats<<<K2G, 256, K2_SMEM>>>(ea, ei, Wc, Wf, Wb);
    k3_reduce<<<CD, 256>>>(g1, be1, g2, be2, g3, be3);
    k4_fused<<<K4G, 256, K4_SMEM>>>(ea, ei, Wc, Wf, Wb, bond);
    k5_reduce<<<KD, 256>>>(g4, be4);
    k6_out<<<(NN*64 + 255)/256, 256>>>(x, out);
}

// round 11
// speedup vs baseline: 1.3029x; 1.0046x over previous
#include <cuda_runtime.h>
#include <cuda_fp16.h>
#include <math.h>

#define NN 100000
#define NNBR 12
#define NE (NN*NNBR)
#define CD 192
#define KD 64
#define NBINS 1024
#define NB4 256
#define BN_EPS 1e-5f

#define K1G 296
#define K2G 296
#define K4G 296
#define NST 12500   // NE/96 supertiles (8 nodes each)

// ---------------- scratch (static __device__, no allocs) ----------------
// PD/PS stored in PERMUTED column order: P<128: even=core j (j=P/2),
// odd=filter j; P>=128: bond j=P-128.
__device__ __half g_PDh[(size_t)NN*CD];
__device__ __half g_PSh[(size_t)NN*CD];
__device__ float  g_binS[(size_t)CD*NBINS];  // [P][bin]
__device__ float  g_binQ[(size_t)CD*NBINS];
__device__ float  g_scale[CD];               // permuted order
__device__ float  g_shift[CD];
__device__ float  g_nbr[NN*KD];
__device__ float  g_b4S[KD*NB4];
__device__ float  g_b4Q[KD*NB4];
__device__ float  g_scale4[KD];
__device__ float  g_shift4[KD];
__device__ int    g_is64;

__device__ __forceinline__ void ffma2(float2 &d, float2 a, float2 b) {
    asm("fma.rn.f32x2 %0, %1, %2, %0;"
        : "+l"(reinterpret_cast<unsigned long long&>(d))
        : "l"(reinterpret_cast<unsigned long long&>(a)),
          "l"(reinterpret_cast<unsigned long long&>(b)));
}

__device__ __forceinline__ void mma16816(float* c, const unsigned* a, const unsigned* b) {
    asm volatile(
        "mma.sync.aligned.m16n8k16.row.col.f32.f16.f16.f32 "
        "{%0,%1,%2,%3}, {%4,%5,%6,%7}, {%8,%9}, {%0,%1,%2,%3};"
        : "+f"(c[0]), "+f"(c[1]), "+f"(c[2]), "+f"(c[3])
        : "r"(a[0]), "r"(a[1]), "r"(a[2]), "r"(a[3]), "r"(b[0]), "r"(b[1]));
}

__device__ __forceinline__ void ldsm_x4(unsigned* a, unsigned saddr) {
    asm volatile("ldmatrix.sync.aligned.m8n8.x4.shared.b16 {%0,%1,%2,%3}, [%4];"
        : "=r"(a[0]), "=r"(a[1]), "=r"(a[2]), "=r"(a[3]) : "r"(saddr));
}

__device__ __forceinline__ unsigned smem_u32(const void* p) {
    return (unsigned)__cvta_generic_to_shared(p);
}
__device__ __forceinline__ void cpa16(unsigned s, const void* g) {
    asm volatile("cp.async.cg.shared.global [%0], [%1], 16;" :: "r"(s), "l"(g));
}
__device__ __forceinline__ void cpa_commit() {
    asm volatile("cp.async.commit_group;");
}
__device__ __forceinline__ void cpa_wait1() {
    asm volatile("cp.async.wait_group 1;");
}

__device__ __forceinline__ float softplus_f(float x) {
    return fmaxf(x, 0.f) + __logf(1.f + __expf(-fabsf(x)));
}
__device__ __forceinline__ float sigmoid_f(float x) {
    return __fdividef(1.f, 1.f + __expf(-x));
}

__device__ __forceinline__ int permP(int j) {
    if (j < 64)  return 2*j;
    if (j < 128) return 2*(j-64) + 1;
    return j;
}

// ---------------- K1: zero stats + detect dtype + node pre-GEMM -----------
#define K1_SMEM (64*384*4 + 2*64*8*4)
__global__ void k1_nodegemm(const float* __restrict__ x,
                            const int*   __restrict__ eidx32,
                            const float* __restrict__ Wc, const float* __restrict__ bc,
                            const float* __restrict__ Wf, const float* __restrict__ bf,
                            const float* __restrict__ Wb, const float* __restrict__ bb)
{
    extern __shared__ float sm[];
    float* sW = sm;             // [64][384]
    float* sX = sm + 64*384;    // [2][64][8]
    int tx = threadIdx.x, ty = threadIdx.y;
    int tid = ty*96 + tx;
    int gtid = blockIdx.x*192 + tid;

    for (int i = gtid; i < CD*NBINS; i += K1G*192) { g_binS[i] = 0.f; g_binQ[i] = 0.f; }
    for (int i = gtid; i < KD*NB4;   i += K1G*192) { g_b4S[i]  = 0.f; g_b4Q[i]  = 0.f; }
    if (gtid == 0) g_is64 = (eidx32[25] == 0) ? 1 : 0;

    for (int idx = tid; idx < 64*384; idx += 192) {
        int k  = idx / 384;
        int j3 = idx - k*384;
        int j  = (j3 >= 192) ? j3 - 192 : j3;
        int kk = (j3 >= 192) ? 64 + k : k;
        const float* W; int r;
        if (j < 64)       { W = Wc; r = j; }
        else if (j < 128) { W = Wf; r = j - 64; }
        else              { W = Wb; r = j - 128; }
        sW[idx] = W[r*CD + kk];
    }
    int j0 = tx, j1 = tx + 96;
    int P0 = permP(j0), P1 = permP(j1);
    float bias0 = (j0 < 64) ? bc[j0] : ((j0 < 128) ? bf[j0-64] : bb[j0-128]);
    float bias1 = (j1 < 128) ? bf[j1-64] : bb[j1-128];
    float* sXt = sX + ty*512;

    for (int g = blockIdx.x; g < NN/16; g += gridDim.x) {
        int n0 = (g*2 + ty) * 8;
        __syncthreads();
        const float4* x4 = (const float4*)(x + (size_t)n0*64);
        for (int i = tx; i < 128; i += 96) {
            float4 v = x4[i];
            int nl = i >> 4, k4 = (i & 15) * 4;
            sXt[(k4+0)*8 + nl] = v.x;
            sXt[(k4+1)*8 + nl] = v.y;
            sXt[(k4+2)*8 + nl] = v.z;
            sXt[(k4+3)*8 + nl] = v.w;
        }
        __syncthreads();

        float2 ad0[4], ad1[4], as0[4], as1[4];
        #pragma unroll
        for (int p = 0; p < 4; p++) {
            ad0[p] = make_float2(0.f,0.f); ad1[p] = make_float2(0.f,0.f);
            as0[p] = make_float2(0.f,0.f); as1[p] = make_float2(0.f,0.f);
        }
        #pragma unroll 8
        for (int k = 0; k < 64; k++) {
            float wd0 = sW[k*384 + j0];
            float wd1 = sW[k*384 + j1];
            float ws0 = sW[k*384 + 192 + j0];
            float ws1 = sW[k*384 + 192 + j1];
            float2 Wd0 = make_float2(wd0, wd0), Wd1 = make_float2(wd1, wd1);
            float2 Ws0 = make_float2(ws0, ws0), Ws1 = make_float2(ws1, ws1);
            const float2* xp = (const float2*)(sXt + k*8);
            #pragma unroll
            for (int p = 0; p < 4; p++) {
                float2 xv = xp[p];
                ffma2(ad0[p], xv, Wd0);
                ffma2(ad1[p], xv, Wd1);
                ffma2(as0[p], xv, Ws0);
                ffma2(as1[p], xv, Ws1);
            }
        }
        #pragma unroll
        for (int p = 0; p < 4; p++) {
            size_t na = (size_t)(n0 + 2*p)*CD, nb = na + CD;
            g_PDh[na + P0] = __float2half_rn(ad0[p].x + bias0);
            g_PDh[nb + P0] = __float2half_rn(ad0[p].y + bias0);
            g_PDh[na + P1] = __float2half_rn(ad1[p].x + bias1);
            g_PDh[nb + P1] = __float2half_rn(ad1[p].y + bias1);
            g_PSh[na + P0] = __float2half_rn(as0[p].x);
            g_PSh[nb + P0] = __float2half_rn(as0[p].y);
            g_PSh[na + P1] = __float2half_rn(as1[p].x);
            g_PSh[nb + P1] = __float2half_rn(as1[p].y);
        }
    }
}

// ---------------- shared smem layout for k2/k4 ----------------------------
#define SW_BYTES   (192*32*4)       // 24576: permuted W_edge fp16 [P][64k]
#define EA32_STRIDE 272             // 64 floats + 16B pad
#define EA32B      (32*EA32_STRIDE) // 8704
#define A16_STRIDE 144              // 64 halves + 16B pad (LDSM conflict-free)
#define A16B       (32*A16_STRIDE)  // 4608
#define PD_STRIDE  400
#define PDB        (32*PD_STRIDE)   // 12800
#define PSB        (8*PD_STRIDE)    // 3200
#define EA_OFF(b)  (SW_BYTES + (b)*EA32B)
#define A16_OFF    (SW_BYTES + 2*EA32B)
#define PD_OFF(b)  (A16_OFF + A16B + (b)*PDB)
#define PS_OFF(b)  (A16_OFF + A16B + 2*PDB + (b)*PSB)
#define COMMON_SMEM (A16_OFF + A16B + 2*PDB + 2*PSB)   // 78592
#define GT_OFF     COMMON_SMEM
#define GT_STRIDE  68
#define K2_SMEM    COMMON_SMEM
#define K4_SMEM    (GT_OFF + 96*GT_STRIDE*4)           // 104704

// ---------------- K2s: stats-only edge GEMM (supertile-96) ----------------
__global__ void __launch_bounds__(256, 2)
k2_stats(const float* __restrict__ ea,
         const void* __restrict__ eidx_raw,
         const float* __restrict__ Wc,
         const float* __restrict__ Wf,
         const float* __restrict__ Wb)
{
    extern __shared__ char smc[];
    unsigned* sW32 = (unsigned*)smc;
    unsigned smb = smem_u32(smc);
    int tid = threadIdx.x;
    int w   = tid >> 5, lane = tid & 31;
    int gq  = lane >> 2, tl = lane & 3;
    int mb  = (w & 1) * 16;
    int nw  = (w >> 1);
    int is64 = g_is64;

    for (int i = tid; i < 192*32; i += 256) {
        int P = i >> 5, k2 = i & 31;
        const float* W; int r;
        if (P < 128) { r = P >> 1; W = (P & 1) ? Wf : Wc; }
        else         { r = P - 128; W = Wb; }
        float2 v = *(const float2*)(W + (size_t)r*CD + 128 + 2*k2);
        __half2 h = __floats2half2_rn(v.x, v.y);
        sW32[P*32 + k2] = *(unsigned*)&h;
    }
    __syncthreads();

    unsigned Bf[6][4][2];
    #pragma unroll
    for (int nt = 0; nt < 6; nt++) {
        int n = nw*48 + nt*8 + gq;
        #pragma unroll
        for (int ks = 0; ks < 4; ks++) {
            Bf[nt][ks][0] = sW32[n*32 + ks*8 + tl];
            Bf[nt][ks][1] = sW32[n*32 + ks*8 + tl + 4];
        }
    }
    __syncthreads();

    // per-lane ldmatrix base address (rows mb..mb+15 of A16 tile)
    unsigned aBase = smb + A16_OFF + (mb + (lane & 15))*A16_STRIDE + (lane >> 4)*16;

    float sS[12], sQ[12];
    #pragma unroll
    for (int i = 0; i < 12; i++) { sS[i] = 0.f; sQ[i] = 0.f; }

    auto stageEA = [&](int buf, int ebase) {
        #pragma unroll
        for (int i = 0; i < 2; i++) {
            int f = tid + i*256;
            int r = f >> 4, c = f & 15;
            cpa16(smb + EA_OFF(buf) + r*EA32_STRIDE + c*16,
                  ea + (size_t)(ebase+r)*64 + c*4);
        }
    };
    auto stagePD = [&](int buf, int ebase) {
        #pragma unroll
        for (int i = 0; i < 3; i++) {
            int f = tid + i*256;
            int r = f / 24, c = f - r*24;
            int e = ebase + r;
            int dst;
            if (is64) dst = (int)((const long long*)eidx_raw)[(size_t)NE + e];
            else      dst = ((const int*)eidx_raw)[(size_t)NE + e];
            cpa16(smb + PD_OFF(buf) + r*PD_STRIDE + c*16,
                  g_PDh + (size_t)dst*CD + c*8);
        }
    };
    auto stagePS = [&](int buf, int nodebase) {
        if (tid < 192) {
            int r = tid / 24, c = tid - r*24;
            cpa16(smb + PS_OFF(buf) + r*PD_STRIDE + c*16,
                  g_PSh + (size_t)(nodebase + r)*CD + c*8);
        }
    };

    int buf = 0, psb = 0;
    stagePD(0, blockIdx.x*96);
    stageEA(0, blockIdx.x*96);
    stagePS(0, blockIdx.x*8);
    cpa_commit();

    for (int st = blockIdx.x; st < NST; st += gridDim.x) {
        #pragma unroll 1
        for (int s = 0; s < 3; s++) {
            __syncthreads();   // readers of buf^1 (and A16) done
            int nst = (s < 2) ? st : st + (int)gridDim.x;
            int nss = (s < 2) ? s + 1 : 0;
            if (nst < NST) {
                stagePD(buf ^ 1, nst*96 + nss*32);
                stageEA(buf ^ 1, nst*96 + nss*32);
                if (s == 2) stagePS(psb ^ 1, nst*8);
            }
            cpa_commit();
            cpa_wait1();
            __syncthreads();

            // convert fp32 ea (buf) -> fp16 A-tile
            {
                const float4* src = (const float4*)(smc + EA_OFF(buf)
                                    + (tid >> 3)*EA32_STRIDE) + (tid & 7)*2;
                float4 f0 = src[0], f1 = src[1];
                __half2 h0 = __floats2half2_rn(f0.x, f0.y);
                __half2 h1 = __floats2half2_rn(f0.z, f0.w);
                __half2 h2 = __floats2half2_rn(f1.x, f1.y);
                __half2 h3 = __floats2half2_rn(f1.z, f1.w);
                uint4 u;
                u.x = *(unsigned*)&h0; u.y = *(unsigned*)&h1;
                u.z = *(unsigned*)&h2; u.w = *(unsigned*)&h3;
                *(uint4*)(smc + A16_OFF + (tid >> 3)*A16_STRIDE + (tid & 7)*16) = u;
            }
            __syncthreads();

            float C[6][4];
            #pragma unroll
            for (int nt = 0; nt < 6; nt++)
                #pragma unroll
                for (int q = 0; q < 4; q++) C[nt][q] = 0.f;

            #pragma unroll
            for (int ks = 0; ks < 4; ks++) {
                unsigned A[4];
                ldsm_x4(A, aBase + ks*32);
                #pragma unroll
                for (int nt = 0; nt < 6; nt++)
                    mma16816(C[nt], A, Bf[nt][ks]);
            }

            const __half* pd = (const __half*)(smc + PD_OFF(buf));
            const __half* ps = (const __half*)(smc + PS_OFF(psb));
            int r0 = mb + gq, r1 = r0 + 8;
            int ln0 = (s*32 + r0) / 12, ln1 = (s*32 + r1) / 12;
            #pragma unroll
            for (int nt = 0; nt < 6; nt++) {
                int P0 = nw*48 + nt*8 + 2*tl;
                float2 pd0 = __half22float2(*(const __half2*)(pd + r0*200 + P0));
                float2 pd1 = __half22float2(*(const __half2*)(pd + r1*200 + P0));
                float2 ps0 = __half22float2(*(const __half2*)(ps + ln0*200 + P0));
                float2 ps1 = __half22float2(*(const __half2*)(ps + ln1*200 + P0));
                float u0x = C[nt][0] + pd0.x + ps0.x, u0y = C[nt][1] + pd0.y + ps0.y;
                float u1x = C[nt][2] + pd1.x + ps1.x, u1y = C[nt][3] + pd1.y + ps1.y;
                sS[nt*2]   += u0x + u1x;
                sQ[nt*2]   += u0x*u0x + u1x*u1x;
                sS[nt*2+1] += u0y + u1y;
                sQ[nt*2+1] += u0y*u0y + u1y*u1y;
            }
            buf ^= 1;
        }
        psb ^= 1;
    }

    #pragma unroll
    for (int i = 0; i < 12; i++) {
        sS[i] += __shfl_xor_sync(0xffffffff, sS[i], 4);
        sS[i] += __shfl_xor_sync(0xffffffff, sS[i], 8);
        sS[i] += __shfl_xor_sync(0xffffffff, sS[i], 16);
        sQ[i] += __shfl_xor_sync(0xffffffff, sQ[i], 4);
        sQ[i] += __shfl_xor_sync(0xffffffff, sQ[i], 8);
        sQ[i] += __shfl_xor_sync(0xffffffff, sQ[i], 16);
    }
    if (lane < 4) {
        int bin = blockIdx.x & (NBINS - 1);
        #pragma unroll
        for (int nt = 0; nt < 6; nt++) {
            int col = nw*48 + nt*8 + 2*lane;
            atomicAdd(&g_binS[(size_t)col*NBINS + bin],     sS[nt*2]);
            atomicAdd(&g_binQ[(size_t)col*NBINS + bin],     sQ[nt*2]);
            atomicAdd(&g_binS[(size_t)(col+1)*NBINS + bin], sS[nt*2+1]);
            atomicAdd(&g_binQ[(size_t)(col+1)*NBINS + bin], sQ[nt*2+1]);
        }
    }
}

// ---------------- K3: reduce bins (permuted) -> scale/shift ----------
__global__ void k3_reduce(const float* __restrict__ g1, const float* __restrict__ be1,
                          const float* __restrict__ g2, const float* __restrict__ be2,
                          const float* __restrict__ g3, const float* __restrict__ be3)
{
    __shared__ float sS[256], sQ[256];
    int P = blockIdx.x, t = threadIdx.x;
    float S = 0.f, Q = 0.f;
    for (int b = t; b < NBINS; b += 256) {
        S += g_binS[(size_t)P*NBINS + b];
        Q += g_binQ[(size_t)P*NBINS + b];
    }
    sS[t] = S; sQ[t] = Q;
    __syncthreads();
    for (int o = 128; o > 0; o >>= 1) {
        if (t < o) { sS[t] += sS[t+o]; sQ[t] += sQ[t+o]; }
        __syncthreads();
    }
    if (t == 0) {
        float mean = sS[0] / (float)NE;
        float var  = sQ[0] / (float)NE - mean*mean;
        float g, be;
        if (P < 128) {
            int jj = P >> 1;
            if ((P & 1) == 0) { g = g1[jj]; be = be1[jj]; }
            else              { g = g2[jj]; be = be2[jj]; }
        } else { g = g3[P-128]; be = be3[P-128]; }
        float sc = g * rsqrtf(var + BN_EPS);
        g_scale[P] = sc;
        g_shift[P] = be - mean * sc;
    }
}

// ---------------- K4f: fused recompute + BN + gate + bond + node-sum ------
__global__ void __launch_bounds__(256, 2)
k4_fused(const float* __restrict__ ea,
         const void* __restrict__ eidx_raw,
         const float* __restrict__ Wc,
         const float* __restrict__ Wf,
         const float* __restrict__ Wb,
         float* __restrict__ bond_out)
{
    extern __shared__ char smc[];
    unsigned* sW32 = (unsigned*)smc;
    float* gated = (float*)(smc + GT_OFF);
    unsigned smb = smem_u32(smc);
    int tid = threadIdx.x;
    int w   = tid >> 5, lane = tid & 31;
    int gq  = lane >> 2, tl = lane & 3;
    int mb  = (w & 1) * 16;
    int nw  = (w >> 1);
    int is64 = g_is64;

    for (int i = tid; i < 192*32; i += 256) {
        int P = i >> 5, k2 = i & 31;
        const float* W; int r;
        if (P < 128) { r = P >> 1; W = (P & 1) ? Wf : Wc; }
        else         { r = P - 128; W = Wb; }
        float2 v = *(const float2*)(W + (size_t)r*CD + 128 + 2*k2);
        __half2 h = __floats2half2_rn(v.x, v.y);
        sW32[P*32 + k2] = *(unsigned*)&h;
    }
    __syncthreads();

    unsigned Bf[6][4][2];
    #pragma unroll
    for (int nt = 0; nt < 6; nt++) {
        int n = nw*48 + nt*8 + gq;
        #pragma unroll
        for (int ks = 0; ks < 4; ks++) {
            Bf[nt][ks][0] = sW32[n*32 + ks*8 + tl];
            Bf[nt][ks][1] = sW32[n*32 + ks*8 + tl + 4];
        }
    }

    float2 scp[6], shp[6];
    #pragma unroll
    for (int nt = 0; nt < 6; nt++) {
        int P0 = nw*48 + nt*8 + 2*tl;
        scp[nt] = *(const float2*)(g_scale + P0);
        shp[nt] = *(const float2*)(g_shift + P0);
    }

    unsigned aBase = smb + A16_OFF + (mb + (lane & 15))*A16_STRIDE + (lane >> 4)*16;
    float stS = 0.f, stQ = 0.f;

    auto stageEA = [&](int buf, int ebase) {
        #pragma unroll
        for (int i = 0; i < 2; i++) {
            int f = tid + i*256;
            int r = f >> 4, c = f & 15;
            cpa16(smb + EA_OFF(buf) + r*EA32_STRIDE + c*16,
                  ea + (size_t)(ebase+r)*64 + c*4);
        }
    };
    auto stagePD = [&](int buf, int ebase) {
        #pragma unroll
        for (int i = 0; i < 3; i++) {
            int f = tid + i*256;
            int r = f / 24, c = f - r*24;
            int e = ebase + r;
            int dst;
            if (is64) dst = (int)((const long long*)eidx_raw)[(size_t)NE + e];
            else      dst = ((const int*)eidx_raw)[(size_t)NE + e];
            cpa16(smb + PD_OFF(buf) + r*PD_STRIDE + c*16,
                  g_PDh + (size_t)dst*CD + c*8);
        }
    };
    auto stagePS = [&](int buf, int nodebase) {
        if (tid < 192) {
            int r = tid / 24, c = tid - r*24;
            cpa16(smb + PS_OFF(buf) + r*PD_STRIDE + c*16,
                  g_PSh + (size_t)(nodebase + r)*CD + c*8);
        }
    };

    int buf = 0, psb = 0;
    stagePD(0, blockIdx.x*96);
    stageEA(0, blockIdx.x*96);
    stagePS(0, blockIdx.x*8);
    cpa_commit();

    for (int st = blockIdx.x; st < NST; st += gridDim.x) {
        #pragma unroll 1
        for (int s = 0; s < 3; s++) {
            __syncthreads();   // readers of buf^1 / A16 / (gated at s==0) done
            int nst = (s < 2) ? st : st + (int)gridDim.x;
            int nss = (s < 2) ? s + 1 : 0;
            if (nst < NST) {
                stagePD(buf ^ 1, nst*96 + nss*32);
                stageEA(buf ^ 1, nst*96 + nss*32);
                if (s == 2) stagePS(psb ^ 1, nst*8);
            }
            cpa_commit();
            cpa_wait1();
            __syncthreads();

            // convert fp32 ea (buf) -> fp16 A-tile
            {
                const float4* src = (const float4*)(smc + EA_OFF(buf)
                                    + (tid >> 3)*EA32_STRIDE) + (tid & 7)*2;
                float4 f0 = src[0], f1 = src[1];
                __half2 h0 = __floats2half2_rn(f0.x, f0.y);
                __half2 h1 = __floats2half2_rn(f0.z, f0.w);
                __half2 h2 = __floats2half2_rn(f1.x, f1.y);
                __half2 h3 = __floats2half2_rn(f1.z, f1.w);
                uint4 u;
                u.x = *(unsigned*)&h0; u.y = *(unsigned*)&h1;
                u.z = *(unsigned*)&h2; u.w = *(unsigned*)&h3;
                *(uint4*)(smc + A16_OFF + (tid >> 3)*A16_STRIDE + (tid & 7)*16) = u;
            }
            __syncthreads();

            int ebase = st*96 + s*32;
            int r0 = mb + gq, r1 = r0 + 8;
            int e0g = ebase + r0, e1g = ebase + r1;

            float C[6][4];
            #pragma unroll
            for (int nt = 0; nt < 6; nt++)
                #pragma unroll
                for (int q = 0; q < 4; q++) C[nt][q] = 0.f;

            #pragma unroll
            for (int ks = 0; ks < 4; ks++) {
                unsigned A[4];
                ldsm_x4(A, aBase + ks*32);
                #pragma unroll
                for (int nt = 0; nt < 6; nt++)
                    mma16816(C[nt], A, Bf[nt][ks]);
            }

            const __half* pd = (const __half*)(smc + PD_OFF(buf));
            const __half* ps = (const __half*)(smc + PS_OFF(psb));
            const float* eaS = (const float*)(smc + EA_OFF(buf));
            int ln0 = (s*32 + r0) / 12, ln1 = (s*32 + r1) / 12;
            int row0 = s*32 + r0, row1 = s*32 + r1;

            #pragma unroll
            for (int nt = 0; nt < 6; nt++) {
                int P0 = nw*48 + nt*8 + 2*tl;
                float2 pd0 = __half22float2(*(const __half2*)(pd + r0*200 + P0));
                float2 pd1 = __half22float2(*(const __half2*)(pd + r1*200 + P0));
                float2 ps0 = __half22float2(*(const __half2*)(ps + ln0*200 + P0));
                float2 ps1 = __half22float2(*(const __half2*)(ps + ln1*200 + P0));
                float v00 = fmaf(C[nt][0] + pd0.x + ps0.x, scp[nt].x, shp[nt].x);
                float v01 = fmaf(C[nt][1] + pd0.y + ps0.y, scp[nt].y, shp[nt].y);
                float v10 = fmaf(C[nt][2] + pd1.x + ps1.x, scp[nt].x, shp[nt].x);
                float v11 = fmaf(C[nt][3] + pd1.y + ps1.y, scp[nt].y, shp[nt].y);
                if (P0 < 128) {
                    int j = P0 >> 1;   // even=core(sigmoid), odd=filter(softplus)
                    gated[row0*GT_STRIDE + j] = sigmoid_f(v00) * softplus_f(v01);
                    gated[row1*GT_STRIDE + j] = sigmoid_f(v10) * softplus_f(v11);
                } else {
                    int jb = P0 - 128;
                    float2 ev0 = *(const float2*)(eaS + r0*68 + jb);
                    float2 ev1 = *(const float2*)(eaS + r1*68 + jb);
                    float2 bo0, bo1;
                    bo0.x = softplus_f(ev0.x + v00);
                    bo0.y = softplus_f(ev0.y + v01);
                    bo1.x = softplus_f(ev1.x + v10);
                    bo1.y = softplus_f(ev1.y + v11);
                    *(float2*)(bond_out + (size_t)e0g*64 + jb) = bo0;
                    *(float2*)(bond_out + (size_t)e1g*64 + jb) = bo1;
                }
            }
            buf ^= 1;
        }
        __syncthreads();   // gated complete

        {
            int j = tid & 63;
            #pragma unroll
            for (int h = 0; h < 2; h++) {
                int d = (tid >> 6) + 4*h;
                float acc = 0.f;
                #pragma unroll
                for (int k = 0; k < 12; k++)
                    acc += gated[(d*12 + k)*GT_STRIDE + j];
                g_nbr[(size_t)(st*8 + d)*64 + j] = acc;
                stS += acc; stQ += acc*acc;
            }
        }
        psb ^= 1;
    }

    {
        int j = tid & 63;
        int bin = blockIdx.x & (NB4 - 1);
        atomicAdd(&g_b4S[j*NB4 + bin], stS);
        atomicAdd(&g_b4Q[j*NB4 + bin], stQ);
    }
}

// ---------------- K5: parallel reduce node-BN ----------------
__global__ void k5_reduce(const float* __restrict__ g4, const float* __restrict__ be4)
{
    __shared__ float sS[256], sQ[256];
    int j = blockIdx.x, t = threadIdx.x;
    float S = (t < NB4) ? g_b4S[j*NB4 + t] : 0.f;
    float Q = (t < NB4) ? g_b4Q[j*NB4 + t] : 0.f;
    sS[t] = S; sQ[t] = Q;
    __syncthreads();
    for (int o = 128; o > 0; o >>= 1) {
        if (t < o) { sS[t] += sS[t+o]; sQ[t] += sQ[t+o]; }
        __syncthreads();
    }
    if (t == 0) {
        float mean = sS[0] / (float)NN;
        float var  = sQ[0] / (float)NN - mean*mean;
        float sc = g4[j] * rsqrtf(var + BN_EPS);
        g_scale4[j] = sc;
        g_shift4[j] = be4[j] - mean * sc;
    }
}

// ---------------- K6: out = softplus(x + bn4(nbr_sum)) ----------------
__global__ void k6_out(const float* __restrict__ x, float* __restrict__ out)
{
    int i = blockIdx.x * 256 + threadIdx.x;
    if (i < NN*64) {
        int j = i & 63;
        float v = x[i] + fmaf(g_nbr[i], g_scale4[j], g_shift4[j]);
        out[i] = softplus_f(v);
    }
}

extern "C" void kernel_launch(void* const* d_in, const int* in_sizes, int n_in,
                              void* d_out, int out_size)
{
    const float* x   = (const float*)d_in[0];
    const void*  ei  = (const void*)d_in[1];
    const float* ea  = (const float*)d_in[2];
    const float* Wc  = (const float*)d_in[3];
    const float* bc  = (const float*)d_in[4];
    const float* Wf  = (const float*)d_in[5];
    const float* bf  = (const float*)d_in[6];
    const float* Wb  = (const float*)d_in[7];
    const float* bb  = (const float*)d_in[8];
    const float* g1  = (const float*)d_in[9];
    const float* be1 = (const float*)d_in[10];
    const float* g2  = (const float*)d_in[11];
    const float* be2 = (const float*)d_in[12];
    const float* g3  = (const float*)d_in[13];
    const float* be3 = (const float*)d_in[14];
    const float* g4  = (const float*)d_in[15];
    const float* be4 = (const float*)d_in[16];

    float* out  = (float*)d_out;
    float* bond = out + (size_t)NN * 64;

    cudaFuncSetAttribute(k1_nodegemm, cudaFuncAttributeMaxDynamicSharedMemorySize, K1_SMEM);
    cudaFuncSetAttribute(k2_stats,    cudaFuncAttributeMaxDynamicSharedMemorySize, K2_SMEM);
    cudaFuncSetAttribute(k4_fused,    cudaFuncAttributeMaxDynamicSharedMemorySize, K4_SMEM);

    k1_nodegemm<<<K1G, dim3(96,2,1), K1_SMEM>>>(x, (const int*)ei, Wc, bc, Wf, bf, Wb, bb);
    k2_stats<<<K2G, 256, K2_SMEM>>>(ea, ei, Wc, Wf, Wb);
    k3_reduce<<<CD, 256>>>(g1, be1, g2, be2, g3, be3);
    k4_fused<<<K4G, 256, K4_SMEM>>>(ea, ei, Wc, Wf, Wb, bond);
    k5_reduce<<<KD, 256>>>(g4, be4);
    k6_out<<<(NN*64 + 255)/256, 256>>>(x, out);
}

// round 12
// speedup vs baseline: 1.3049x; 1.0015x over previous
#include <cuda_runtime.h>
#include <cuda_fp16.h>
#include <math.h>

#define NN 100000
#define NNBR 12
#define NE (NN*NNBR)
#define CD 192
#define KD 64
#define NBINS 1024
#define NB4 256
#define BN_EPS 1e-5f

#define K1G 296
#define K2G 296
#define K4G 296
#define NST 12500   // NE/96 supertiles (8 nodes each)

// ---------------- scratch (static __device__, no allocs) ----------------
// PD/PS stored in PERMUTED column order: P<128: even=core j (j=P/2),
// odd=filter j; P>=128: bond j=P-128.
__device__ __half g_PDh[(size_t)NN*CD];
__device__ __half g_PSh[(size_t)NN*CD];
__device__ float  g_binS[(size_t)CD*NBINS];  // [P][bin]
__device__ float  g_binQ[(size_t)CD*NBINS];
__device__ float  g_scale[CD];               // permuted order
__device__ float  g_shift[CD];
__device__ float  g_nbr[NN*KD];
__device__ float  g_b4S[KD*NB4];
__device__ float  g_b4Q[KD*NB4];
__device__ float  g_scale4[KD];
__device__ float  g_shift4[KD];
__device__ int    g_is64;

__device__ __forceinline__ void ffma2(float2 &d, float2 a, float2 b) {
    asm("fma.rn.f32x2 %0, %1, %2, %0;"
        : "+l"(reinterpret_cast<unsigned long long&>(d))
        : "l"(reinterpret_cast<unsigned long long&>(a)),
          "l"(reinterpret_cast<unsigned long long&>(b)));
}

__device__ __forceinline__ void mma16816(float* c, const unsigned* a, const unsigned* b) {
    asm volatile(
        "mma.sync.aligned.m16n8k16.row.col.f32.f16.f16.f32 "
        "{%0,%1,%2,%3}, {%4,%5,%6,%7}, {%8,%9}, {%0,%1,%2,%3};"
        : "+f"(c[0]), "+f"(c[1]), "+f"(c[2]), "+f"(c[3])
        : "r"(a[0]), "r"(a[1]), "r"(a[2]), "r"(a[3]), "r"(b[0]), "r"(b[1]));
}

__device__ __forceinline__ void ldsm_x4(unsigned* a, unsigned saddr) {
    asm volatile("ldmatrix.sync.aligned.m8n8.x4.shared.b16 {%0,%1,%2,%3}, [%4];"
        : "=r"(a[0]), "=r"(a[1]), "=r"(a[2]), "=r"(a[3]) : "r"(saddr));
}

__device__ __forceinline__ unsigned smem_u32(const void* p) {
    return (unsigned)__cvta_generic_to_shared(p);
}
__device__ __forceinline__ void cpa16(unsigned s, const void* g) {
    asm volatile("cp.async.cg.shared.global [%0], [%1], 16;" :: "r"(s), "l"(g));
}
__device__ __forceinline__ void cpa_commit() {
    asm volatile("cp.async.commit_group;");
}
__device__ __forceinline__ void cpa_wait1() {
    asm volatile("cp.async.wait_group 1;");
}

__device__ __forceinline__ float softplus_f(float x) {
    return fmaxf(x, 0.f) + __logf(1.f + __expf(-fabsf(x)));
}
__device__ __forceinline__ float sigmoid_f(float x) {
    return __fdividef(1.f, 1.f + __expf(-x));
}

__device__ __forceinline__ int permP(int j) {
    if (j < 64)  return 2*j;
    if (j < 128) return 2*(j-64) + 1;
    return j;
}

// ---------------- K1: zero stats + detect dtype + node pre-GEMM -----------
#define K1_SMEM (64*384*4 + 2*64*8*4)
__global__ void k1_nodegemm(const float* __restrict__ x,
                            const int*   __restrict__ eidx32,
                            const float* __restrict__ Wc, const float* __restrict__ bc,
                            const float* __restrict__ Wf, const float* __restrict__ bf,
                            const float* __restrict__ Wb, const float* __restrict__ bb)
{
    extern __shared__ float sm[];
    float* sW = sm;             // [64][384]
    float* sX = sm + 64*384;    // [2][64][8]
    int tx = threadIdx.x, ty = threadIdx.y;
    int tid = ty*96 + tx;
    int gtid = blockIdx.x*192 + tid;

    for (int i = gtid; i < CD*NBINS; i += K1G*192) { g_binS[i] = 0.f; g_binQ[i] = 0.f; }
    for (int i = gtid; i < KD*NB4;   i += K1G*192) { g_b4S[i]  = 0.f; g_b4Q[i]  = 0.f; }
    if (gtid == 0) g_is64 = (eidx32[25] == 0) ? 1 : 0;

    for (int idx = tid; idx < 64*384; idx += 192) {
        int k  = idx / 384;
        int j3 = idx - k*384;
        int j  = (j3 >= 192) ? j3 - 192 : j3;
        int kk = (j3 >= 192) ? 64 + k : k;
        const float* W; int r;
        if (j < 64)       { W = Wc; r = j; }
        else if (j < 128) { W = Wf; r = j - 64; }
        else              { W = Wb; r = j - 128; }
        sW[idx] = W[r*CD + kk];
    }
    int j0 = tx, j1 = tx + 96;
    int P0 = permP(j0), P1 = permP(j1);
    float bias0 = (j0 < 64) ? bc[j0] : ((j0 < 128) ? bf[j0-64] : bb[j0-128]);
    float bias1 = (j1 < 128) ? bf[j1-64] : bb[j1-128];
    float* sXt = sX + ty*512;

    for (int g = blockIdx.x; g < NN/16; g += gridDim.x) {
        int n0 = (g*2 + ty) * 8;
        __syncthreads();
        const float4* x4 = (const float4*)(x + (size_t)n0*64);
        for (int i = tx; i < 128; i += 96) {
            float4 v = x4[i];
            int nl = i >> 4, k4 = (i & 15) * 4;
            sXt[(k4+0)*8 + nl] = v.x;
            sXt[(k4+1)*8 + nl] = v.y;
            sXt[(k4+2)*8 + nl] = v.z;
            sXt[(k4+3)*8 + nl] = v.w;
        }
        __syncthreads();

        float2 ad0[4], ad1[4], as0[4], as1[4];
        #pragma unroll
        for (int p = 0; p < 4; p++) {
            ad0[p] = make_float2(0.f,0.f); ad1[p] = make_float2(0.f,0.f);
            as0[p] = make_float2(0.f,0.f); as1[p] = make_float2(0.f,0.f);
        }
        #pragma unroll 8
        for (int k = 0; k < 64; k++) {
            float wd0 = sW[k*384 + j0];
            float wd1 = sW[k*384 + j1];
            float ws0 = sW[k*384 + 192 + j0];
            float ws1 = sW[k*384 + 192 + j1];
            float2 Wd0 = make_float2(wd0, wd0), Wd1 = make_float2(wd1, wd1);
            float2 Ws0 = make_float2(ws0, ws0), Ws1 = make_float2(ws1, ws1);
            const float2* xp = (const float2*)(sXt + k*8);
            #pragma unroll
            for (int p = 0; p < 4; p++) {
                float2 xv = xp[p];
                ffma2(ad0[p], xv, Wd0);
                ffma2(ad1[p], xv, Wd1);
                ffma2(as0[p], xv, Ws0);
                ffma2(as1[p], xv, Ws1);
            }
        }
        #pragma unroll
        for (int p = 0; p < 4; p++) {
            size_t na = (size_t)(n0 + 2*p)*CD, nb = na + CD;
            g_PDh[na + P0] = __float2half_rn(ad0[p].x + bias0);
            g_PDh[nb + P0] = __float2half_rn(ad0[p].y + bias0);
            g_PDh[na + P1] = __float2half_rn(ad1[p].x + bias1);
            g_PDh[nb + P1] = __float2half_rn(ad1[p].y + bias1);
            g_PSh[na + P0] = __float2half_rn(as0[p].x);
            g_PSh[nb + P0] = __float2half_rn(as0[p].y);
            g_PSh[na + P1] = __float2half_rn(as1[p].x);
            g_PSh[nb + P1] = __float2half_rn(as1[p].y);
        }
    }
}

// ---------------- shared smem layout for k2/k4 ----------------------------
#define SW_BYTES   (192*32*4)       // 24576: permuted W_edge fp16 [P][64k]
#define EA32_STRIDE 272             // 64 floats + 16B pad
#define EA32B      (32*EA32_STRIDE) // 8704
#define A16_STRIDE 144              // 64 halves + 16B pad (LDSM conflict-free)
#define A16B       (32*A16_STRIDE)  // 4608
#define PD_STRIDE  400
#define PDB        (32*PD_STRIDE)   // 12800
#define PSB        (8*PD_STRIDE)    // 3200
#define EA_OFF(b)  (SW_BYTES + (b)*EA32B)
#define A16_OFF    (SW_BYTES + 2*EA32B)
#define PD_OFF(b)  (A16_OFF + A16B + (b)*PDB)
#define PS_OFF(b)  (A16_OFF + A16B + 2*PDB + (b)*PSB)
#define COMMON_SMEM (A16_OFF + A16B + 2*PDB + 2*PSB)   // 78592
#define GT_OFF     COMMON_SMEM
#define GT_STRIDE  68
#define K2_SMEM    COMMON_SMEM
#define K4_SMEM    (GT_OFF + 96*GT_STRIDE*4)           // 104704

// ---------------- K2s: stats-only edge GEMM (supertile-96) ----------------
__global__ void __launch_bounds__(256, 2)
k2_stats(const float* __restrict__ ea,
         const void* __restrict__ eidx_raw,
         const float* __restrict__ Wc,
         const float* __restrict__ Wf,
         const float* __restrict__ Wb)
{
    extern __shared__ char smc[];
    unsigned* sW32 = (unsigned*)smc;
    unsigned smb = smem_u32(smc);
    int tid = threadIdx.x;
    int w   = tid >> 5, lane = tid & 31;
    int gq  = lane >> 2, tl = lane & 3;
    int mb  = (w & 1) * 16;
    int nw  = (w >> 1);
    int is64 = g_is64;

    for (int i = tid; i < 192*32; i += 256) {
        int P = i >> 5, k2 = i & 31;
        const float* W; int r;
        if (P < 128) { r = P >> 1; W = (P & 1) ? Wf : Wc; }
        else         { r = P - 128; W = Wb; }
        float2 v = *(const float2*)(W + (size_t)r*CD + 128 + 2*k2);
        __half2 h = __floats2half2_rn(v.x, v.y);
        sW32[P*32 + k2] = *(unsigned*)&h;
    }
    __syncthreads();

    unsigned Bf[6][4][2];
    #pragma unroll
    for (int nt = 0; nt < 6; nt++) {
        int n = nw*48 + nt*8 + gq;
        #pragma unroll
        for (int ks = 0; ks < 4; ks++) {
            Bf[nt][ks][0] = sW32[n*32 + ks*8 + tl];
            Bf[nt][ks][1] = sW32[n*32 + ks*8 + tl + 4];
        }
    }
    __syncthreads();

    // per-lane ldmatrix base address (rows mb..mb+15 of A16 tile)
    unsigned aBase = smb + A16_OFF + (mb + (lane & 15))*A16_STRIDE + (lane >> 4)*16;

    float sS[12], sQ[12];
    #pragma unroll
    for (int i = 0; i < 12; i++) { sS[i] = 0.f; sQ[i] = 0.f; }

    auto stageEA = [&](int buf, int ebase) {
        #pragma unroll
        for (int i = 0; i < 2; i++) {
            int f = tid + i*256;
            int r = f >> 4, c = f & 15;
            cpa16(smb + EA_OFF(buf) + r*EA32_STRIDE + c*16,
                  ea + (size_t)(ebase+r)*64 + c*4);
        }
    };
    auto stagePD = [&](int buf, int ebase) {
        #pragma unroll
        for (int i = 0; i < 3; i++) {
            int f = tid + i*256;
            int r = f / 24, c = f - r*24;
            int e = ebase + r;
            int dst;
            if (is64) dst = (int)((const long long*)eidx_raw)[(size_t)NE + e];
            else      dst = ((const int*)eidx_raw)[(size_t)NE + e];
            cpa16(smb + PD_OFF(buf) + r*PD_STRIDE + c*16,
                  g_PDh + (size_t)dst*CD + c*8);
        }
    };
    auto stagePS = [&](int buf, int nodebase) {
        if (tid < 192) {
            int r = tid / 24, c = tid - r*24;
            cpa16(smb + PS_OFF(buf) + r*PD_STRIDE + c*16,
                  g_PSh + (size_t)(nodebase + r)*CD + c*8);
        }
    };

    int buf = 0, psb = 0;
    stagePD(0, blockIdx.x*96);
    stageEA(0, blockIdx.x*96);
    stagePS(0, blockIdx.x*8);
    cpa_commit();

    for (int st = blockIdx.x; st < NST; st += gridDim.x) {
        #pragma unroll 1
        for (int s = 0; s < 3; s++) {
            __syncthreads();   // readers of buf^1 (and A16) done
            int nst = (s < 2) ? st : st + (int)gridDim.x;
            int nss = (s < 2) ? s + 1 : 0;
            if (nst < NST) {
                stagePD(buf ^ 1, nst*96 + nss*32);
                stageEA(buf ^ 1, nst*96 + nss*32);
                if (s == 2) stagePS(psb ^ 1, nst*8);
            }
            cpa_commit();
            cpa_wait1();
            __syncthreads();

            // convert fp32 ea (buf) -> fp16 A-tile
            {
                const float4* src = (const float4*)(smc + EA_OFF(buf)
                                    + (tid >> 3)*EA32_STRIDE) + (tid & 7)*2;
                float4 f0 = src[0], f1 = src[1];
                __half2 h0 = __floats2half2_rn(f0.x, f0.y);
                __half2 h1 = __floats2half2_rn(f0.z, f0.w);
                __half2 h2 = __floats2half2_rn(f1.x, f1.y);
                __half2 h3 = __floats2half2_rn(f1.z, f1.w);
                uint4 u;
                u.x = *(unsigned*)&h0; u.y = *(unsigned*)&h1;
                u.z = *(unsigned*)&h2; u.w = *(unsigned*)&h3;
                *(uint4*)(smc + A16_OFF + (tid >> 3)*A16_STRIDE + (tid & 7)*16) = u;
            }
            __syncthreads();

            float C[6][4];
            #pragma unroll
            for (int nt = 0; nt < 6; nt++)
                #pragma unroll
                for (int q = 0; q < 4; q++) C[nt][q] = 0.f;

            #pragma unroll
            for (int ks = 0; ks < 4; ks++) {
                unsigned A[4];
                ldsm_x4(A, aBase + ks*32);
                #pragma unroll
                for (int nt = 0; nt < 6; nt++)
                    mma16816(C[nt], A, Bf[nt][ks]);
            }

            const __half* pd = (const __half*)(smc + PD_OFF(buf));
            const __half* ps = (const __half*)(smc + PS_OFF(psb));
            int r0 = mb + gq, r1 = r0 + 8;
            int ln0 = (s*32 + r0) / 12, ln1 = (s*32 + r1) / 12;
            #pragma unroll
            for (int nt = 0; nt < 6; nt++) {
                int P0 = nw*48 + nt*8 + 2*tl;
                float2 pd0 = __half22float2(*(const __half2*)(pd + r0*200 + P0));
                float2 pd1 = __half22float2(*(const __half2*)(pd + r1*200 + P0));
                float2 ps0 = __half22float2(*(const __half2*)(ps + ln0*200 + P0));
                float2 ps1 = __half22float2(*(const __half2*)(ps + ln1*200 + P0));
                float u0x = C[nt][0] + pd0.x + ps0.x, u0y = C[nt][1] + pd0.y + ps0.y;
                float u1x = C[nt][2] + pd1.x + ps1.x, u1y = C[nt][3] + pd1.y + ps1.y;
                sS[nt*2]   += u0x + u1x;
                sQ[nt*2]   += u0x*u0x + u1x*u1x;
                sS[nt*2+1] += u0y + u1y;
                sQ[nt*2+1] += u0y*u0y + u1y*u1y;
            }
            buf ^= 1;
        }
        psb ^= 1;
    }

    #pragma unroll
    for (int i = 0; i < 12; i++) {
        sS[i] += __shfl_xor_sync(0xffffffff, sS[i], 4);
        sS[i] += __shfl_xor_sync(0xffffffff, sS[i], 8);
        sS[i] += __shfl_xor_sync(0xffffffff, sS[i], 16);
        sQ[i] += __shfl_xor_sync(0xffffffff, sQ[i], 4);
        sQ[i] += __shfl_xor_sync(0xffffffff, sQ[i], 8);
        sQ[i] += __shfl_xor_sync(0xffffffff, sQ[i], 16);
    }
    if (lane < 4) {
        int bin = blockIdx.x & (NBINS - 1);
        #pragma unroll
        for (int nt = 0; nt < 6; nt++) {
            int col = nw*48 + nt*8 + 2*lane;
            atomicAdd(&g_binS[(size_t)col*NBINS + bin],     sS[nt*2]);
            atomicAdd(&g_binQ[(size_t)col*NBINS + bin],     sQ[nt*2]);
            atomicAdd(&g_binS[(size_t)(col+1)*NBINS + bin], sS[nt*2+1]);
            atomicAdd(&g_binQ[(size_t)(col+1)*NBINS + bin], sQ[nt*2+1]);
        }
    }
}

// ---------------- K3: reduce bins (permuted) -> scale/shift ----------
__global__ void k3_reduce(const float* __restrict__ g1, const float* __restrict__ be1,
                          const float* __restrict__ g2, const float* __restrict__ be2,
                          const float* __restrict__ g3, const float* __restrict__ be3)
{
    __shared__ float sS[256], sQ[256];
    int P = blockIdx.x, t = threadIdx.x;
    float S = 0.f, Q = 0.f;
    for (int b = t; b < NBINS; b += 256) {
        S += g_binS[(size_t)P*NBINS + b];
        Q += g_binQ[(size_t)P*NBINS + b];
    }
    sS[t] = S; sQ[t] = Q;
    __syncthreads();
    for (int o = 128; o > 0; o >>= 1) {
        if (t < o) { sS[t] += sS[t+o]; sQ[t] += sQ[t+o]; }
        __syncthreads();
    }
    if (t == 0) {
        float mean = sS[0] / (float)NE;
        float var  = sQ[0] / (float)NE - mean*mean;
        float g, be;
        if (P < 128) {
            int jj = P >> 1;
            if ((P & 1) == 0) { g = g1[jj]; be = be1[jj]; }
            else              { g = g2[jj]; be = be2[jj]; }
        } else { g = g3[P-128]; be = be3[P-128]; }
        float sc = g * rsqrtf(var + BN_EPS);
        g_scale[P] = sc;
        g_shift[P] = be - mean * sc;
    }
}

// ---------------- K4f: fused recompute + BN + gate + bond + node-sum ------
__global__ void __launch_bounds__(256, 2)
k4_fused(const float* __restrict__ ea,
         const void* __restrict__ eidx_raw,
         const float* __restrict__ Wc,
         const float* __restrict__ Wf,
         const float* __restrict__ Wb,
         float* __restrict__ bond_out)
{
    extern __shared__ char smc[];
    unsigned* sW32 = (unsigned*)smc;
    float* gated = (float*)(smc + GT_OFF);
    unsigned smb = smem_u32(smc);
    int tid = threadIdx.x;
    int w   = tid >> 5, lane = tid & 31;
    int gq  = lane >> 2, tl = lane & 3;
    int mb  = (w & 1) * 16;
    int nw  = (w >> 1);
    int is64 = g_is64;

    for (int i = tid; i < 192*32; i += 256) {
        int P = i >> 5, k2 = i & 31;
        const float* W; int r;
        if (P < 128) { r = P >> 1; W = (P & 1) ? Wf : Wc; }
        else         { r = P - 128; W = Wb; }
        float2 v = *(const float2*)(W + (size_t)r*CD + 128 + 2*k2);
        __half2 h = __floats2half2_rn(v.x, v.y);
        sW32[P*32 + k2] = *(unsigned*)&h;
    }
    __syncthreads();

    unsigned Bf[6][4][2];
    #pragma unroll
    for (int nt = 0; nt < 6; nt++) {
        int n = nw*48 + nt*8 + gq;
        #pragma unroll
        for (int ks = 0; ks < 4; ks++) {
            Bf[nt][ks][0] = sW32[n*32 + ks*8 + tl];
            Bf[nt][ks][1] = sW32[n*32 + ks*8 + tl + 4];
        }
    }

    float2 scp[6], shp[6];
    #pragma unroll
    for (int nt = 0; nt < 6; nt++) {
        int P0 = nw*48 + nt*8 + 2*tl;
        scp[nt] = *(const float2*)(g_scale + P0);
        shp[nt] = *(const float2*)(g_shift + P0);
    }

    unsigned aBase = smb + A16_OFF + (mb + (lane & 15))*A16_STRIDE + (lane >> 4)*16;
    float stS = 0.f, stQ = 0.f;

    auto stageEA = [&](int buf, int ebase) {
        #pragma unroll
        for (int i = 0; i < 2; i++) {
            int f = tid + i*256;
            int r = f >> 4, c = f & 15;
            cpa16(smb + EA_OFF(buf) + r*EA32_STRIDE + c*16,
                  ea + (size_t)(ebase+r)*64 + c*4);
        }
    };
    auto stagePD = [&](int buf, int ebase) {
        #pragma unroll
        for (int i = 0; i < 3; i++) {
            int f = tid + i*256;
            int r = f / 24, c = f - r*24;
            int e = ebase + r;
            int dst;
            if (is64) dst = (int)((const long long*)eidx_raw)[(size_t)NE + e];
            else      dst = ((const int*)eidx_raw)[(size_t)NE + e];
            cpa16(smb + PD_OFF(buf) + r*PD_STRIDE + c*16,
                  g_PDh + (size_t)dst*CD + c*8);
        }
    };
    auto stagePS = [&](int buf, int nodebase) {
        if (tid < 192) {
            int r = tid / 24, c = tid - r*24;
            cpa16(smb + PS_OFF(buf) + r*PD_STRIDE + c*16,
                  g_PSh + (size_t)(nodebase + r)*CD + c*8);
        }
    };

    int buf = 0, psb = 0;
    stagePD(0, blockIdx.x*96);
    stageEA(0, blockIdx.x*96);
    stagePS(0, blockIdx.x*8);
    cpa_commit();

    for (int st = blockIdx.x; st < NST; st += gridDim.x) {
        #pragma unroll 1
        for (int s = 0; s < 3; s++) {
            __syncthreads();   // readers of buf^1 / A16 / (gated at s==0) done
            int nst = (s < 2) ? st : st + (int)gridDim.x;
            int nss = (s < 2) ? s + 1 : 0;
            if (nst < NST) {
                stagePD(buf ^ 1, nst*96 + nss*32);
                stageEA(buf ^ 1, nst*96 + nss*32);
                if (s == 2) stagePS(psb ^ 1, nst*8);
            }
            cpa_commit();
            cpa_wait1();
            __syncthreads();

            // convert fp32 ea (buf) -> fp16 A-tile
            {
                const float4* src = (const float4*)(smc + EA_OFF(buf)
                                    + (tid >> 3)*EA32_STRIDE) + (tid & 7)*2;
                float4 f0 = src[0], f1 = src[1];
                __half2 h0 = __floats2half2_rn(f0.x, f0.y);
                __half2 h1 = __floats2half2_rn(f0.z, f0.w);
                __half2 h2 = __floats2half2_rn(f1.x, f1.y);
                __half2 h3 = __floats2half2_rn(f1.z, f1.w);
                uint4 u;
                u.x = *(unsigned*)&h0; u.y = *(unsigned*)&h1;
                u.z = *(unsigned*)&h2; u.w = *(unsigned*)&h3;
                *(uint4*)(smc + A16_OFF + (tid >> 3)*A16_STRIDE + (tid & 7)*16) = u;
            }
            __syncthreads();

            int ebase = st*96 + s*32;
            int r0 = mb + gq, r1 = r0 + 8;
            int e0g = ebase + r0, e1g = ebase + r1;

            float C[6][4];
            #pragma unroll
            for (int nt = 0; nt < 6; nt++)
                #pragma unroll
                for (int q = 0; q < 4; q++) C[nt][q] = 0.f;

            #pragma unroll
            for (int ks = 0; ks < 4; ks++) {
                unsigned A[4];
                ldsm_x4(A, aBase + ks*32);
                #pragma unroll
                for (int nt = 0; nt < 6; nt++)
                    mma16816(C[nt], A, Bf[nt][ks]);
            }

            const __half* pd = (const __half*)(smc + PD_OFF(buf));
            const __half* ps = (const __half*)(smc + PS_OFF(psb));
            const float* eaS = (const float*)(smc + EA_OFF(buf));
            int ln0 = (s*32 + r0) / 12, ln1 = (s*32 + r1) / 12;
            int row0 = s*32 + r0, row1 = s*32 + r1;

            #pragma unroll
            for (int nt = 0; nt < 6; nt++) {
                int P0 = nw*48 + nt*8 + 2*tl;
                float2 pd0 = __half22float2(*(const __half2*)(pd + r0*200 + P0));
                float2 pd1 = __half22float2(*(const __half2*)(pd + r1*200 + P0));
                float2 ps0 = __half22float2(*(const __half2*)(ps + ln0*200 + P0));
                float2 ps1 = __half22float2(*(const __half2*)(ps + ln1*200 + P0));
                float v00 = fmaf(C[nt][0] + pd0.x + ps0.x, scp[nt].x, shp[nt].x);
                float v01 = fmaf(C[nt][1] + pd0.y + ps0.y, scp[nt].y, shp[nt].y);
                float v10 = fmaf(C[nt][2] + pd1.x + ps1.x, scp[nt].x, shp[nt].x);
                float v11 = fmaf(C[nt][3] + pd1.y + ps1.y, scp[nt].y, shp[nt].y);
                if (P0 < 128) {
                    int j = P0 >> 1;   // even=core(sigmoid), odd=filter(softplus)
                    gated[row0*GT_STRIDE + j] = sigmoid_f(v00) * softplus_f(v01);
                    gated[row1*GT_STRIDE + j] = sigmoid_f(v10) * softplus_f(v11);
                } else {
                    int jb = P0 - 128;
                    float2 ev0 = *(const float2*)(eaS + r0*68 + jb);
                    float2 ev1 = *(const float2*)(eaS + r1*68 + jb);
                    float2 bo0, bo1;
                    bo0.x = softplus_f(ev0.x + v00);
                    bo0.y = softplus_f(ev0.y + v01);
                    bo1.x = softplus_f(ev1.x + v10);
                    bo1.y = softplus_f(ev1.y + v11);
                    *(float2*)(bond_out + (size_t)e0g*64 + jb) = bo0;
                    *(float2*)(bond_out + (size_t)e1g*64 + jb) = bo1;
                }
            }
            buf ^= 1;
        }
        __syncthreads();   // gated complete

        {
            int j = tid & 63;
            #pragma unroll
            for (int h = 0; h < 2; h++) {
                int d = (tid >> 6) + 4*h;
                float acc = 0.f;
                #pragma unroll
                for (int k = 0; k < 12; k++)
                    acc += gated[(d*12 + k)*GT_STRIDE + j];
                g_nbr[(size_t)(st*8 + d)*64 + j] = acc;
                stS += acc; stQ += acc*acc;
            }
        }
        psb ^= 1;
    }

    {
        int j = tid & 63;
        int bin = blockIdx.x & (NB4 - 1);
        atomicAdd(&g_b4S[j*NB4 + bin], stS);
        atomicAdd(&g_b4Q[j*NB4 + bin], stQ);
    }
}

// ---------------- K5: parallel reduce node-BN ----------------
__global__ void k5_reduce(const float* __restrict__ g4, const float* __restrict__ be4)
{
    __shared__ float sS[256], sQ[256];
    int j = blockIdx.x, t = threadIdx.x;
    float S = (t < NB4) ? g_b4S[j*NB4 + t] : 0.f;
    float Q = (t < NB4) ? g_b4Q[j*NB4 + t] : 0.f;
    sS[t] = S; sQ[t] = Q;
    __syncthreads();
    for (int o = 128; o > 0; o >>= 1) {
        if (t < o) { sS[t] += sS[t+o]; sQ[t] += sQ[t+o]; }
        __syncthreads();
    }
    if (t == 0) {
        float mean = sS[0] / (float)NN;
        float var  = sQ[0] / (float)NN - mean*mean;
        float sc = g4[j] * rsqrtf(var + BN_EPS);
        g_scale4[j] = sc;
        g_shift4[j] = be4[j] - mean * sc;
    }
}

// ---------------- K6: out = softplus(x + bn4(nbr_sum)) ----------------
__global__ void k6_out(const float* __restrict__ x, float* __restrict__ out)
{
    int i = blockIdx.x * 256 + threadIdx.x;
    if (i < NN*64) {
        int j = i & 63;
        float v = x[i] + fmaf(g_nbr[i], g_scale4[j], g_shift4[j]);
        out[i] = softplus_f(v);
    }
}

extern "C" void kernel_launch(void* const* d_in, const int* in_sizes, int n_in,
                              void* d_out, int out_size)
{
    const float* x   = (const float*)d_in[0];
    const void*  ei  = (const void*)d_in[1];
    const float* ea  = (const float*)d_in[2];
    const float* Wc  = (const float*)d_in[3];
    const float* bc  = (const float*)d_in[4];
    const float* Wf  = (const float*)d_in[5];
    const float* bf  = (const float*)d_in[6];
    const float* Wb  = (const float*)d_in[7];
    const float* bb  = (const float*)d_in[8];
    const float* g1  = (const float*)d_in[9];
    const float* be1 = (const float*)d_in[10];
    const float* g2  = (const float*)d_in[11];
    const float* be2 = (const float*)d_in[12];
    const float* g3  = (const float*)d_in[13];
    const float* be3 = (const float*)d_in[14];
    const float* g4  = (const float*)d_in[15];
    const float* be4 = (const float*)d_in[16];

    float* out  = (float*)d_out;
    float* bond = out + (size_t)NN * 64;

    cudaFuncSetAttribute(k1_nodegemm, cudaFuncAttributeMaxDynamicSharedMemorySize, K1_SMEM);
    cudaFuncSetAttribute(k2_stats,    cudaFuncAttributeMaxDynamicSharedMemorySize, K2_SMEM);
    cudaFuncSetAttribute(k4_fused,    cudaFuncAttributeMaxDynamicSharedMemorySize, K4_SMEM);

    k1_nodegemm<<<K1G, dim3(96,2,1), K1_SMEM>>>(x, (const int*)ei, Wc, bc, Wf, bf, Wb, bb);
    k2_stats<<<K2G, 256, K2_SMEM>>>(ea, ei, Wc, Wf, Wb);
    k3_reduce<<<CD, 256>>>(g1, be1, g2, be2, g3, be3);
    k4_fused<<<K4G, 256, K4_SMEM>>>(ea, ei, Wc, Wf, Wb, bond);
    k5_reduce<<<KD, 256>>>(g4, be4);
    k6_out<<<(NN*64 + 255)/256, 256>>>(x, out);
}

// round 13
// speedup vs baseline: 1.3068x; 1.0015x over previous
#include <cuda_runtime.h>
#include <cuda_fp16.h>
#include <math.h>

#define NN 100000
#define NNBR 12
#define NE (NN*NNBR)
#define CD 192
#define KD 64
#define NBINS 1024
#define NB4 256
#define BN_EPS 1e-5f

#define K1G 296
#define K2G 296
#define K4G 296
#define NST 12500   // NE/96 supertiles (8 nodes each)

// ---------------- scratch (static __device__, no allocs) ----------------
// PD/PS stored in PERMUTED column order: P<128: even=core j (j=P/2),
// odd=filter j; P>=128: bond j=P-128.
__device__ __half g_PDh[(size_t)NN*CD];
__device__ __half g_PSh[(size_t)NN*CD];
__device__ __half g_EAh[(size_t)NE*KD];      // fp16 copy of edge_attr (153.6MB)
__device__ float  g_binS[(size_t)CD*NBINS];  // [P][bin]
__device__ float  g_binQ[(size_t)CD*NBINS];
__device__ float  g_scale[CD];               // permuted order
__device__ float  g_shift[CD];
__device__ float  g_nbr[NN*KD];
__device__ float  g_b4S[KD*NB4];
__device__ float  g_b4Q[KD*NB4];
__device__ float  g_scale4[KD];
__device__ float  g_shift4[KD];
__device__ int    g_is64;

__device__ __forceinline__ void ffma2(float2 &d, float2 a, float2 b) {
    asm("fma.rn.f32x2 %0, %1, %2, %0;"
        : "+l"(reinterpret_cast<unsigned long long&>(d))
        : "l"(reinterpret_cast<unsigned long long&>(a)),
          "l"(reinterpret_cast<unsigned long long&>(b)));
}

__device__ __forceinline__ void mma16816(float* c, const unsigned* a, const unsigned* b) {
    asm volatile(
        "mma.sync.aligned.m16n8k16.row.col.f32.f16.f16.f32 "
        "{%0,%1,%2,%3}, {%4,%5,%6,%7}, {%8,%9}, {%0,%1,%2,%3};"
        : "+f"(c[0]), "+f"(c[1]), "+f"(c[2]), "+f"(c[3])
        : "r"(a[0]), "r"(a[1]), "r"(a[2]), "r"(a[3]), "r"(b[0]), "r"(b[1]));
}

__device__ __forceinline__ void ldsm_x4(unsigned* a, unsigned saddr) {
    asm volatile("ldmatrix.sync.aligned.m8n8.x4.shared.b16 {%0,%1,%2,%3}, [%4];"
        : "=r"(a[0]), "=r"(a[1]), "=r"(a[2]), "=r"(a[3]) : "r"(saddr));
}

__device__ __forceinline__ unsigned smem_u32(const void* p) {
    return (unsigned)__cvta_generic_to_shared(p);
}
__device__ __forceinline__ void cpa16(unsigned s, const void* g) {
    asm volatile("cp.async.cg.shared.global [%0], [%1], 16;" :: "r"(s), "l"(g));
}
__device__ __forceinline__ void cpa_commit() {
    asm volatile("cp.async.commit_group;");
}
__device__ __forceinline__ void cpa_wait1() {
    asm volatile("cp.async.wait_group 1;");
}

__device__ __forceinline__ float softplus_f(float x) {
    return fmaxf(x, 0.f) + __logf(1.f + __expf(-fabsf(x)));
}
__device__ __forceinline__ float sigmoid_f(float x) {
    return __fdividef(1.f, 1.f + __expf(-x));
}

__device__ __forceinline__ int permP(int j) {
    if (j < 64)  return 2*j;
    if (j < 128) return 2*(j-64) + 1;
    return j;
}

// ---------------- K1: zero stats + dtype + ea->fp16 + node pre-GEMM -------
#define K1_SMEM (64*384*4 + 2*64*8*4)
__global__ void k1_nodegemm(const float* __restrict__ x,
                            const int*   __restrict__ eidx32,
                            const float* __restrict__ ea,
                            const float* __restrict__ Wc, const float* __restrict__ bc,
                            const float* __restrict__ Wf, const float* __restrict__ bf,
                            const float* __restrict__ Wb, const float* __restrict__ bb)
{
    extern __shared__ float sm[];
    float* sW = sm;             // [64][384]
    float* sX = sm + 64*384;    // [2][64][8]
    int tx = threadIdx.x, ty = threadIdx.y;
    int tid = ty*96 + tx;
    int gtid = blockIdx.x*192 + tid;

    for (int i = gtid; i < CD*NBINS; i += K1G*192) { g_binS[i] = 0.f; g_binQ[i] = 0.f; }
    for (int i = gtid; i < KD*NB4;   i += K1G*192) { g_b4S[i]  = 0.f; g_b4Q[i]  = 0.f; }
    if (gtid == 0) g_is64 = (eidx32[25] == 0) ? 1 : 0;

    // convert ea fp32 -> fp16 (grid-stride, 8 elems per iter)
    {
        const size_t NCH = (size_t)NE*KD/8;   // 9.6M uint4 chunks of output
        const float4* s4 = (const float4*)ea;
        uint4* d4 = (uint4*)g_EAh;
        for (size_t i = gtid; i < NCH; i += (size_t)K1G*192) {
            float4 a = s4[i*2], b = s4[i*2+1];
            __half2 h0 = __floats2half2_rn(a.x, a.y);
            __half2 h1 = __floats2half2_rn(a.z, a.w);
            __half2 h2 = __floats2half2_rn(b.x, b.y);
            __half2 h3 = __floats2half2_rn(b.z, b.w);
            uint4 u;
            u.x = *(unsigned*)&h0; u.y = *(unsigned*)&h1;
            u.z = *(unsigned*)&h2; u.w = *(unsigned*)&h3;
            d4[i] = u;
        }
    }

    for (int idx = tid; idx < 64*384; idx += 192) {
        int k  = idx / 384;
        int j3 = idx - k*384;
        int j  = (j3 >= 192) ? j3 - 192 : j3;
        int kk = (j3 >= 192) ? 64 + k : k;
        const float* W; int r;
        if (j < 64)       { W = Wc; r = j; }
        else if (j < 128) { W = Wf; r = j - 64; }
        else              { W = Wb; r = j - 128; }
        sW[idx] = W[r*CD + kk];
    }
    int j0 = tx, j1 = tx + 96;
    int P0 = permP(j0), P1 = permP(j1);
    float bias0 = (j0 < 64) ? bc[j0] : ((j0 < 128) ? bf[j0-64] : bb[j0-128]);
    float bias1 = (j1 < 128) ? bf[j1-64] : bb[j1-128];
    float* sXt = sX + ty*512;

    for (int g = blockIdx.x; g < NN/16; g += gridDim.x) {
        int n0 = (g*2 + ty) * 8;
        __syncthreads();
        const float4* x4 = (const float4*)(x + (size_t)n0*64);
        for (int i = tx; i < 128; i += 96) {
            float4 v = x4[i];
            int nl = i >> 4, k4 = (i & 15) * 4;
            sXt[(k4+0)*8 + nl] = v.x;
            sXt[(k4+1)*8 + nl] = v.y;
            sXt[(k4+2)*8 + nl] = v.z;
            sXt[(k4+3)*8 + nl] = v.w;
        }
        __syncthreads();

        float2 ad0[4], ad1[4], as0[4], as1[4];
        #pragma unroll
        for (int p = 0; p < 4; p++) {
            ad0[p] = make_float2(0.f,0.f); ad1[p] = make_float2(0.f,0.f);
            as0[p] = make_float2(0.f,0.f); as1[p] = make_float2(0.f,0.f);
        }
        #pragma unroll 8
        for (int k = 0; k < 64; k++) {
            float wd0 = sW[k*384 + j0];
            float wd1 = sW[k*384 + j1];
            float ws0 = sW[k*384 + 192 + j0];
            float ws1 = sW[k*384 + 192 + j1];
            float2 Wd0 = make_float2(wd0, wd0), Wd1 = make_float2(wd1, wd1);
            float2 Ws0 = make_float2(ws0, ws0), Ws1 = make_float2(ws1, ws1);
            const float2* xp = (const float2*)(sXt + k*8);
            #pragma unroll
            for (int p = 0; p < 4; p++) {
                float2 xv = xp[p];
                ffma2(ad0[p], xv, Wd0);
                ffma2(ad1[p], xv, Wd1);
                ffma2(as0[p], xv, Ws0);
                ffma2(as1[p], xv, Ws1);
            }
        }
        #pragma unroll
        for (int p = 0; p < 4; p++) {
            size_t na = (size_t)(n0 + 2*p)*CD, nb = na + CD;
            g_PDh[na + P0] = __float2half_rn(ad0[p].x + bias0);
            g_PDh[nb + P0] = __float2half_rn(ad0[p].y + bias0);
            g_PDh[na + P1] = __float2half_rn(ad1[p].x + bias1);
            g_PDh[nb + P1] = __float2half_rn(ad1[p].y + bias1);
            g_PSh[na + P0] = __float2half_rn(as0[p].x);
            g_PSh[nb + P0] = __float2half_rn(as0[p].y);
            g_PSh[na + P1] = __float2half_rn(as1[p].x);
            g_PSh[nb + P1] = __float2half_rn(as1[p].y);
        }
    }
}

// ---------------- shared smem layout for k2/k4 ----------------------------
#define SW_BYTES   (192*32*4)       // 24576: permuted W_edge fp16 [P][64k]
#define A16_STRIDE 144              // 64 halves + 16B pad (LDSM conflict-free)
#define A16B       (32*A16_STRIDE)  // 4608
#define PD_STRIDE  400
#define PDB        (32*PD_STRIDE)   // 12800
#define PSB        (8*PD_STRIDE)    // 3200
#define A16_OFF(b) (SW_BYTES + (b)*A16B)
#define PD_OFF(b)  (SW_BYTES + 2*A16B + (b)*PDB)
#define PS_OFF(b)  (SW_BYTES + 2*A16B + 2*PDB + (b)*PSB)
#define COMMON_SMEM (SW_BYTES + 2*A16B + 2*PDB + 2*PSB)   // 65792
#define GT_OFF     COMMON_SMEM
#define GT_STRIDE  68
#define K2_SMEM    COMMON_SMEM
#define K4_SMEM    (GT_OFF + 96*GT_STRIDE*4)              // 91904

// ---------------- K2s: stats-only edge GEMM (supertile-96) ----------------
__global__ void __launch_bounds__(256, 2)
k2_stats(const void* __restrict__ eidx_raw,
         const float* __restrict__ Wc,
         const float* __restrict__ Wf,
         const float* __restrict__ Wb)
{
    extern __shared__ char smc[];
    unsigned* sW32 = (unsigned*)smc;
    unsigned smb = smem_u32(smc);
    int tid = threadIdx.x;
    int w   = tid >> 5, lane = tid & 31;
    int gq  = lane >> 2, tl = lane & 3;
    int mb  = (w & 1) * 16;
    int nw  = (w >> 1);
    int is64 = g_is64;

    for (int i = tid; i < 192*32; i += 256) {
        int P = i >> 5, k2 = i & 31;
        const float* W; int r;
        if (P < 128) { r = P >> 1; W = (P & 1) ? Wf : Wc; }
        else         { r = P - 128; W = Wb; }
        float2 v = *(const float2*)(W + (size_t)r*CD + 128 + 2*k2);
        __half2 h = __floats2half2_rn(v.x, v.y);
        sW32[P*32 + k2] = *(unsigned*)&h;
    }
    __syncthreads();

    unsigned Bf[6][4][2];
    #pragma unroll
    for (int nt = 0; nt < 6; nt++) {
        int n = nw*48 + nt*8 + gq;
        #pragma unroll
        for (int ks = 0; ks < 4; ks++) {
            Bf[nt][ks][0] = sW32[n*32 + ks*8 + tl];
            Bf[nt][ks][1] = sW32[n*32 + ks*8 + tl + 4];
        }
    }
    __syncthreads();

    unsigned aBase = smb + (mb + (lane & 15))*A16_STRIDE + (lane >> 4)*16;

    float sS[12], sQ[12];
    #pragma unroll
    for (int i = 0; i < 12; i++) { sS[i] = 0.f; sQ[i] = 0.f; }

    auto stageA = [&](int buf, int ebase) {
        int r = tid >> 3, c = tid & 7;     // 32 rows x 8 x 16B
        cpa16(smb + A16_OFF(buf) + r*A16_STRIDE + c*16,
              g_EAh + (size_t)(ebase+r)*64 + c*8);
    };
    auto stagePD = [&](int buf, int ebase) {
        #pragma unroll
        for (int i = 0; i < 3; i++) {
            int f = tid + i*256;
            int r = f / 24, c = f - r*24;
            int e = ebase + r;
            int dst;
            if (is64) dst = (int)((const long long*)eidx_raw)[(size_t)NE + e];
            else      dst = ((const int*)eidx_raw)[(size_t)NE + e];
            cpa16(smb + PD_OFF(buf) + r*PD_STRIDE + c*16,
                  g_PDh + (size_t)dst*CD + c*8);
        }
    };
    auto stagePS = [&](int buf, int nodebase) {
        if (tid < 192) {
            int r = tid / 24, c = tid - r*24;
            cpa16(smb + PS_OFF(buf) + r*PD_STRIDE + c*16,
                  g_PSh + (size_t)(nodebase + r)*CD + c*8);
        }
    };

    int buf = 0, psb = 0;
    stagePD(0, blockIdx.x*96);
    stageA(0, blockIdx.x*96);
    stagePS(0, blockIdx.x*8);
    cpa_commit();

    for (int st = blockIdx.x; st < NST; st += gridDim.x) {
        #pragma unroll 1
        for (int s = 0; s < 3; s++) {
            __syncthreads();   // readers of buf^1 done
            int nst = (s < 2) ? st : st + (int)gridDim.x;
            int nss = (s < 2) ? s + 1 : 0;
            if (nst < NST) {
                stagePD(buf ^ 1, nst*96 + nss*32);
                stageA(buf ^ 1, nst*96 + nss*32);
                if (s == 2) stagePS(psb ^ 1, nst*8);
            }
            cpa_commit();
            cpa_wait1();
            __syncthreads();

            float C[6][4];
            #pragma unroll
            for (int nt = 0; nt < 6; nt++)
                #pragma unroll
                for (int q = 0; q < 4; q++) C[nt][q] = 0.f;

            #pragma unroll
            for (int ks = 0; ks < 4; ks++) {
                unsigned A[4];
                ldsm_x4(A, aBase + A16_OFF(buf) - SW_BYTES + SW_BYTES + ks*32);
                #pragma unroll
                for (int nt = 0; nt < 6; nt++)
                    mma16816(C[nt], A, Bf[nt][ks]);
            }

            const __half* pd = (const __half*)(smc + PD_OFF(buf));
            const __half* ps = (const __half*)(smc + PS_OFF(psb));
            int r0 = mb + gq, r1 = r0 + 8;
            int ln0 = (s*32 + r0) / 12, ln1 = (s*32 + r1) / 12;
            #pragma unroll
            for (int nt = 0; nt < 6; nt++) {
                int P0 = nw*48 + nt*8 + 2*tl;
                __half2 p0 = __hadd2(*(const __half2*)(pd + r0*200 + P0),
                                     *(const __half2*)(ps + ln0*200 + P0));
                __half2 p1 = __hadd2(*(const __half2*)(pd + r1*200 + P0),
                                     *(const __half2*)(ps + ln1*200 + P0));
                float2 pf0 = __half22float2(p0);
                float2 pf1 = __half22float2(p1);
                float u0x = C[nt][0] + pf0.x, u0y = C[nt][1] + pf0.y;
                float u1x = C[nt][2] + pf1.x, u1y = C[nt][3] + pf1.y;
                sS[nt*2]   += u0x + u1x;
                sQ[nt*2]   += u0x*u0x + u1x*u1x;
                sS[nt*2+1] += u0y + u1y;
                sQ[nt*2+1] += u0y*u0y + u1y*u1y;
            }
            buf ^= 1;
        }
        psb ^= 1;
    }

    #pragma unroll
    for (int i = 0; i < 12; i++) {
        sS[i] += __shfl_xor_sync(0xffffffff, sS[i], 4);
        sS[i] += __shfl_xor_sync(0xffffffff, sS[i], 8);
        sS[i] += __shfl_xor_sync(0xffffffff, sS[i], 16);
        sQ[i] += __shfl_xor_sync(0xffffffff, sQ[i], 4);
        sQ[i] += __shfl_xor_sync(0xffffffff, sQ[i], 8);
        sQ[i] += __shfl_xor_sync(0xffffffff, sQ[i], 16);
    }
    if (lane < 4) {
        int bin = blockIdx.x & (NBINS - 1);
        #pragma unroll
        for (int nt = 0; nt < 6; nt++) {
            int col = nw*48 + nt*8 + 2*lane;
            atomicAdd(&g_binS[(size_t)col*NBINS + bin],     sS[nt*2]);
            atomicAdd(&g_binQ[(size_t)col*NBINS + bin],     sQ[nt*2]);
            atomicAdd(&g_binS[(size_t)(col+1)*NBINS + bin], sS[nt*2+1]);
            atomicAdd(&g_binQ[(size_t)(col+1)*NBINS + bin], sQ[nt*2+1]);
        }
    }
}

// ---------------- K3: reduce bins (permuted) -> scale/shift ----------
__global__ void k3_reduce(const float* __restrict__ g1, const float* __restrict__ be1,
                          const float* __restrict__ g2, const float* __restrict__ be2,
                          const float* __restrict__ g3, const float* __restrict__ be3)
{
    __shared__ float sS[256], sQ[256];
    int P = blockIdx.x, t = threadIdx.x;
    float S = 0.f, Q = 0.f;
    for (int b = t; b < NBINS; b += 256) {
        S += g_binS[(size_t)P*NBINS + b];
        Q += g_binQ[(size_t)P*NBINS + b];
    }
    sS[t] = S; sQ[t] = Q;
    __syncthreads();
    for (int o = 128; o > 0; o >>= 1) {
        if (t < o) { sS[t] += sS[t+o]; sQ[t] += sQ[t+o]; }
        __syncthreads();
    }
    if (t == 0) {
        float mean = sS[0] / (float)NE;
        float var  = sQ[0] / (float)NE - mean*mean;
        float g, be;
        if (P < 128) {
            int jj = P >> 1;
            if ((P & 1) == 0) { g = g1[jj]; be = be1[jj]; }
            else              { g = g2[jj]; be = be2[jj]; }
        } else { g = g3[P-128]; be = be3[P-128]; }
        float sc = g * rsqrtf(var + BN_EPS);
        g_scale[P] = sc;
        g_shift[P] = be - mean * sc;
    }
}

// ---------------- K4f: fused recompute + BN + gate + bond + node-sum ------
__global__ void __launch_bounds__(256, 2)
k4_fused(const void* __restrict__ eidx_raw,
         const float* __restrict__ Wc,
         const float* __restrict__ Wf,
         const float* __restrict__ Wb,
         float* __restrict__ bond_out)
{
    extern __shared__ char smc[];
    unsigned* sW32 = (unsigned*)smc;
    float* gated = (float*)(smc + GT_OFF);
    unsigned smb = smem_u32(smc);
    int tid = threadIdx.x;
    int w   = tid >> 5, lane = tid & 31;
    int gq  = lane >> 2, tl = lane & 3;
    int mb  = (w & 1) * 16;
    int nw  = (w >> 1);
    int is64 = g_is64;

    for (int i = tid; i < 192*32; i += 256) {
        int P = i >> 5, k2 = i & 31;
        const float* W; int r;
        if (P < 128) { r = P >> 1; W = (P & 1) ? Wf : Wc; }
        else         { r = P - 128; W = Wb; }
        float2 v = *(const float2*)(W + (size_t)r*CD + 128 + 2*k2);
        __half2 h = __floats2half2_rn(v.x, v.y);
        sW32[P*32 + k2] = *(unsigned*)&h;
    }
    __syncthreads();

    unsigned Bf[6][4][2];
    #pragma unroll
    for (int nt = 0; nt < 6; nt++) {
        int n = nw*48 + nt*8 + gq;
        #pragma unroll
        for (int ks = 0; ks < 4; ks++) {
            Bf[nt][ks][0] = sW32[n*32 + ks*8 + tl];
            Bf[nt][ks][1] = sW32[n*32 + ks*8 + tl + 4];
        }
    }

    float2 scp[6], shp[6];
    #pragma unroll
    for (int nt = 0; nt < 6; nt++) {
        int P0 = nw*48 + nt*8 + 2*tl;
        scp[nt] = *(const float2*)(g_scale + P0);
        shp[nt] = *(const float2*)(g_shift + P0);
    }

    unsigned aBase = smb + (mb + (lane & 15))*A16_STRIDE + (lane >> 4)*16;
    float stS = 0.f, stQ = 0.f;

    auto stageA = [&](int buf, int ebase) {
        int r = tid >> 3, c = tid & 7;
        cpa16(smb + A16_OFF(buf) + r*A16_STRIDE + c*16,
              g_EAh + (size_t)(ebase+r)*64 + c*8);
    };
    auto stagePD = [&](int buf, int ebase) {
        #pragma unroll
        for (int i = 0; i < 3; i++) {
            int f = tid + i*256;
            int r = f / 24, c = f - r*24;
            int e = ebase + r;
            int dst;
            if (is64) dst = (int)((const long long*)eidx_raw)[(size_t)NE + e];
            else      dst = ((const int*)eidx_raw)[(size_t)NE + e];
            cpa16(smb + PD_OFF(buf) + r*PD_STRIDE + c*16,
                  g_PDh + (size_t)dst*CD + c*8);
        }
    };
    auto stagePS = [&](int buf, int nodebase) {
        if (tid < 192) {
            int r = tid / 24, c = tid - r*24;
            cpa16(smb + PS_OFF(buf) + r*PD_STRIDE + c*16,
                  g_PSh + (size_t)(nodebase + r)*CD + c*8);
        }
    };

    int buf = 0, psb = 0;
    stagePD(0, blockIdx.x*96);
    stageA(0, blockIdx.x*96);
    stagePS(0, blockIdx.x*8);
    cpa_commit();

    for (int st = blockIdx.x; st < NST; st += gridDim.x) {
        #pragma unroll 1
        for (int s = 0; s < 3; s++) {
            __syncthreads();   // readers of buf^1 / (gated at s==0) done
            int nst = (s < 2) ? st : st + (int)gridDim.x;
            int nss = (s < 2) ? s + 1 : 0;
            if (nst < NST) {
                stagePD(buf ^ 1, nst*96 + nss*32);
                stageA(buf ^ 1, nst*96 + nss*32);
                if (s == 2) stagePS(psb ^ 1, nst*8);
            }
            cpa_commit();
            cpa_wait1();
            __syncthreads();

            int ebase = st*96 + s*32;
            int r0 = mb + gq, r1 = r0 + 8;
            int e0g = ebase + r0, e1g = ebase + r1;

            float C[6][4];
            #pragma unroll
            for (int nt = 0; nt < 6; nt++)
                #pragma unroll
                for (int q = 0; q < 4; q++) C[nt][q] = 0.f;

            #pragma unroll
            for (int ks = 0; ks < 4; ks++) {
                unsigned A[4];
                ldsm_x4(A, aBase + A16_OFF(buf) - SW_BYTES + SW_BYTES + ks*32);
                #pragma unroll
                for (int nt = 0; nt < 6; nt++)
                    mma16816(C[nt], A, Bf[nt][ks]);
            }

            const __half* pd = (const __half*)(smc + PD_OFF(buf));
            const __half* ps = (const __half*)(smc + PS_OFF(psb));
            const __half* aS = (const __half*)(smc + A16_OFF(buf));
            int ln0 = (s*32 + r0) / 12, ln1 = (s*32 + r1) / 12;
            int row0 = s*32 + r0, row1 = s*32 + r1;

            #pragma unroll
            for (int nt = 0; nt < 6; nt++) {
                int P0 = nw*48 + nt*8 + 2*tl;
                __half2 p0 = __hadd2(*(const __half2*)(pd + r0*200 + P0),
                                     *(const __half2*)(ps + ln0*200 + P0));
                __half2 p1 = __hadd2(*(const __half2*)(pd + r1*200 + P0),
                                     *(const __half2*)(ps + ln1*200 + P0));
                float2 pf0 = __half22float2(p0);
                float2 pf1 = __half22float2(p1);
                float v00 = fmaf(C[nt][0] + pf0.x, scp[nt].x, shp[nt].x);
                float v01 = fmaf(C[nt][1] + pf0.y, scp[nt].y, shp[nt].y);
                float v10 = fmaf(C[nt][2] + pf1.x, scp[nt].x, shp[nt].x);
                float v11 = fmaf(C[nt][3] + pf1.y, scp[nt].y, shp[nt].y);
                if (P0 < 128) {
                    int j = P0 >> 1;   // even=core(sigmoid), odd=filter(softplus)
                    gated[row0*GT_STRIDE + j] = sigmoid_f(v00) * softplus_f(v01);
                    gated[row1*GT_STRIDE + j] = sigmoid_f(v10) * softplus_f(v11);
                } else {
                    int jb = P0 - 128;
                    float2 ev0 = __half22float2(*(const __half2*)(aS + r0*72 + jb));
                    float2 ev1 = __half22float2(*(const __half2*)(aS + r1*72 + jb));
                    float2 bo0, bo1;
                    bo0.x = softplus_f(ev0.x + v00);
                    bo0.y = softplus_f(ev0.y + v01);
                    bo1.x = softplus_f(ev1.x + v10);
                    bo1.y = softplus_f(ev1.y + v11);
                    *(float2*)(bond_out + (size_t)e0g*64 + jb) = bo0;
                    *(float2*)(bond_out + (size_t)e1g*64 + jb) = bo1;
                }
            }
            buf ^= 1;
        }
        __syncthreads();   // gated complete

        {
            int j = tid & 63;
            #pragma unroll
            for (int h = 0; h < 2; h++) {
                int d = (tid >> 6) + 4*h;
                float acc = 0.f;
                #pragma unroll
                for (int k = 0; k < 12; k++)
                    acc += gated[(d*12 + k)*GT_STRIDE + j];
                g_nbr[(size_t)(st*8 + d)*64 + j] = acc;
                stS += acc; stQ += acc*acc;
            }
        }
        psb ^= 1;
    }

    {
        int j = tid & 63;
        int bin = blockIdx.x & (NB4 - 1);
        atomicAdd(&g_b4S[j*NB4 + bin], stS);
        atomicAdd(&g_b4Q[j*NB4 + bin], stQ);
    }
}

// ---------------- K5: parallel reduce node-BN ----------------
__global__ void k5_reduce(const float* __restrict__ g4, const float* __restrict__ be4)
{
    __shared__ float sS[256], sQ[256];
    int j = blockIdx.x, t = threadIdx.x;
    float S = (t < NB4) ? g_b4S[j*NB4 + t] : 0.f;
    float Q = (t < NB4) ? g_b4Q[j*NB4 + t] : 0.f;
    sS[t] = S; sQ[t] = Q;
    __syncthreads();
    for (int o = 128; o > 0; o >>= 1) {
        if (t < o) { sS[t] += sS[t+o]; sQ[t] += sQ[t+o]; }
        __syncthreads();
    }
    if (t == 0) {
        float mean = sS[0] / (float)NN;
        float var  = sQ[0] / (float)NN - mean*mean;
        float sc = g4[j] * rsqrtf(var + BN_EPS);
        g_scale4[j] = sc;
        g_shift4[j] = be4[j] - mean * sc;
    }
}

// ---------------- K6: out = softplus(x + bn4(nbr_sum)) ----------------
__global__ void k6_out(const float* __restrict__ x, float* __restrict__ out)
{
    int i = blockIdx.x * 256 + threadIdx.x;
    if (i < NN*64) {
        int j = i & 63;
        float v = x[i] + fmaf(g_nbr[i], g_scale4[j], g_shift4[j]);
        out[i] = softplus_f(v);
    }
}

extern "C" void kernel_launch(void* const* d_in, const int* in_sizes, int n_in,
                              void* d_out, int out_size)
{
    const float* x   = (const float*)d_in[0];
    const void*  ei  = (const void*)d_in[1];
    const float* ea  = (const float*)d_in[2];
    const float* Wc  = (const float*)d_in[3];
    const float* bc  = (const float*)d_in[4];
    const float* Wf  = (const float*)d_in[5];
    const float* bf  = (const float*)d_in[6];
    const float* Wb  = (const float*)d_in[7];
    const float* bb  = (const float*)d_in[8];
    const float* g1  = (const float*)d_in[9];
    const float* be1 = (const float*)d_in[10];
    const float* g2  = (const float*)d_in[11];
    const float* be2 = (const float*)d_in[12];
    const float* g3  = (const float*)d_in[13];
    const float* be3 = (const float*)d_in[14];
    const float* g4  = (const float*)d_in[15];
    const float* be4 = (const float*)d_in[16];

    float* out  = (float*)d_out;
    float* bond = out + (size_t)NN * 64;

    cudaFuncSetAttribute(k1_nodegemm, cudaFuncAttributeMaxDynamicSharedMemorySize, K1_SMEM);
    cudaFuncSetAttribute(k2_stats,    cudaFuncAttributeMaxDynamicSharedMemorySize, K2_SMEM);
    cudaFuncSetAttribute(k4_fused,    cudaFuncAttributeMaxDynamicSharedMemorySize, K4_SMEM);

    k1_nodegemm<<<K1G, dim3(96,2,1), K1_SMEM>>>(x, (const int*)ei, ea, Wc, bc, Wf, bf, Wb, bb);
    k2_stats<<<K2G, 256, K2_SMEM>>>(ei, Wc, Wf, Wb);
    k3_reduce<<<CD, 256>>>(g1, be1, g2, be2, g3, be3);
    k4_fused<<<K4G, 256, K4_SMEM>>>(ei, Wc, Wf, Wb, bond);
    k5_reduce<<<KD, 256>>>(g4, be4);
    k6_out<<<(NN*64 + 255)/256, 256>>>(x, out);
}

// round 14
// speedup vs baseline: 1.3556x; 1.0374x over previous
#include <cuda_runtime.h>
#include <cuda_fp16.h>
#include <math.h>

#define NN 100000
#define NNBR 12
#define NE (NN*NNBR)
#define CD 192
#define KD 64
#define NBINS 1024
#define NB4 256
#define BN_EPS 1e-5f

#define K1G 296
#define K2G 444
#define K4G 444
#define NST 12500   // NE/96 supertiles (8 nodes each)

// ---------------- scratch (static __device__, no allocs) ----------------
// PD/PS stored in PERMUTED column order: P<128: even=core j (j=P/2),
// odd=filter j; P>=128: bond j=P-128.
__device__ __half g_PDh[(size_t)NN*CD];
__device__ __half g_PSh[(size_t)NN*CD];
__device__ __half g_EAh[(size_t)NE*KD];      // fp16 copy of edge_attr (153.6MB)
__device__ float  g_binS[(size_t)CD*NBINS];  // [P][bin]
__device__ float  g_binQ[(size_t)CD*NBINS];
__device__ float  g_scale[CD];               // permuted order
__device__ float  g_shift[CD];
__device__ float  g_nbr[NN*KD];
__device__ float  g_b4S[KD*NB4];
__device__ float  g_b4Q[KD*NB4];
__device__ float  g_scale4[KD];
__device__ float  g_shift4[KD];
__device__ int    g_is64;

__device__ __forceinline__ void ffma2(float2 &d, float2 a, float2 b) {
    asm("fma.rn.f32x2 %0, %1, %2, %0;"
        : "+l"(reinterpret_cast<unsigned long long&>(d))
        : "l"(reinterpret_cast<unsigned long long&>(a)),
          "l"(reinterpret_cast<unsigned long long&>(b)));
}

__device__ __forceinline__ void mma16816(float* c, const unsigned* a, const unsigned* b) {
    asm volatile(
        "mma.sync.aligned.m16n8k16.row.col.f32.f16.f16.f32 "
        "{%0,%1,%2,%3}, {%4,%5,%6,%7}, {%8,%9}, {%0,%1,%2,%3};"
        : "+f"(c[0]), "+f"(c[1]), "+f"(c[2]), "+f"(c[3])
        : "r"(a[0]), "r"(a[1]), "r"(a[2]), "r"(a[3]), "r"(b[0]), "r"(b[1]));
}

__device__ __forceinline__ void ldsm_x4(unsigned* a, unsigned saddr) {
    asm volatile("ldmatrix.sync.aligned.m8n8.x4.shared.b16 {%0,%1,%2,%3}, [%4];"
        : "=r"(a[0]), "=r"(a[1]), "=r"(a[2]), "=r"(a[3]) : "r"(saddr));
}

__device__ __forceinline__ unsigned smem_u32(const void* p) {
    return (unsigned)__cvta_generic_to_shared(p);
}
__device__ __forceinline__ void cpa16(unsigned s, const void* g) {
    asm volatile("cp.async.cg.shared.global [%0], [%1], 16;" :: "r"(s), "l"(g));
}
__device__ __forceinline__ void cpa_commit() {
    asm volatile("cp.async.commit_group;");
}
__device__ __forceinline__ void cpa_wait1() {
    asm volatile("cp.async.wait_group 1;");
}

__device__ __forceinline__ float softplus_f(float x) {
    return fmaxf(x, 0.f) + __logf(1.f + __expf(-fabsf(x)));
}
__device__ __forceinline__ float sigmoid_f(float x) {
    return __fdividef(1.f, 1.f + __expf(-x));
}

__device__ __forceinline__ int permP(int j) {
    if (j < 64)  return 2*j;
    if (j < 128) return 2*(j-64) + 1;
    return j;
}

// ---------------- K1: zero stats + dtype + ea->fp16 + node pre-GEMM -------
#define K1_SMEM (64*384*4 + 2*64*8*4)
__global__ void k1_nodegemm(const float* __restrict__ x,
                            const int*   __restrict__ eidx32,
                            const float* __restrict__ ea,
                            const float* __restrict__ Wc, const float* __restrict__ bc,
                            const float* __restrict__ Wf, const float* __restrict__ bf,
                            const float* __restrict__ Wb, const float* __restrict__ bb)
{
    extern __shared__ float sm[];
    float* sW = sm;             // [64][384]
    float* sX = sm + 64*384;    // [2][64][8]
    int tx = threadIdx.x, ty = threadIdx.y;
    int tid = ty*96 + tx;
    int gtid = blockIdx.x*192 + tid;

    for (int i = gtid; i < CD*NBINS; i += K1G*192) { g_binS[i] = 0.f; g_binQ[i] = 0.f; }
    for (int i = gtid; i < KD*NB4;   i += K1G*192) { g_b4S[i]  = 0.f; g_b4Q[i]  = 0.f; }
    if (gtid == 0) g_is64 = (eidx32[25] == 0) ? 1 : 0;

    // convert ea fp32 -> fp16 (grid-stride, 8 elems per iter)
    {
        const size_t NCH = (size_t)NE*KD/8;
        const float4* s4 = (const float4*)ea;
        uint4* d4 = (uint4*)g_EAh;
        for (size_t i = gtid; i < NCH; i += (size_t)K1G*192) {
            float4 a = s4[i*2], b = s4[i*2+1];
            __half2 h0 = __floats2half2_rn(a.x, a.y);
            __half2 h1 = __floats2half2_rn(a.z, a.w);
            __half2 h2 = __floats2half2_rn(b.x, b.y);
            __half2 h3 = __floats2half2_rn(b.z, b.w);
            uint4 u;
            u.x = *(unsigned*)&h0; u.y = *(unsigned*)&h1;
            u.z = *(unsigned*)&h2; u.w = *(unsigned*)&h3;
            d4[i] = u;
        }
    }

    for (int idx = tid; idx < 64*384; idx += 192) {
        int k  = idx / 384;
        int j3 = idx - k*384;
        int j  = (j3 >= 192) ? j3 - 192 : j3;
        int kk = (j3 >= 192) ? 64 + k : k;
        const float* W; int r;
        if (j < 64)       { W = Wc; r = j; }
        else if (j < 128) { W = Wf; r = j - 64; }
        else              { W = Wb; r = j - 128; }
        sW[idx] = W[r*CD + kk];
    }
    int j0 = tx, j1 = tx + 96;
    int P0 = permP(j0), P1 = permP(j1);
    float bias0 = (j0 < 64) ? bc[j0] : ((j0 < 128) ? bf[j0-64] : bb[j0-128]);
    float bias1 = (j1 < 128) ? bf[j1-64] : bb[j1-128];
    float* sXt = sX + ty*512;

    for (int g = blockIdx.x; g < NN/16; g += gridDim.x) {
        int n0 = (g*2 + ty) * 8;
        __syncthreads();
        const float4* x4 = (const float4*)(x + (size_t)n0*64);
        for (int i = tx; i < 128; i += 96) {
            float4 v = x4[i];
            int nl = i >> 4, k4 = (i & 15) * 4;
            sXt[(k4+0)*8 + nl] = v.x;
            sXt[(k4+1)*8 + nl] = v.y;
            sXt[(k4+2)*8 + nl] = v.z;
            sXt[(k4+3)*8 + nl] = v.w;
        }
        __syncthreads();

        float2 ad0[4], ad1[4], as0[4], as1[4];
        #pragma unroll
        for (int p = 0; p < 4; p++) {
            ad0[p] = make_float2(0.f,0.f); ad1[p] = make_float2(0.f,0.f);
            as0[p] = make_float2(0.f,0.f); as1[p] = make_float2(0.f,0.f);
        }
        #pragma unroll 8
        for (int k = 0; k < 64; k++) {
            float wd0 = sW[k*384 + j0];
            float wd1 = sW[k*384 + j1];
            float ws0 = sW[k*384 + 192 + j0];
            float ws1 = sW[k*384 + 192 + j1];
            float2 Wd0 = make_float2(wd0, wd0), Wd1 = make_float2(wd1, wd1);
            float2 Ws0 = make_float2(ws0, ws0), Ws1 = make_float2(ws1, ws1);
            const float2* xp = (const float2*)(sXt + k*8);
            #pragma unroll
            for (int p = 0; p < 4; p++) {
                float2 xv = xp[p];
                ffma2(ad0[p], xv, Wd0);
                ffma2(ad1[p], xv, Wd1);
                ffma2(as0[p], xv, Ws0);
                ffma2(as1[p], xv, Ws1);
            }
        }
        #pragma unroll
        for (int p = 0; p < 4; p++) {
            size_t na = (size_t)(n0 + 2*p)*CD, nb = na + CD;
            g_PDh[na + P0] = __float2half_rn(ad0[p].x + bias0);
            g_PDh[nb + P0] = __float2half_rn(ad0[p].y + bias0);
            g_PDh[na + P1] = __float2half_rn(ad1[p].x + bias1);
            g_PDh[nb + P1] = __float2half_rn(ad1[p].y + bias1);
            g_PSh[na + P0] = __float2half_rn(as0[p].x);
            g_PSh[nb + P0] = __float2half_rn(as0[p].y);
            g_PSh[na + P1] = __float2half_rn(as1[p].x);
            g_PSh[nb + P1] = __float2half_rn(as1[p].y);
        }
    }
}

// ---------------- shared smem layout for k2/k4 (sW overlapped) ------------
#define A16_STRIDE 144              // 64 halves + 16B pad (LDSM conflict-free)
#define A16B       (32*A16_STRIDE)  // 4608
#define PD_STRIDE  400
#define PDB        (32*PD_STRIDE)   // 12800
#define PSB        (8*PD_STRIDE)    // 3200
#define A16_OFF(b) ((b)*A16B)                      // 0, 4608
#define PD_OFF(b)  (2*A16B + (b)*PDB)              // 9216, 22016
#define PS_OFF(b)  (2*A16B + 2*PDB + (b)*PSB)      // 34816, 38016
#define K2_SMEM    (2*A16B + 2*PDB + 2*PSB)        // 41216
#define GT_OFF     K2_SMEM
#define GT_STRIDE  68
#define K4_SMEM    (GT_OFF + 96*GT_STRIDE*4)       // 67328
// W staged temporarily at offset 0 during init (24576 <= 41216)

// ---------------- K2s: stats-only edge GEMM (warp = M32 x N24) ------------
__global__ void __launch_bounds__(256, 3)
k2_stats(const void* __restrict__ eidx_raw,
         const float* __restrict__ Wc,
         const float* __restrict__ Wf,
         const float* __restrict__ Wb)
{
    extern __shared__ char smc[];
    unsigned* sW32 = (unsigned*)smc;       // temporary, overlapped
    unsigned smb = smem_u32(smc);
    int tid = threadIdx.x;
    int w   = tid >> 5, lane = tid & 31;
    int gq  = lane >> 2, tl = lane & 3;
    int is64 = g_is64;

    // stage permuted W_edge into (temporary) smem [P][32 u32]
    for (int i = tid; i < 192*32; i += 256) {
        int P = i >> 5, k2 = i & 31;
        const float* W; int r;
        if (P < 128) { r = P >> 1; W = (P & 1) ? Wf : Wc; }
        else         { r = P - 128; W = Wb; }
        float2 v = *(const float2*)(W + (size_t)r*CD + 128 + 2*k2);
        __half2 h = __floats2half2_rn(v.x, v.y);
        sW32[P*32 + k2] = *(unsigned*)&h;
    }
    __syncthreads();

    unsigned Bf[3][4][2];
    #pragma unroll
    for (int nt = 0; nt < 3; nt++) {
        int n = w*24 + nt*8 + gq;
        #pragma unroll
        for (int ks = 0; ks < 4; ks++) {
            Bf[nt][ks][0] = sW32[n*32 + ks*8 + tl];
            Bf[nt][ks][1] = sW32[n*32 + ks*8 + tl + 4];
        }
    }
    __syncthreads();   // done reading W region; pipeline may overwrite

    unsigned aB0 = smb + (lane & 15)*A16_STRIDE + (lane >> 4)*16;
    unsigned aB1 = aB0 + 16*A16_STRIDE;

    float sS[6], sQ[6];
    #pragma unroll
    for (int i = 0; i < 6; i++) { sS[i] = 0.f; sQ[i] = 0.f; }

    auto stageA = [&](int buf, int ebase) {
        int r = tid >> 3, c = tid & 7;
        cpa16(smb + A16_OFF(buf) + r*A16_STRIDE + c*16,
              g_EAh + (size_t)(ebase+r)*64 + c*8);
    };
    auto stagePD = [&](int buf, int ebase) {
        #pragma unroll
        for (int i = 0; i < 3; i++) {
            int f = tid + i*256;
            int r = f / 24, c = f - r*24;
            int e = ebase + r;
            int dst;
            if (is64) dst = (int)((const long long*)eidx_raw)[(size_t)NE + e];
            else      dst = ((const int*)eidx_raw)[(size_t)NE + e];
            cpa16(smb + PD_OFF(buf) + r*PD_STRIDE + c*16,
                  g_PDh + (size_t)dst*CD + c*8);
        }
    };
    auto stagePS = [&](int buf, int nodebase) {
        if (tid < 192) {
            int r = tid / 24, c = tid - r*24;
            cpa16(smb + PS_OFF(buf) + r*PD_STRIDE + c*16,
                  g_PSh + (size_t)(nodebase + r)*CD + c*8);
        }
    };

    int buf = 0, psb = 0;
    stagePD(0, blockIdx.x*96);
    stageA(0, blockIdx.x*96);
    stagePS(0, blockIdx.x*8);
    cpa_commit();

    for (int st = blockIdx.x; st < NST; st += gridDim.x) {
        #pragma unroll 1
        for (int s = 0; s < 3; s++) {
            __syncthreads();   // readers of buf^1 done
            int nst = (s < 2) ? st : st + (int)gridDim.x;
            int nss = (s < 2) ? s + 1 : 0;
            if (nst < NST) {
                stagePD(buf ^ 1, nst*96 + nss*32);
                stageA(buf ^ 1, nst*96 + nss*32);
                if (s == 2) stagePS(psb ^ 1, nst*8);
            }
            cpa_commit();
            cpa_wait1();
            __syncthreads();

            float C[2][3][4];
            #pragma unroll
            for (int g = 0; g < 2; g++)
                #pragma unroll
                for (int nt = 0; nt < 3; nt++)
                    #pragma unroll
                    for (int q = 0; q < 4; q++) C[g][nt][q] = 0.f;

            #pragma unroll
            for (int ks = 0; ks < 4; ks++) {
                unsigned A0[4], A1[4];
                ldsm_x4(A0, aB0 + A16_OFF(buf) + ks*32);
                ldsm_x4(A1, aB1 + A16_OFF(buf) + ks*32);
                #pragma unroll
                for (int nt = 0; nt < 3; nt++) {
                    mma16816(C[0][nt], A0, Bf[nt][ks]);
                    mma16816(C[1][nt], A1, Bf[nt][ks]);
                }
            }

            const __half* pd = (const __half*)(smc + PD_OFF(buf));
            const __half* ps = (const __half*)(smc + PS_OFF(psb));
            #pragma unroll
            for (int g = 0; g < 2; g++) {
                int r0 = g*16 + gq, r1 = r0 + 8;
                int ln0 = (s*32 + r0) / 12, ln1 = (s*32 + r1) / 12;
                #pragma unroll
                for (int nt = 0; nt < 3; nt++) {
                    int P0 = w*24 + nt*8 + 2*tl;
                    __half2 p0 = __hadd2(*(const __half2*)(pd + r0*200 + P0),
                                         *(const __half2*)(ps + ln0*200 + P0));
                    __half2 p1 = __hadd2(*(const __half2*)(pd + r1*200 + P0),
                                         *(const __half2*)(ps + ln1*200 + P0));
                    float2 pf0 = __half22float2(p0);
                    float2 pf1 = __half22float2(p1);
                    float u0x = C[g][nt][0] + pf0.x, u0y = C[g][nt][1] + pf0.y;
                    float u1x = C[g][nt][2] + pf1.x, u1y = C[g][nt][3] + pf1.y;
                    sS[nt*2]   += u0x + u1x;
                    sQ[nt*2]   += u0x*u0x + u1x*u1x;
                    sS[nt*2+1] += u0y + u1y;
                    sQ[nt*2+1] += u0y*u0y + u1y*u1y;
                }
            }
            buf ^= 1;
        }
        psb ^= 1;
    }

    #pragma unroll
    for (int i = 0; i < 6; i++) {
        sS[i] += __shfl_xor_sync(0xffffffff, sS[i], 4);
        sS[i] += __shfl_xor_sync(0xffffffff, sS[i], 8);
        sS[i] += __shfl_xor_sync(0xffffffff, sS[i], 16);
        sQ[i] += __shfl_xor_sync(0xffffffff, sQ[i], 4);
        sQ[i] += __shfl_xor_sync(0xffffffff, sQ[i], 8);
        sQ[i] += __shfl_xor_sync(0xffffffff, sQ[i], 16);
    }
    if (lane < 4) {
        int bin = blockIdx.x & (NBINS - 1);
        #pragma unroll
        for (int nt = 0; nt < 3; nt++) {
            int col = w*24 + nt*8 + 2*lane;
            atomicAdd(&g_binS[(size_t)col*NBINS + bin],     sS[nt*2]);
            atomicAdd(&g_binQ[(size_t)col*NBINS + bin],     sQ[nt*2]);
            atomicAdd(&g_binS[(size_t)(col+1)*NBINS + bin], sS[nt*2+1]);
            atomicAdd(&g_binQ[(size_t)(col+1)*NBINS + bin], sQ[nt*2+1]);
        }
    }
}

// ---------------- K3: reduce bins (permuted) -> scale/shift ----------
__global__ void k3_reduce(const float* __restrict__ g1, const float* __restrict__ be1,
                          const float* __restrict__ g2, const float* __restrict__ be2,
                          const float* __restrict__ g3, const float* __restrict__ be3)
{
    __shared__ float sS[256], sQ[256];
    int P = blockIdx.x, t = threadIdx.x;
    float S = 0.f, Q = 0.f;
    for (int b = t; b < NBINS; b += 256) {
        S += g_binS[(size_t)P*NBINS + b];
        Q += g_binQ[(size_t)P*NBINS + b];
    }
    sS[t] = S; sQ[t] = Q;
    __syncthreads();
    for (int o = 128; o > 0; o >>= 1) {
        if (t < o) { sS[t] += sS[t+o]; sQ[t] += sQ[t+o]; }
        __syncthreads();
    }
    if (t == 0) {
        float mean = sS[0] / (float)NE;
        float var  = sQ[0] / (float)NE - mean*mean;
        float g, be;
        if (P < 128) {
            int jj = P >> 1;
            if ((P & 1) == 0) { g = g1[jj]; be = be1[jj]; }
            else              { g = g2[jj]; be = be2[jj]; }
        } else { g = g3[P-128]; be = be3[P-128]; }
        float sc = g * rsqrtf(var + BN_EPS);
        g_scale[P] = sc;
        g_shift[P] = be - mean * sc;
    }
}

// ---------------- K4f: fused recompute + BN + gate + bond + node-sum ------
__global__ void __launch_bounds__(256, 3)
k4_fused(const void* __restrict__ eidx_raw,
         const float* __restrict__ Wc,
         const float* __restrict__ Wf,
         const float* __restrict__ Wb,
         float* __restrict__ bond_out)
{
    extern __shared__ char smc[];
    unsigned* sW32 = (unsigned*)smc;       // temporary, overlapped
    float* gated = (float*)(smc + GT_OFF);
    unsigned smb = smem_u32(smc);
    int tid = threadIdx.x;
    int w   = tid >> 5, lane = tid & 31;
    int gq  = lane >> 2, tl = lane & 3;
    int is64 = g_is64;

    for (int i = tid; i < 192*32; i += 256) {
        int P = i >> 5, k2 = i & 31;
        const float* W; int r;
        if (P < 128) { r = P >> 1; W = (P & 1) ? Wf : Wc; }
        else         { r = P - 128; W = Wb; }
        float2 v = *(const float2*)(W + (size_t)r*CD + 128 + 2*k2);
        __half2 h = __floats2half2_rn(v.x, v.y);
        sW32[P*32 + k2] = *(unsigned*)&h;
    }
    __syncthreads();

    unsigned Bf[3][4][2];
    #pragma unroll
    for (int nt = 0; nt < 3; nt++) {
        int n = w*24 + nt*8 + gq;
        #pragma unroll
        for (int ks = 0; ks < 4; ks++) {
            Bf[nt][ks][0] = sW32[n*32 + ks*8 + tl];
            Bf[nt][ks][1] = sW32[n*32 + ks*8 + tl + 4];
        }
    }
    __syncthreads();   // W region now reusable

    float2 scp[3], shp[3];
    #pragma unroll
    for (int nt = 0; nt < 3; nt++) {
        int P0 = w*24 + nt*8 + 2*tl;
        scp[nt] = *(const float2*)(g_scale + P0);
        shp[nt] = *(const float2*)(g_shift + P0);
    }

    unsigned aB0 = smb + (lane & 15)*A16_STRIDE + (lane >> 4)*16;
    unsigned aB1 = aB0 + 16*A16_STRIDE;
    float stS = 0.f, stQ = 0.f;

    auto stageA = [&](int buf, int ebase) {
        int r = tid >> 3, c = tid & 7;
        cpa16(smb + A16_OFF(buf) + r*A16_STRIDE + c*16,
              g_EAh + (size_t)(ebase+r)*64 + c*8);
    };
    auto stagePD = [&](int buf, int ebase) {
        #pragma unroll
        for (int i = 0; i < 3; i++) {
            int f = tid + i*256;
            int r = f / 24, c = f - r*24;
            int e = ebase + r;
            int dst;
            if (is64) dst = (int)((const long long*)eidx_raw)[(size_t)NE + e];
            else      dst = ((const int*)eidx_raw)[(size_t)NE + e];
            cpa16(smb + PD_OFF(buf) + r*PD_STRIDE + c*16,
                  g_PDh + (size_t)dst*CD + c*8);
        }
    };
    auto stagePS = [&](int buf, int nodebase) {
        if (tid < 192) {
            int r = tid / 24, c = tid - r*24;
            cpa16(smb + PS_OFF(buf) + r*PD_STRIDE + c*16,
                  g_PSh + (size_t)(nodebase + r)*CD + c*8);
        }
    };

    int buf = 0, psb = 0;
    stagePD(0, blockIdx.x*96);
    stageA(0, blockIdx.x*96);
    stagePS(0, blockIdx.x*8);
    cpa_commit();

    for (int st = blockIdx.x; st < NST; st += gridDim.x) {
        #pragma unroll 1
        for (int s = 0; s < 3; s++) {
            __syncthreads();   // readers of buf^1 / (gated at s==0) done
            int nst = (s < 2) ? st : st + (int)gridDim.x;
            int nss = (s < 2) ? s + 1 : 0;
            if (nst < NST) {
                stagePD(buf ^ 1, nst*96 + nss*32);
                stageA(buf ^ 1, nst*96 + nss*32);
                if (s == 2) stagePS(psb ^ 1, nst*8);
            }
            cpa_commit();
            cpa_wait1();
            __syncthreads();

            int ebase = st*96 + s*32;

            float C[2][3][4];
            #pragma unroll
            for (int g = 0; g < 2; g++)
                #pragma unroll
                for (int nt = 0; nt < 3; nt++)
                    #pragma unroll
                    for (int q = 0; q < 4; q++) C[g][nt][q] = 0.f;

            #pragma unroll
            for (int ks = 0; ks < 4; ks++) {
                unsigned A0[4], A1[4];
                ldsm_x4(A0, aB0 + A16_OFF(buf) + ks*32);
                ldsm_x4(A1, aB1 + A16_OFF(buf) + ks*32);
                #pragma unroll
                for (int nt = 0; nt < 3; nt++) {
                    mma16816(C[0][nt], A0, Bf[nt][ks]);
                    mma16816(C[1][nt], A1, Bf[nt][ks]);
                }
            }

            const __half* pd = (const __half*)(smc + PD_OFF(buf));
            const __half* ps = (const __half*)(smc + PS_OFF(psb));
            const __half* aS = (const __half*)(smc + A16_OFF(buf));

            #pragma unroll
            for (int g = 0; g < 2; g++) {
                int r0 = g*16 + gq, r1 = r0 + 8;
                int e0g = ebase + r0, e1g = ebase + r1;
                int ln0 = (s*32 + r0) / 12, ln1 = (s*32 + r1) / 12;
                int row0 = s*32 + r0, row1 = s*32 + r1;
                #pragma unroll
                for (int nt = 0; nt < 3; nt++) {
                    int P0 = w*24 + nt*8 + 2*tl;
                    __half2 p0 = __hadd2(*(const __half2*)(pd + r0*200 + P0),
                                         *(const __half2*)(ps + ln0*200 + P0));
                    __half2 p1 = __hadd2(*(const __half2*)(pd + r1*200 + P0),
                                         *(const __half2*)(ps + ln1*200 + P0));
                    float2 pf0 = __half22float2(p0);
                    float2 pf1 = __half22float2(p1);
                    float v00 = fmaf(C[g][nt][0] + pf0.x, scp[nt].x, shp[nt].x);
                    float v01 = fmaf(C[g][nt][1] + pf0.y, scp[nt].y, shp[nt].y);
                    float v10 = fmaf(C[g][nt][2] + pf1.x, scp[nt].x, shp[nt].x);
                    float v11 = fmaf(C[g][nt][3] + pf1.y, scp[nt].y, shp[nt].y);
                    if (P0 < 128) {
                        int j = P0 >> 1;
                        gated[row0*GT_STRIDE + j] = sigmoid_f(v00) * softplus_f(v01);
                        gated[row1*GT_STRIDE + j] = sigmoid_f(v10) * softplus_f(v11);
                    } else {
                        int jb = P0 - 128;
                        float2 ev0 = __half22float2(*(const __half2*)(aS + r0*72 + jb));
                        float2 ev1 = __half22float2(*(const __half2*)(aS + r1*72 + jb));
                        float2 bo0, bo1;
                        bo0.x = softplus_f(ev0.x + v00);
                        bo0.y = softplus_f(ev0.y + v01);
                        bo1.x = softplus_f(ev1.x + v10);
                        bo1.y = softplus_f(ev1.y + v11);
                        *(float2*)(bond_out + (size_t)e0g*64 + jb) = bo0;
                        *(float2*)(bond_out + (size_t)e1g*64 + jb) = bo1;
                    }
                }
            }
            buf ^= 1;
        }
        __syncthreads();   // gated complete

        {
            int j = tid & 63;
            #pragma unroll
            for (int h = 0; h < 2; h++) {
                int d = (tid >> 6) + 4*h;
                float acc = 0.f;
                #pragma unroll
                for (int k = 0; k < 12; k++)
                    acc += gated[(d*12 + k)*GT_STRIDE + j];
                g_nbr[(size_t)(st*8 + d)*64 + j] = acc;
                stS += acc; stQ += acc*acc;
            }
        }
        psb ^= 1;
    }

    {
        int j = tid & 63;
        int bin = blockIdx.x & (NB4 - 1);
        atomicAdd(&g_b4S[j*NB4 + bin], stS);
        atomicAdd(&g_b4Q[j*NB4 + bin], stQ);
    }
}

// ---------------- K5: parallel reduce node-BN ----------------
__global__ void k5_reduce(const float* __restrict__ g4, const float* __restrict__ be4)
{
    __shared__ float sS[256], sQ[256];
    int j = blockIdx.x, t = threadIdx.x;
    float S = (t < NB4) ? g_b4S[j*NB4 + t] : 0.f;
    float Q = (t < NB4) ? g_b4Q[j*NB4 + t] : 0.f;
    sS[t] = S; sQ[t] = Q;
    __syncthreads();
    for (int o = 128; o > 0; o >>= 1) {
        if (t < o) { sS[t] += sS[t+o]; sQ[t] += sQ[t+o]; }
        __syncthreads();
    }
    if (t == 0) {
        float mean = sS[0] / (float)NN;
        float var  = sQ[0] / (float)NN - mean*mean;
        float sc = g4[j] * rsqrtf(var + BN_EPS);
        g_scale4[j] = sc;
        g_shift4[j] = be4[j] - mean * sc;
    }
}

// ---------------- K6: out = softplus(x + bn4(nbr_sum)) ----------------
__global__ void k6_out(const float* __restrict__ x, float* __restrict__ out)
{
    int i = blockIdx.x * 256 + threadIdx.x;
    if (i < NN*64) {
        int j = i & 63;
        float v = x[i] + fmaf(g_nbr[i], g_scale4[j], g_shift4[j]);
        out[i] = softplus_f(v);
    }
}

extern "C" void kernel_launch(void* const* d_in, const int* in_sizes, int n_in,
                              void* d_out, int out_size)
{
    const float* x   = (const float*)d_in[0];
    const void*  ei  = (const void*)d_in[1];
    const float* ea  = (const float*)d_in[2];
    const float* Wc  = (const float*)d_in[3];
    const float* bc  = (const float*)d_in[4];
    const float* Wf  = (const float*)d_in[5];
    const float* bf  = (const float*)d_in[6];
    const float* Wb  = (const float*)d_in[7];
    const float* bb  = (const float*)d_in[8];
    const float* g1  = (const float*)d_in[9];
    const float* be1 = (const float*)d_in[10];
    const float* g2  = (const float*)d_in[11];
    const float* be2 = (const float*)d_in[12];
    const float* g3  = (const float*)d_in[13];
    const float* be3 = (const float*)d_in[14];
    const float* g4  = (const float*)d_in[15];
    const float* be4 = (const float*)d_in[16];

    float* out  = (float*)d_out;
    float* bond = out + (size_t)NN * 64;

    cudaFuncSetAttribute(k1_nodegemm, cudaFuncAttributeMaxDynamicSharedMemorySize, K1_SMEM);
    cudaFuncSetAttribute(k2_stats,    cudaFuncAttributeMaxDynamicSharedMemorySize, K2_SMEM);
    cudaFuncSetAttribute(k4_fused,    cudaFuncAttributeMaxDynamicSharedMemorySize, K4_SMEM);

    k1_nodegemm<<<K1G, dim3(96,2,1), K1_SMEM>>>(x, (const int*)ei, ea, Wc, bc, Wf, bf, Wb, bb);
    k2_stats<<<K2G, 256, K2_SMEM>>>(ei, Wc, Wf, Wb);
    k3_reduce<<<CD, 256>>>(g1, be1, g2, be2, g3, be3);
    k4_fused<<<K4G, 256, K4_SMEM>>>(ei, Wc, Wf, Wb, bond);
    k5_reduce<<<KD, 256>>>(g4, be4);
    k6_out<<<(NN*64 + 255)/256, 256>>>(x, out);
}

// round 15
// speedup vs baseline: 1.4048x; 1.0363x over previous
#include <cuda_runtime.h>
#include <cuda_fp16.h>
#include <math.h>

#define NN 100000
#define NNBR 12
#define NE (NN*NNBR)
#define CD 192
#define KD 64
#define NBINS 1024
#define NB4 256
#define BN_EPS 1e-5f

#define K1G 296
#define K2G 444
#define K4G 444
#define NST 12500   // NE/96 supertiles (8 nodes each)

// ---------------- scratch (static __device__, no allocs) ----------------
// PD/PS stored in PERMUTED column order: P<128: even=core j (j=P/2),
// odd=filter j; P>=128: bond j=P-128.
__device__ __half g_PDh[(size_t)NN*CD];
__device__ __half g_PSh[(size_t)NN*CD];
__device__ __half g_EAh[(size_t)NE*KD];      // fp16 copy of edge_attr (153.6MB)
__device__ float  g_binS[(size_t)CD*NBINS];  // [P][bin]
__device__ float  g_binQ[(size_t)CD*NBINS];
__device__ float  g_scale[CD];               // permuted order
__device__ float  g_shift[CD];
__device__ float  g_nbr[NN*KD];
__device__ float  g_b4S[KD*NB4];
__device__ float  g_b4Q[KD*NB4];
__device__ float  g_scale4[KD];
__device__ float  g_shift4[KD];
__device__ int    g_is64;

__device__ __forceinline__ void ffma2(float2 &d, float2 a, float2 b) {
    asm("fma.rn.f32x2 %0, %1, %2, %0;"
        : "+l"(reinterpret_cast<unsigned long long&>(d))
        : "l"(reinterpret_cast<unsigned long long&>(a)),
          "l"(reinterpret_cast<unsigned long long&>(b)));
}

__device__ __forceinline__ void mma16816(float* c, const unsigned* a, const unsigned* b) {
    asm volatile(
        "mma.sync.aligned.m16n8k16.row.col.f32.f16.f16.f32 "
        "{%0,%1,%2,%3}, {%4,%5,%6,%7}, {%8,%9}, {%0,%1,%2,%3};"
        : "+f"(c[0]), "+f"(c[1]), "+f"(c[2]), "+f"(c[3])
        : "r"(a[0]), "r"(a[1]), "r"(a[2]), "r"(a[3]), "r"(b[0]), "r"(b[1]));
}

__device__ __forceinline__ void ldsm_x4(unsigned* a, unsigned saddr) {
    asm volatile("ldmatrix.sync.aligned.m8n8.x4.shared.b16 {%0,%1,%2,%3}, [%4];"
        : "=r"(a[0]), "=r"(a[1]), "=r"(a[2]), "=r"(a[3]) : "r"(saddr));
}

__device__ __forceinline__ unsigned smem_u32(const void* p) {
    return (unsigned)__cvta_generic_to_shared(p);
}
__device__ __forceinline__ void cpa16(unsigned s, const void* g) {
    asm volatile("cp.async.cg.shared.global [%0], [%1], 16;" :: "r"(s), "l"(g));
}
__device__ __forceinline__ void cpa_commit() {
    asm volatile("cp.async.commit_group;");
}
__device__ __forceinline__ void cpa_wait1() {
    asm volatile("cp.async.wait_group 1;");
}

__device__ __forceinline__ float softplus_f(float x) {
    return fmaxf(x, 0.f) + __logf(1.f + __expf(-fabsf(x)));
}
__device__ __forceinline__ float sigmoid_f(float x) {
    return __fdividef(1.f, 1.f + __expf(-x));
}

__device__ __forceinline__ int permP(int j) {
    if (j < 64)  return 2*j;
    if (j < 128) return 2*(j-64) + 1;
    return j;
}

// ---------------- K1: zero stats + dtype + ea->fp16 + node pre-GEMM -------
#define K1_SMEM (64*384*4 + 2*64*8*4)
__global__ void k1_nodegemm(const float* __restrict__ x,
                            const int*   __restrict__ eidx32,
                            const float* __restrict__ ea,
                            const float* __restrict__ Wc, const float* __restrict__ bc,
                            const float* __restrict__ Wf, const float* __restrict__ bf,
                            const float* __restrict__ Wb, const float* __restrict__ bb)
{
    extern __shared__ float sm[];
    float* sW = sm;             // [64][384]
    float* sX = sm + 64*384;    // [2][64][8]
    int tx = threadIdx.x, ty = threadIdx.y;
    int tid = ty*96 + tx;
    int gtid = blockIdx.x*192 + tid;

    for (int i = gtid; i < CD*NBINS; i += K1G*192) { g_binS[i] = 0.f; g_binQ[i] = 0.f; }
    for (int i = gtid; i < KD*NB4;   i += K1G*192) { g_b4S[i]  = 0.f; g_b4Q[i]  = 0.f; }
    if (gtid == 0) g_is64 = (eidx32[25] == 0) ? 1 : 0;

    // convert ea fp32 -> fp16
    {
        const size_t NCH = (size_t)NE*KD/8;
        const float4* s4 = (const float4*)ea;
        uint4* d4 = (uint4*)g_EAh;
        for (size_t i = gtid; i < NCH; i += (size_t)K1G*192) {
            float4 a = s4[i*2], b = s4[i*2+1];
            __half2 h0 = __floats2half2_rn(a.x, a.y);
            __half2 h1 = __floats2half2_rn(a.z, a.w);
            __half2 h2 = __floats2half2_rn(b.x, b.y);
            __half2 h3 = __floats2half2_rn(b.z, b.w);
            uint4 u;
            u.x = *(unsigned*)&h0; u.y = *(unsigned*)&h1;
            u.z = *(unsigned*)&h2; u.w = *(unsigned*)&h3;
            d4[i] = u;
        }
    }

    for (int idx = tid; idx < 64*384; idx += 192) {
        int k  = idx / 384;
        int j3 = idx - k*384;
        int j  = (j3 >= 192) ? j3 - 192 : j3;
        int kk = (j3 >= 192) ? 64 + k : k;
        const float* W; int r;
        if (j < 64)       { W = Wc; r = j; }
        else if (j < 128) { W = Wf; r = j - 64; }
        else              { W = Wb; r = j - 128; }
        sW[idx] = W[r*CD + kk];
    }
    int j0 = tx, j1 = tx + 96;
    int P0 = permP(j0), P1 = permP(j1);
    float bias0 = (j0 < 64) ? bc[j0] : ((j0 < 128) ? bf[j0-64] : bb[j0-128]);
    float bias1 = (j1 < 128) ? bf[j1-64] : bb[j1-128];
    float* sXt = sX + ty*512;

    for (int g = blockIdx.x; g < NN/16; g += gridDim.x) {
        int n0 = (g*2 + ty) * 8;
        __syncthreads();
        const float4* x4 = (const float4*)(x + (size_t)n0*64);
        for (int i = tx; i < 128; i += 96) {
            float4 v = x4[i];
            int nl = i >> 4, k4 = (i & 15) * 4;
            sXt[(k4+0)*8 + nl] = v.x;
            sXt[(k4+1)*8 + nl] = v.y;
            sXt[(k4+2)*8 + nl] = v.z;
            sXt[(k4+3)*8 + nl] = v.w;
        }
        __syncthreads();

        float2 ad0[4], ad1[4], as0[4], as1[4];
        #pragma unroll
        for (int p = 0; p < 4; p++) {
            ad0[p] = make_float2(0.f,0.f); ad1[p] = make_float2(0.f,0.f);
            as0[p] = make_float2(0.f,0.f); as1[p] = make_float2(0.f,0.f);
        }
        #pragma unroll 8
        for (int k = 0; k < 64; k++) {
            float wd0 = sW[k*384 + j0];
            float wd1 = sW[k*384 + j1];
            float ws0 = sW[k*384 + 192 + j0];
            float ws1 = sW[k*384 + 192 + j1];
            float2 Wd0 = make_float2(wd0, wd0), Wd1 = make_float2(wd1, wd1);
            float2 Ws0 = make_float2(ws0, ws0), Ws1 = make_float2(ws1, ws1);
            const float2* xp = (const float2*)(sXt + k*8);
            #pragma unroll
            for (int p = 0; p < 4; p++) {
                float2 xv = xp[p];
                ffma2(ad0[p], xv, Wd0);
                ffma2(ad1[p], xv, Wd1);
                ffma2(as0[p], xv, Ws0);
                ffma2(as1[p], xv, Ws1);
            }
        }
        #pragma unroll
        for (int p = 0; p < 4; p++) {
            size_t na = (size_t)(n0 + 2*p)*CD, nb = na + CD;
            g_PDh[na + P0] = __float2half_rn(ad0[p].x + bias0);
            g_PDh[nb + P0] = __float2half_rn(ad0[p].y + bias0);
            g_PDh[na + P1] = __float2half_rn(ad1[p].x + bias1);
            g_PDh[nb + P1] = __float2half_rn(ad1[p].y + bias1);
            g_PSh[na + P0] = __float2half_rn(as0[p].x);
            g_PSh[nb + P0] = __float2half_rn(as0[p].y);
            g_PSh[na + P1] = __float2half_rn(as1[p].x);
            g_PSh[nb + P1] = __float2half_rn(as1[p].y);
        }
    }
}

// ---------------- shared smem layout: 3-ring A/PD, 2-ring PS --------------
#define A16_STRIDE 144              // 64 halves + 16B pad (LDSM conflict-free)
#define A16B       (32*A16_STRIDE)  // 4608
#define PD_STRIDE  400
#define PDB        (32*PD_STRIDE)   // 12800
#define PSB        (8*PD_STRIDE)    // 3200
#define A16_OFF(b) ((b)*A16B)                      // 0..2
#define PD_OFF(b)  (3*A16B + (b)*PDB)
#define PS_OFF(b)  (3*A16B + 3*PDB + (b)*PSB)
#define K2_SMEM    (3*A16B + 3*PDB + 2*PSB)        // 58624
#define GT_OFF     K2_SMEM
#define GT_STRIDE  68                              // halves per gated row
#define K4_SMEM    (GT_OFF + 96*GT_STRIDE*2)       // 71680
// W staged temporarily at offset 0 during init (24576 <= 58624)

// ---------------- K2s: stats-only edge GEMM (1 sync/subtile) --------------
__global__ void __launch_bounds__(256, 3)
k2_stats(const void* __restrict__ eidx_raw,
         const float* __restrict__ Wc,
         const float* __restrict__ Wf,
         const float* __restrict__ Wb)
{
    extern __shared__ char smc[];
    unsigned* sW32 = (unsigned*)smc;       // temporary, overlapped
    unsigned smb = smem_u32(smc);
    int tid = threadIdx.x;
    int w   = tid >> 5, lane = tid & 31;
    int gq  = lane >> 2, tl = lane & 3;
    int is64 = g_is64;

    for (int i = tid; i < 192*32; i += 256) {
        int P = i >> 5, k2 = i & 31;
        const float* W; int r;
        if (P < 128) { r = P >> 1; W = (P & 1) ? Wf : Wc; }
        else         { r = P - 128; W = Wb; }
        float2 v = *(const float2*)(W + (size_t)r*CD + 128 + 2*k2);
        __half2 h = __floats2half2_rn(v.x, v.y);
        sW32[P*32 + k2] = *(unsigned*)&h;
    }
    __syncthreads();

    unsigned Bf[3][4][2];
    #pragma unroll
    for (int nt = 0; nt < 3; nt++) {
        int n = w*24 + nt*8 + gq;
        #pragma unroll
        for (int ks = 0; ks < 4; ks++) {
            Bf[nt][ks][0] = sW32[n*32 + ks*8 + tl];
            Bf[nt][ks][1] = sW32[n*32 + ks*8 + tl + 4];
        }
    }
    __syncthreads();   // W region reusable

    unsigned aB0 = smb + (lane & 15)*A16_STRIDE + (lane >> 4)*16;
    unsigned aB1 = aB0 + 16*A16_STRIDE;

    float sS[6], sQ[6];
    #pragma unroll
    for (int i = 0; i < 6; i++) { sS[i] = 0.f; sQ[i] = 0.f; }

    // staging cursor
    int stq_st = blockIdx.x, stq_s = 0, psq = 0;

    auto stageNext = [&](int slot) {
        if (stq_st < NST) {
            int ebase = stq_st*96 + stq_s*32;
            {   // A tile
                int r = tid >> 3, c = tid & 7;
                cpa16(smb + A16_OFF(slot) + r*A16_STRIDE + c*16,
                      g_EAh + (size_t)(ebase+r)*64 + c*8);
            }
            #pragma unroll
            for (int i = 0; i < 3; i++) {   // PD
                int f = tid + i*256;
                int r = f / 24, c = f - r*24;
                int e = ebase + r;
                int dst;
                if (is64) dst = (int)((const long long*)eidx_raw)[(size_t)NE + e];
                else      dst = ((const int*)eidx_raw)[(size_t)NE + e];
                cpa16(smb + PD_OFF(slot) + r*PD_STRIDE + c*16,
                      g_PDh + (size_t)dst*CD + c*8);
            }
            if (stq_s == 0) {               // PS for this supertile
                if (tid < 192) {
                    int r = tid / 24, c = tid - r*24;
                    cpa16(smb + PS_OFF(psq) + r*PD_STRIDE + c*16,
                          g_PSh + (size_t)(stq_st*8 + r)*CD + c*8);
                }
                psq ^= 1;
            }
        }
        if (++stq_s == 3) { stq_s = 0; stq_st += gridDim.x; }
    };

    stageNext(0); cpa_commit();
    stageNext(1); cpa_commit();

    int slot = 0, slotS = 2, psb = 0;
    for (int st = blockIdx.x; st < NST; st += gridDim.x) {
        #pragma unroll 1
        for (int s = 0; s < 3; s++) {
            cpa_wait1();
            __syncthreads();
            stageNext(slotS); slotS = (slotS == 2) ? 0 : slotS + 1;
            cpa_commit();

            float C[2][3][4];
            #pragma unroll
            for (int g = 0; g < 2; g++)
                #pragma unroll
                for (int nt = 0; nt < 3; nt++)
                    #pragma unroll
                    for (int q = 0; q < 4; q++) C[g][nt][q] = 0.f;

            #pragma unroll
            for (int ks = 0; ks < 4; ks++) {
                unsigned A0[4], A1[4];
                ldsm_x4(A0, aB0 + A16_OFF(slot) + ks*32);
                ldsm_x4(A1, aB1 + A16_OFF(slot) + ks*32);
                #pragma unroll
                for (int nt = 0; nt < 3; nt++) {
                    mma16816(C[0][nt], A0, Bf[nt][ks]);
                    mma16816(C[1][nt], A1, Bf[nt][ks]);
                }
            }

            const __half* pd = (const __half*)(smc + PD_OFF(slot));
            const __half* ps = (const __half*)(smc + PS_OFF(psb));
            #pragma unroll
            for (int g = 0; g < 2; g++) {
                int r0 = g*16 + gq, r1 = r0 + 8;
                int ln0 = (s*32 + r0) / 12, ln1 = (s*32 + r1) / 12;
                #pragma unroll
                for (int nt = 0; nt < 3; nt++) {
                    int P0 = w*24 + nt*8 + 2*tl;
                    __half2 p0 = __hadd2(*(const __half2*)(pd + r0*200 + P0),
                                         *(const __half2*)(ps + ln0*200 + P0));
                    __half2 p1 = __hadd2(*(const __half2*)(pd + r1*200 + P0),
                                         *(const __half2*)(ps + ln1*200 + P0));
                    float2 pf0 = __half22float2(p0);
                    float2 pf1 = __half22float2(p1);
                    float u0x = C[g][nt][0] + pf0.x, u0y = C[g][nt][1] + pf0.y;
                    float u1x = C[g][nt][2] + pf1.x, u1y = C[g][nt][3] + pf1.y;
                    sS[nt*2]   += u0x + u1x;
                    sQ[nt*2]   += u0x*u0x + u1x*u1x;
                    sS[nt*2+1] += u0y + u1y;
                    sQ[nt*2+1] += u0y*u0y + u1y*u1y;
                }
            }
            slot = (slot == 2) ? 0 : slot + 1;
        }
        psb ^= 1;
    }

    #pragma unroll
    for (int i = 0; i < 6; i++) {
        sS[i] += __shfl_xor_sync(0xffffffff, sS[i], 4);
        sS[i] += __shfl_xor_sync(0xffffffff, sS[i], 8);
        sS[i] += __shfl_xor_sync(0xffffffff, sS[i], 16);
        sQ[i] += __shfl_xor_sync(0xffffffff, sQ[i], 4);
        sQ[i] += __shfl_xor_sync(0xffffffff, sQ[i], 8);
        sQ[i] += __shfl_xor_sync(0xffffffff, sQ[i], 16);
    }
    if (lane < 4) {
        int bin = blockIdx.x & (NBINS - 1);
        #pragma unroll
        for (int nt = 0; nt < 3; nt++) {
            int col = w*24 + nt*8 + 2*lane;
            atomicAdd(&g_binS[(size_t)col*NBINS + bin],     sS[nt*2]);
            atomicAdd(&g_binQ[(size_t)col*NBINS + bin],     sQ[nt*2]);
            atomicAdd(&g_binS[(size_t)(col+1)*NBINS + bin], sS[nt*2+1]);
            atomicAdd(&g_binQ[(size_t)(col+1)*NBINS + bin], sQ[nt*2+1]);
        }
    }
}

// ---------------- K3: reduce bins (permuted) -> scale/shift ----------
__global__ void k3_reduce(const float* __restrict__ g1, const float* __restrict__ be1,
                          const float* __restrict__ g2, const float* __restrict__ be2,
                          const float* __restrict__ g3, const float* __restrict__ be3)
{
    __shared__ float sS[256], sQ[256];
    int P = blockIdx.x, t = threadIdx.x;
    float S = 0.f, Q = 0.f;
    for (int b = t; b < NBINS; b += 256) {
        S += g_binS[(size_t)P*NBINS + b];
        Q += g_binQ[(size_t)P*NBINS + b];
    }
    sS[t] = S; sQ[t] = Q;
    __syncthreads();
    for (int o = 128; o > 0; o >>= 1) {
        if (t < o) { sS[t] += sS[t+o]; sQ[t] += sQ[t+o]; }
        __syncthreads();
    }
    if (t == 0) {
        float mean = sS[0] / (float)NE;
        float var  = sQ[0] / (float)NE - mean*mean;
        float g, be;
        if (P < 128) {
            int jj = P >> 1;
            if ((P & 1) == 0) { g = g1[jj]; be = be1[jj]; }
            else              { g = g2[jj]; be = be2[jj]; }
        } else { g = g3[P-128]; be = be3[P-128]; }
        float sc = g * rsqrtf(var + BN_EPS);
        g_scale[P] = sc;
        g_shift[P] = be - mean * sc;
    }
}

// ---------------- K4f: fused recompute + BN + gate + bond + node-sum ------
__global__ void __launch_bounds__(256, 3)
k4_fused(const void* __restrict__ eidx_raw,
         const float* __restrict__ Wc,
         const float* __restrict__ Wf,
         const float* __restrict__ Wb,
         float* __restrict__ bond_out)
{
    extern __shared__ char smc[];
    unsigned* sW32 = (unsigned*)smc;       // temporary, overlapped
    __half* gatedH = (__half*)(smc + GT_OFF);
    unsigned smb = smem_u32(smc);
    int tid = threadIdx.x;
    int w   = tid >> 5, lane = tid & 31;
    int gq  = lane >> 2, tl = lane & 3;
    int is64 = g_is64;

    for (int i = tid; i < 192*32; i += 256) {
        int P = i >> 5, k2 = i & 31;
        const float* W; int r;
        if (P < 128) { r = P >> 1; W = (P & 1) ? Wf : Wc; }
        else         { r = P - 128; W = Wb; }
        float2 v = *(const float2*)(W + (size_t)r*CD + 128 + 2*k2);
        __half2 h = __floats2half2_rn(v.x, v.y);
        sW32[P*32 + k2] = *(unsigned*)&h;
    }
    __syncthreads();

    unsigned Bf[3][4][2];
    #pragma unroll
    for (int nt = 0; nt < 3; nt++) {
        int n = w*24 + nt*8 + gq;
        #pragma unroll
        for (int ks = 0; ks < 4; ks++) {
            Bf[nt][ks][0] = sW32[n*32 + ks*8 + tl];
            Bf[nt][ks][1] = sW32[n*32 + ks*8 + tl + 4];
        }
    }
    __syncthreads();

    float2 scp[3], shp[3];
    #pragma unroll
    for (int nt = 0; nt < 3; nt++) {
        int P0 = w*24 + nt*8 + 2*tl;
        scp[nt] = *(const float2*)(g_scale + P0);
        shp[nt] = *(const float2*)(g_shift + P0);
    }

    unsigned aB0 = smb + (lane & 15)*A16_STRIDE + (lane >> 4)*16;
    unsigned aB1 = aB0 + 16*A16_STRIDE;
    float2 stS = make_float2(0.f,0.f), stQ = make_float2(0.f,0.f);

    int stq_st = blockIdx.x, stq_s = 0, psq = 0;
    auto stageNext = [&](int slot) {
        if (stq_st < NST) {
            int ebase = stq_st*96 + stq_s*32;
            {
                int r = tid >> 3, c = tid & 7;
                cpa16(smb + A16_OFF(slot) + r*A16_STRIDE + c*16,
                      g_EAh + (size_t)(ebase+r)*64 + c*8);
            }
            #pragma unroll
            for (int i = 0; i < 3; i++) {
                int f = tid + i*256;
                int r = f / 24, c = f - r*24;
                int e = ebase + r;
                int dst;
                if (is64) dst = (int)((const long long*)eidx_raw)[(size_t)NE + e];
                else      dst = ((const int*)eidx_raw)[(size_t)NE + e];
                cpa16(smb + PD_OFF(slot) + r*PD_STRIDE + c*16,
                      g_PDh + (size_t)dst*CD + c*8);
            }
            if (stq_s == 0) {
                if (tid < 192) {
                    int r = tid / 24, c = tid - r*24;
                    cpa16(smb + PS_OFF(psq) + r*PD_STRIDE + c*16,
                          g_PSh + (size_t)(stq_st*8 + r)*CD + c*8);
                }
                psq ^= 1;
            }
        }
        if (++stq_s == 3) { stq_s = 0; stq_st += gridDim.x; }
    };

    stageNext(0); cpa_commit();
    stageNext(1); cpa_commit();

    int slot = 0, slotS = 2, psb = 0;
    for (int st = blockIdx.x; st < NST; st += gridDim.x) {
        #pragma unroll 1
        for (int s = 0; s < 3; s++) {
            cpa_wait1();
            __syncthreads();   // data(slot) visible; slotS safe to restage; gated reduce done
            stageNext(slotS); slotS = (slotS == 2) ? 0 : slotS + 1;
            cpa_commit();

            int ebase = st*96 + s*32;

            float C[2][3][4];
            #pragma unroll
            for (int g = 0; g < 2; g++)
                #pragma unroll
                for (int nt = 0; nt < 3; nt++)
                    #pragma unroll
                    for (int q = 0; q < 4; q++) C[g][nt][q] = 0.f;

            #pragma unroll
            for (int ks = 0; ks < 4; ks++) {
                unsigned A0[4], A1[4];
                ldsm_x4(A0, aB0 + A16_OFF(slot) + ks*32);
                ldsm_x4(A1, aB1 + A16_OFF(slot) + ks*32);
                #pragma unroll
                for (int nt = 0; nt < 3; nt++) {
                    mma16816(C[0][nt], A0, Bf[nt][ks]);
                    mma16816(C[1][nt], A1, Bf[nt][ks]);
                }
            }

            const __half* pd = (const __half*)(smc + PD_OFF(slot));
            const __half* ps = (const __half*)(smc + PS_OFF(psb));
            const __half* aS = (const __half*)(smc + A16_OFF(slot));

            #pragma unroll
            for (int g = 0; g < 2; g++) {
                int r0 = g*16 + gq, r1 = r0 + 8;
                int e0g = ebase + r0, e1g = ebase + r1;
                int ln0 = (s*32 + r0) / 12, ln1 = (s*32 + r1) / 12;
                int row0 = s*32 + r0, row1 = s*32 + r1;
                #pragma unroll
                for (int nt = 0; nt < 3; nt++) {
                    int P0 = w*24 + nt*8 + 2*tl;
                    __half2 p0 = __hadd2(*(const __half2*)(pd + r0*200 + P0),
                                         *(const __half2*)(ps + ln0*200 + P0));
                    __half2 p1 = __hadd2(*(const __half2*)(pd + r1*200 + P0),
                                         *(const __half2*)(ps + ln1*200 + P0));
                    float2 pf0 = __half22float2(p0);
                    float2 pf1 = __half22float2(p1);
                    float v00 = fmaf(C[g][nt][0] + pf0.x, scp[nt].x, shp[nt].x);
                    float v01 = fmaf(C[g][nt][1] + pf0.y, scp[nt].y, shp[nt].y);
                    float v10 = fmaf(C[g][nt][2] + pf1.x, scp[nt].x, shp[nt].x);
                    float v11 = fmaf(C[g][nt][3] + pf1.y, scp[nt].y, shp[nt].y);
                    if (P0 < 128) {
                        int j = P0 >> 1;
                        gatedH[row0*GT_STRIDE + j] =
                            __float2half_rn(sigmoid_f(v00) * softplus_f(v01));
                        gatedH[row1*GT_STRIDE + j] =
                            __float2half_rn(sigmoid_f(v10) * softplus_f(v11));
                    } else {
                        int jb = P0 - 128;
                        float2 ev0 = __half22float2(*(const __half2*)(aS + r0*72 + jb));
                        float2 ev1 = __half22float2(*(const __half2*)(aS + r1*72 + jb));
                        float2 bo0, bo1;
                        bo0.x = softplus_f(ev0.x + v00);
                        bo0.y = softplus_f(ev0.y + v01);
                        bo1.x = softplus_f(ev1.x + v10);
                        bo1.y = softplus_f(ev1.y + v11);
                        *(float2*)(bond_out + (size_t)e0g*64 + jb) = bo0;
                        *(float2*)(bond_out + (size_t)e1g*64 + jb) = bo1;
                    }
                }
            }
            slot = (slot == 2) ? 0 : slot + 1;
        }
        __syncthreads();   // gated complete for all 96 rows

        // node reduce: thread = (node d = tid>>5, col-pair jp = lane)
        {
            int d = tid >> 5;
            int jp = lane;
            float2 acc = make_float2(0.f, 0.f);
            #pragma unroll
            for (int k = 0; k < 12; k++) {
                float2 gf = __half22float2(
                    *(const __half2*)(gatedH + (d*12 + k)*GT_STRIDE + 2*jp));
                acc.x += gf.x; acc.y += gf.y;
            }
            *(float2*)(g_nbr + (size_t)(st*8 + d)*64 + 2*jp) = acc;
            stS.x += acc.x; stQ.x += acc.x*acc.x;
            stS.y += acc.y; stQ.y += acc.y*acc.y;
        }
        psb ^= 1;
    }

    {
        int bin = blockIdx.x & (NB4 - 1);
        atomicAdd(&g_b4S[(2*lane)*NB4 + bin],   stS.x);
        atomicAdd(&g_b4Q[(2*lane)*NB4 + bin],   stQ.x);
        atomicAdd(&g_b4S[(2*lane+1)*NB4 + bin], stS.y);
        atomicAdd(&g_b4Q[(2*lane+1)*NB4 + bin], stQ.y);
    }
}

// ---------------- K5: parallel reduce node-BN ----------------
__global__ void k5_reduce(const float* __restrict__ g4, const float* __restrict__ be4)
{
    __shared__ float sS[256], sQ[256];
    int j = blockIdx.x, t = threadIdx.x;
    float S = (t < NB4) ? g_b4S[j*NB4 + t] : 0.f;
    float Q = (t < NB4) ? g_b4Q[j*NB4 + t] : 0.f;
    sS[t] = S; sQ[t] = Q;
    __syncthreads();
    for (int o = 128; o > 0; o >>= 1) {
        if (t < o) { sS[t] += sS[t+o]; sQ[t] += sQ[t+o]; }
        __syncthreads();
    }
    if (t == 0) {
        float mean = sS[0] / (float)NN;
        float var  = sQ[0] / (float)NN - mean*mean;
        float sc = g4[j] * rsqrtf(var + BN_EPS);
        g_scale4[j] = sc;
        g_shift4[j] = be4[j] - mean * sc;
    }
}

// ---------------- K6: out = softplus(x + bn4(nbr_sum)) ----------------
__global__ void k6_out(const float* __restrict__ x, float* __restrict__ out)
{
    int i = blockIdx.x * 256 + threadIdx.x;
    if (i < NN*64) {
        int j = i & 63;
        float v = x[i] + fmaf(g_nbr[i], g_scale4[j], g_shift4[j]);
        out[i] = softplus_f(v);
    }
}

extern "C" void kernel_launch(void* const* d_in, const int* in_sizes, int n_in,
                              void* d_out, int out_size)
{
    const float* x   = (const float*)d_in[0];
    const void*  ei  = (const void*)d_in[1];
    const float* ea  = (const float*)d_in[2];
    const float* Wc  = (const float*)d_in[3];
    const float* bc  = (const float*)d_in[4];
    const float* Wf  = (const float*)d_in[5];
    const float* bf  = (const float*)d_in[6];
    const float* Wb  = (const float*)d_in[7];
    const float* bb  = (const float*)d_in[8];
    const float* g1  = (const float*)d_in[9];
    const float* be1 = (const float*)d_in[10];
    const float* g2  = (const float*)d_in[11];
    const float* be2 = (const float*)d_in[12];
    const float* g3  = (const float*)d_in[13];
    const float* be3 = (const float*)d_in[14];
    const float* g4  = (const float*)d_in[15];
    const float* be4 = (const float*)d_in[16];

    float* out  = (float*)d_out;
    float* bond = out + (size_t)NN * 64;

    cudaFuncSetAttribute(k1_nodegemm, cudaFuncAttributeMaxDynamicSharedMemorySize, K1_SMEM);
    cudaFuncSetAttribute(k2_stats,    cudaFuncAttributeMaxDynamicSharedMemorySize, K2_SMEM);
    cudaFuncSetAttribute(k4_fused,    cudaFuncAttributeMaxDynamicSharedMemorySize, K4_SMEM);

    k1_nodegemm<<<K1G, dim3(96,2,1), K1_SMEM>>>(x, (const int*)ei, ea, Wc, bc, Wf, bf, Wb, bb);
    k2_stats<<<K2G, 256, K2_SMEM>>>(ei, Wc, Wf, Wb);
    k3_reduce<<<CD, 256>>>(g1, be1, g2, be2, g3, be3);
    k4_fused<<<K4G, 256, K4_SMEM>>>(ei, Wc, Wf, Wb, bond);
    k5_reduce<<<KD, 256>>>(g4, be4);
    k6_out<<<(NN*64 + 255)/256, 256>>>(x, out);
}